// round 7
// baseline (speedup 1.0000x reference)
#include <cuda_runtime.h>
#include <cuda_bf16.h>
#include <cstdint>

// ---------------------------------------------------------------------------
// Problem constants
// ---------------------------------------------------------------------------
#define NPTS   8192
#define CIN    128
#define DDIM   256
#define KNN    16

#define NODES_PB 8             // nodes per edge-MMA block (M = 8*16 = 128)
#define EM_THREADS 512         // 16 warps: 4 (m) x 4 (n)

// Grid kNN parameters
#define G    32
#define OXC  (-4.0f)
#define CSZ  0.25f
#define NCELL (G * G * G)

// Scratch (device globals — no allocation allowed)
__device__ float g_AB[NPTS * 512];
__device__ int   g_idx[NPTS * KNN];
__device__ uint32_t g_W2hi32[32768];        // bf16-hi image, row-major [k][n]
__device__ uint32_t g_W2lo32[32768];        // bf16-lo image
// grid structures
__device__ int    g_hist[NCELL];            // per-cell counts
__device__ int    g_cstart[NCELL];          // exclusive prefix (cell start)
__device__ int    g_cptr[NCELL];            // scatter cursors
__device__ int    g_pcell[NPTS];            // cell id per original point
__device__ float4 g_spos[NPTS];             // cell-sorted (x,y,z,sq)
__device__ int    g_sid[NPTS];              // sorted -> original index

// ---------------------------------------------------------------------------
// PTX helpers
// ---------------------------------------------------------------------------
__device__ __forceinline__ uint32_t smem_u32(const void* p) {
    uint32_t a;
    asm("{ .reg .u64 t; cvta.to.shared.u64 t, %1; cvt.u32.u64 %0, t; }"
        : "=r"(a) : "l"(p));
    return a;
}
__device__ __forceinline__ void ldsm_x4(uint32_t& r0, uint32_t& r1,
                                        uint32_t& r2, uint32_t& r3, uint32_t addr) {
    asm volatile("ldmatrix.sync.aligned.m8n8.x4.shared.b16 {%0,%1,%2,%3}, [%4];"
                 : "=r"(r0), "=r"(r1), "=r"(r2), "=r"(r3) : "r"(addr));
}
__device__ __forceinline__ void ldsm_x4_t(uint32_t& r0, uint32_t& r1,
                                          uint32_t& r2, uint32_t& r3, uint32_t addr) {
    asm volatile("ldmatrix.sync.aligned.m8n8.x4.trans.shared.b16 {%0,%1,%2,%3}, [%4];"
                 : "=r"(r0), "=r"(r1), "=r"(r2), "=r"(r3) : "r"(addr));
}
__device__ __forceinline__ void mma_bf16(float& d0, float& d1, float& d2, float& d3,
                                         uint32_t a0, uint32_t a1, uint32_t a2, uint32_t a3,
                                         uint32_t b0, uint32_t b1) {
    asm volatile("mma.sync.aligned.m16n8k16.row.col.f32.bf16.bf16.f32 "
                 "{%0,%1,%2,%3}, {%4,%5,%6,%7}, {%8,%9}, {%0,%1,%2,%3};"
                 : "+f"(d0), "+f"(d1), "+f"(d2), "+f"(d3)
                 : "r"(a0), "r"(a1), "r"(a2), "r"(a3), "r"(b0), "r"(b1));
}
__device__ __forceinline__ uint32_t pack_hi2(float v0, float v1) {
    return ((uint32_t)__bfloat16_as_ushort(__float2bfloat16_rn(v1)) << 16) |
           (uint32_t)__bfloat16_as_ushort(__float2bfloat16_rn(v0));
}

// ---------------------------------------------------------------------------
// Grid build kernels
// ---------------------------------------------------------------------------
__global__ void __launch_bounds__(1024)
zero_hist_kernel() {
    g_hist[blockIdx.x * 1024 + threadIdx.x] = 0;
}

__global__ void __launch_bounds__(256)
cell_assign_kernel(const float* __restrict__ pos) {
    const int i = blockIdx.x * 256 + threadIdx.x;
    const float x = pos[i * 3 + 0];
    const float y = pos[i * 3 + 1];
    const float z = pos[i * 3 + 2];
    const int cx = min(max(__float2int_rd((x - OXC) * (1.0f / CSZ)), 0), G - 1);
    const int cy = min(max(__float2int_rd((y - OXC) * (1.0f / CSZ)), 0), G - 1);
    const int cz = min(max(__float2int_rd((z - OXC) * (1.0f / CSZ)), 0), G - 1);
    const int c = (cz * G + cy) * G + cx;
    g_pcell[i] = c;
    atomicAdd(&g_hist[c], 1);
}

__global__ void __launch_bounds__(1024)
scan_kernel() {
    __shared__ int sd[1024];
    const int t = threadIdx.x;
    int sum = 0;
    for (int k = 0; k < 32; k++) sum += g_hist[t * 32 + k];
    sd[t] = sum;
    __syncthreads();
    for (int off = 1; off < 1024; off <<= 1) {
        const int v = (t >= off) ? sd[t - off] : 0;
        __syncthreads();
        sd[t] += v;
        __syncthreads();
    }
    int run = sd[t] - sum;   // exclusive base for this thread's 32 cells
    for (int k = 0; k < 32; k++) {
        const int c = t * 32 + k;
        g_cstart[c] = run;
        g_cptr[c]   = run;
        run += g_hist[c];
    }
}

__global__ void __launch_bounds__(256)
scatter_kernel(const float* __restrict__ pos) {
    const int i = blockIdx.x * 256 + threadIdx.x;
    const int c = g_pcell[i];
    const int dst = atomicAdd(&g_cptr[c], 1);
    const float x = pos[i * 3 + 0];
    const float y = pos[i * 3 + 1];
    const float z = pos[i * 3 + 2];
    const float sq = fmaf(z, z, fmaf(y, y, x * x));
    g_spos[dst] = make_float4(x, y, z, sq);
    g_sid[dst] = i;
}

// ---------------------------------------------------------------------------
// Exact grid kNN query: one thread per sorted point, expanding shells.
// ---------------------------------------------------------------------------
#define PROCESS_CELL(cc) do {                                                  \
    const int _st = g_cstart[cc];                                              \
    const int _en = _st + g_hist[cc];                                          \
    for (int j = _st; j < _en; j++) {                                          \
        const float4 p = g_spos[j];                                            \
        const float dot = fmaf(me.z, p.z, fmaf(me.y, p.y, me.x * p.x));        \
        const float dist = fmaf(-2.0f, dot, me.w + p.w);                       \
        if (j != q && dist < bd[KNN - 1]) {                                    \
            float d = dist; int id = j;                                        \
            _Pragma("unroll")                                                  \
            for (int s = 0; s < KNN; s++) {                                    \
                const bool sw = d < bd[s];                                     \
                const float td = bd[s]; const int ti = bj[s];                  \
                bd[s] = sw ? d : td;   bj[s] = sw ? id : ti;                   \
                d     = sw ? td : d;   id    = sw ? ti : id;                   \
            }                                                                  \
        }                                                                      \
    }                                                                          \
} while (0)

__global__ void __launch_bounds__(256)
knn_query_kernel(int* __restrict__ idxout) {
    const int q = blockIdx.x * 256 + threadIdx.x;
    const float4 me = g_spos[q];
    const int cx = min(max(__float2int_rd((me.x - OXC) * (1.0f / CSZ)), 0), G - 1);
    const int cy = min(max(__float2int_rd((me.y - OXC) * (1.0f / CSZ)), 0), G - 1);
    const int cz = min(max(__float2int_rd((me.z - OXC) * (1.0f / CSZ)), 0), G - 1);

    float bd[KNN];
    int   bj[KNN];
#pragma unroll
    for (int s = 0; s < KNN; s++) { bd[s] = 1e30f; bj[s] = -1; }

    for (int R = 0; R < G; R++) {
        const int zlo = max(cz - R, 0), zhi = min(cz + R, G - 1);
        const int ylo = max(cy - R, 0), yhi = min(cy + R, G - 1);
        const int xlo = max(cx - R, 0), xhi = min(cx + R, G - 1);
        for (int z = zlo; z <= zhi; z++) {
            const int adz = (z > cz) ? (z - cz) : (cz - z);
            for (int y = ylo; y <= yhi; y++) {
                const int ady = (y > cy) ? (y - cy) : (cy - y);
                const int rowc = (z * G + y) * G;
                if (adz == R || ady == R) {
                    for (int x = xlo; x <= xhi; x++) PROCESS_CELL(rowc + x);
                } else {
                    if (cx - R >= 0) PROCESS_CELL(rowc + cx - R);
                    if (cx + R < G)  PROCESS_CELL(rowc + cx + R);
                }
            }
        }
        // exact stop bound: distance from query to faces of processed region
        // (faces at/beyond grid edge contribute +inf: no cells exist there)
        const float dxl = (cx - R > 0)     ? (me.x - (OXC + (cx - R) * CSZ))     : 1e30f;
        const float dxr = (cx + R + 1 < G) ? ((OXC + (cx + R + 1) * CSZ) - me.x) : 1e30f;
        const float dyl = (cy - R > 0)     ? (me.y - (OXC + (cy - R) * CSZ))     : 1e30f;
        const float dyr = (cy + R + 1 < G) ? ((OXC + (cy + R + 1) * CSZ) - me.y) : 1e30f;
        const float dzl = (cz - R > 0)     ? (me.z - (OXC + (cz - R) * CSZ))     : 1e30f;
        const float dzr = (cz + R + 1 < G) ? ((OXC + (cz + R + 1) * CSZ) - me.z) : 1e30f;
        const float dmin = fminf(fminf(fminf(dxl, dxr), fminf(dyl, dyr)),
                                 fminf(dzl, dzr));
        if (dmin * dmin >= bd[KNN - 1]) break;
    }

    const int orig = g_sid[q];
#pragma unroll
    for (int s = 0; s < KNN; s++) idxout[orig * KNN + s] = g_sid[bj[s]];
}

// ---------------------------------------------------------------------------
// Kernel 2: AB = X @ [W1top - W1bot | W1bot], b1 folded into A columns
// ---------------------------------------------------------------------------
__global__ void __launch_bounds__(256)
gemm1_kernel(const float* __restrict__ X,
             const float* __restrict__ W1,
             const float* __restrict__ b1,
             float* __restrict__ AB) {
    __shared__ float As[16][65];
    __shared__ float Bs[16][64];

    const int bm = blockIdx.y * 64;
    const int bn = blockIdx.x * 64;
    const int t  = threadIdx.x;
    const int tx = t & 15;
    const int ty = t >> 4;

    float acc[4][4];
#pragma unroll
    for (int a = 0; a < 4; a++)
#pragma unroll
        for (int b = 0; b < 4; b++) acc[a][b] = 0.0f;

    for (int k0 = 0; k0 < CIN; k0 += 16) {
#pragma unroll
        for (int r = 0; r < 4; r++) {
            const int e = t + r * 256;
            const int m = e >> 4, k = e & 15;
            As[k][m] = X[(bm + m) * CIN + k0 + k];
        }
#pragma unroll
        for (int r = 0; r < 4; r++) {
            const int e = t + r * 256;
            const int k = e >> 6, n = e & 63;
            const int gk = k0 + k, gn = bn + n;
            float v;
            if (gn < 256)
                v = W1[gk * 256 + gn] - W1[(gk + 128) * 256 + gn];
            else
                v = W1[(gk + 128) * 256 + (gn - 256)];
            Bs[k][n] = v;
        }
        __syncthreads();

#pragma unroll
        for (int k = 0; k < 16; k++) {
            float a0 = As[k][ty * 4 + 0];
            float a1 = As[k][ty * 4 + 1];
            float a2 = As[k][ty * 4 + 2];
            float a3 = As[k][ty * 4 + 3];
            float b0 = Bs[k][tx * 4 + 0];
            float c1 = Bs[k][tx * 4 + 1];
            float c2 = Bs[k][tx * 4 + 2];
            float b3 = Bs[k][tx * 4 + 3];
            acc[0][0] = fmaf(a0, b0, acc[0][0]); acc[0][1] = fmaf(a0, c1, acc[0][1]);
            acc[0][2] = fmaf(a0, c2, acc[0][2]); acc[0][3] = fmaf(a0, b3, acc[0][3]);
            acc[1][0] = fmaf(a1, b0, acc[1][0]); acc[1][1] = fmaf(a1, c1, acc[1][1]);
            acc[1][2] = fmaf(a1, c2, acc[1][2]); acc[1][3] = fmaf(a1, b3, acc[1][3]);
            acc[2][0] = fmaf(a2, b0, acc[2][0]); acc[2][1] = fmaf(a2, c1, acc[2][1]);
            acc[2][2] = fmaf(a2, c2, acc[2][2]); acc[2][3] = fmaf(a2, b3, acc[2][3]);
            acc[3][0] = fmaf(a3, b0, acc[3][0]); acc[3][1] = fmaf(a3, c1, acc[3][1]);
            acc[3][2] = fmaf(a3, c2, acc[3][2]); acc[3][3] = fmaf(a3, b3, acc[3][3]);
        }
        __syncthreads();
    }

#pragma unroll
    for (int ii = 0; ii < 4; ii++)
#pragma unroll
        for (int jj = 0; jj < 4; jj++) {
            const int gn = bn + tx * 4 + jj;
            const float bias = (gn < 256) ? b1[gn] : 0.0f;
            AB[(bm + ty * 4 + ii) * 512 + gn] = acc[ii][jj] + bias;
        }
}

// ---------------------------------------------------------------------------
// Kernel 2b: split W2 into bf16 hi/lo row-major [k][n] images
// ---------------------------------------------------------------------------
__global__ void __launch_bounds__(256)
w2split_kernel(const float* __restrict__ W2) {
    const int id = blockIdx.x * 256 + threadIdx.x;
    const float4 v = ((const float4*)W2)[id];

    const __nv_bfloat16 h0 = __float2bfloat16_rn(v.x);
    const __nv_bfloat16 h1 = __float2bfloat16_rn(v.y);
    const __nv_bfloat16 h2 = __float2bfloat16_rn(v.z);
    const __nv_bfloat16 h3 = __float2bfloat16_rn(v.w);

    g_W2hi32[id * 2 + 0] = ((uint32_t)__bfloat16_as_ushort(h1) << 16) |
                           (uint32_t)__bfloat16_as_ushort(h0);
    g_W2hi32[id * 2 + 1] = ((uint32_t)__bfloat16_as_ushort(h3) << 16) |
                           (uint32_t)__bfloat16_as_ushort(h2);
    g_W2lo32[id * 2 + 0] = pack_hi2(v.x - __bfloat162float(h0),
                                    v.y - __bfloat162float(h1));
    g_W2lo32[id * 2 + 1] = pack_hi2(v.z - __bfloat162float(h2),
                                    v.w - __bfloat162float(h3));
}

// ---------------------------------------------------------------------------
// Kernel 3: mma.sync bf16 edge GEMM (R5-proven version).
// Block = 8 nodes (M=128), N=256, K=256 in 4 chunks of 64.
// ---------------------------------------------------------------------------
#define SA_HI 0
#define SA_LO 65536
#define SB_HI 131072
#define SB_LO 163840
#define SM_TOTAL 196608

__global__ void __launch_bounds__(EM_THREADS, 1)
edge_mma_kernel(const float* __restrict__ AB,
                const int* __restrict__ idx,
                const float* __restrict__ b2,
                float* __restrict__ out) {
    extern __shared__ char smem[];
    const uint32_t sbase = smem_u32(smem);
    __shared__ int idxs[128];

    const int t    = threadIdx.x;
    const int lane = t & 31;
    const int wid  = t >> 5;
    const int wm   = wid & 3;
    const int wn   = wid >> 2;
    const int i0   = blockIdx.x * NODES_PB;

    if (t < 128) idxs[t] = idx[i0 * KNN + t];
    __syncthreads();

    // ---- Phase A: gather + relu + bf16 split -> smem (rows = edges) ----
    {
        const int r = t >> 2;
        const int q = t & 3;
        const int j = idxs[r];
        const float4* arow = (const float4*)(AB + (size_t)(i0 + (r >> 4)) * 512) + q * 16;
        const float4* brow = (const float4*)(AB + (size_t)j * 512 + 256) + q * 16;
        const int sw_r = r & 7;
        char* smem_c = smem;
#pragma unroll
        for (int w = 0; w < 8; w++) {
            const float4 a0 = arow[w * 2 + 0];
            const float4 a1 = arow[w * 2 + 1];
            const float4 e0 = brow[w * 2 + 0];
            const float4 e1 = brow[w * 2 + 1];
            const float v0 = fmaxf(a0.x + e0.x, 0.0f);
            const float v1 = fmaxf(a0.y + e0.y, 0.0f);
            const float v2 = fmaxf(a0.z + e0.z, 0.0f);
            const float v3 = fmaxf(a0.w + e0.w, 0.0f);
            const float v4 = fmaxf(a1.x + e1.x, 0.0f);
            const float v5 = fmaxf(a1.y + e1.y, 0.0f);
            const float v6 = fmaxf(a1.z + e1.z, 0.0f);
            const float v7 = fmaxf(a1.w + e1.w, 0.0f);
            const __nv_bfloat16 h0 = __float2bfloat16_rn(v0);
            const __nv_bfloat16 h1 = __float2bfloat16_rn(v1);
            const __nv_bfloat16 h2 = __float2bfloat16_rn(v2);
            const __nv_bfloat16 h3 = __float2bfloat16_rn(v3);
            const __nv_bfloat16 h4 = __float2bfloat16_rn(v4);
            const __nv_bfloat16 h5 = __float2bfloat16_rn(v5);
            const __nv_bfloat16 h6 = __float2bfloat16_rn(v6);
            const __nv_bfloat16 h7 = __float2bfloat16_rn(v7);
            uint4 H, L;
            H.x = ((uint32_t)__bfloat16_as_ushort(h1) << 16) | __bfloat16_as_ushort(h0);
            H.y = ((uint32_t)__bfloat16_as_ushort(h3) << 16) | __bfloat16_as_ushort(h2);
            H.z = ((uint32_t)__bfloat16_as_ushort(h5) << 16) | __bfloat16_as_ushort(h4);
            H.w = ((uint32_t)__bfloat16_as_ushort(h7) << 16) | __bfloat16_as_ushort(h6);
            L.x = pack_hi2(v0 - __bfloat162float(h0), v1 - __bfloat162float(h1));
            L.y = pack_hi2(v2 - __bfloat162float(h2), v3 - __bfloat162float(h3));
            L.z = pack_hi2(v4 - __bfloat162float(h4), v5 - __bfloat162float(h5));
            L.w = pack_hi2(v6 - __bfloat162float(h6), v7 - __bfloat162float(h7));
            const int c = (q * 8 + w) ^ sw_r;
            *(uint4*)(smem_c + SA_HI + r * 512 + c * 16) = H;
            *(uint4*)(smem_c + SA_LO + r * 512 + c * 16) = L;
        }
    }
    __syncthreads();

    // ---- Main loop: K=256 in 4 chunks of 64 ----
    float D[2][8][4];
#pragma unroll
    for (int mt = 0; mt < 2; mt++)
#pragma unroll
        for (int f = 0; f < 8; f++)
#pragma unroll
            for (int c = 0; c < 4; c++) D[mt][f][c] = 0.0f;

    const int a_row  = wm * 32 + (lane & 15);
    const int a_swz  = a_row & 7;
    const uint32_t a_base_hi = sbase + SA_HI + a_row * 512;
    const uint32_t a_base_lo = sbase + SA_LO + a_row * 512;
    const int b_krow  = lane & 15;
    const int b_cbase = wn * 8 + (lane >> 4);

    for (int kc = 0; kc < 4; kc++) {
        {
            char* smem_c = smem;
#pragma unroll
            for (int ii = 0; ii < 4; ii++) {
                const int e = t + ii * EM_THREADS;
                const int row = e >> 5, c = e & 31;
                const int src = (kc * 64 + row) * 32 + c;
                const int dst = row * 512 + ((c ^ (row & 7)) * 16);
                *(uint4*)(smem_c + SB_HI + dst) = ((const uint4*)g_W2hi32)[src];
                *(uint4*)(smem_c + SB_LO + dst) = ((const uint4*)g_W2lo32)[src];
            }
        }
        __syncthreads();

#pragma unroll
        for (int kt = 0; kt < 4; kt++) {
            const int kg = kc * 4 + kt;
            uint32_t ah[2][4], al[2][4];
#pragma unroll
            for (int mt = 0; mt < 2; mt++) {
                const uint32_t roff = mt * 16 * 512;
                const uint32_t c = (uint32_t)((kg * 2 + (lane >> 4)) ^ a_swz) * 16;
                ldsm_x4(ah[mt][0], ah[mt][1], ah[mt][2], ah[mt][3], a_base_hi + roff + c);
                ldsm_x4(al[mt][0], al[mt][1], al[mt][2], al[mt][3], a_base_lo + roff + c);
            }
#pragma unroll
            for (int g = 0; g < 4; g++) {
                const int krow = kt * 16 + b_krow;
                const uint32_t c = (uint32_t)((b_cbase + g * 2) ^ (krow & 7)) * 16;
                const uint32_t baddr = krow * 512 + c;
                uint32_t bh0, bh1, bh2, bh3, bl0, bl1, bl2, bl3;
                ldsm_x4_t(bh0, bh1, bh2, bh3, sbase + SB_HI + baddr);
                ldsm_x4_t(bl0, bl1, bl2, bl3, sbase + SB_LO + baddr);
#pragma unroll
                for (int mt = 0; mt < 2; mt++) {
                    float* d0 = D[mt][g * 2 + 0];
                    float* d1 = D[mt][g * 2 + 1];
                    mma_bf16(d0[0], d0[1], d0[2], d0[3],
                             ah[mt][0], ah[mt][1], ah[mt][2], ah[mt][3], bh0, bh1);
                    mma_bf16(d0[0], d0[1], d0[2], d0[3],
                             ah[mt][0], ah[mt][1], ah[mt][2], ah[mt][3], bl0, bl1);
                    mma_bf16(d0[0], d0[1], d0[2], d0[3],
                             al[mt][0], al[mt][1], al[mt][2], al[mt][3], bh0, bh1);
                    mma_bf16(d1[0], d1[1], d1[2], d1[3],
                             ah[mt][0], ah[mt][1], ah[mt][2], ah[mt][3], bh2, bh3);
                    mma_bf16(d1[0], d1[1], d1[2], d1[3],
                             ah[mt][0], ah[mt][1], ah[mt][2], ah[mt][3], bl2, bl3);
                    mma_bf16(d1[0], d1[1], d1[2], d1[3],
                             al[mt][0], al[mt][1], al[mt][2], al[mt][3], bh2, bh3);
                }
            }
        }
        __syncthreads();
    }

    // ---- Epilogue: max over each node's 16 rows (warp-local) + b2 ----
#pragma unroll
    for (int mt = 0; mt < 2; mt++) {
        const int node = i0 + wm * 2 + mt;
#pragma unroll
        for (int f = 0; f < 8; f++) {
            float m0 = fmaxf(D[mt][f][0], D[mt][f][2]);
            float m1 = fmaxf(D[mt][f][1], D[mt][f][3]);
            m0 = fmaxf(m0, __shfl_xor_sync(0xffffffffu, m0, 4));
            m1 = fmaxf(m1, __shfl_xor_sync(0xffffffffu, m1, 4));
            m0 = fmaxf(m0, __shfl_xor_sync(0xffffffffu, m0, 8));
            m1 = fmaxf(m1, __shfl_xor_sync(0xffffffffu, m1, 8));
            m0 = fmaxf(m0, __shfl_xor_sync(0xffffffffu, m0, 16));
            m1 = fmaxf(m1, __shfl_xor_sync(0xffffffffu, m1, 16));
            if ((lane >> 2) == 0) {
                const int col = wn * 64 + f * 8 + 2 * (lane & 3);
                float2 o;
                o.x = m0 + b2[col];
                o.y = m1 + b2[col + 1];
                *(float2*)(out + (size_t)node * DDIM + col) = o;
            }
        }
    }
}

// ---------------------------------------------------------------------------
// Launch
// ---------------------------------------------------------------------------
extern "C" void kernel_launch(void* const* d_in, const int* in_sizes, int n_in,
                              void* d_out, int out_size) {
    const float* x   = (const float*)d_in[0];
    const float* pos = (const float*)d_in[1];
    const float* W1  = (const float*)d_in[2];
    const float* b1  = (const float*)d_in[3];
    const float* W2  = (const float*)d_in[4];
    const float* b2  = (const float*)d_in[5];
    float* out = (float*)d_out;
    (void)in_sizes; (void)n_in; (void)out_size;

    int*   idx_ptr = nullptr;
    float* ab_ptr  = nullptr;
    cudaGetSymbolAddress((void**)&idx_ptr, g_idx);
    cudaGetSymbolAddress((void**)&ab_ptr, g_AB);

    static bool attr_done = false;
    if (!attr_done) {
        cudaFuncSetAttribute(edge_mma_kernel,
                             cudaFuncAttributeMaxDynamicSharedMemorySize, SM_TOTAL);
        attr_done = true;
    }

    // grid kNN build + query
    zero_hist_kernel<<<NCELL / 1024, 1024>>>();
    cell_assign_kernel<<<NPTS / 256, 256>>>(pos);
    scan_kernel<<<1, 1024>>>();
    scatter_kernel<<<NPTS / 256, 256>>>(pos);
    knn_query_kernel<<<NPTS / 256, 256>>>(idx_ptr);

    // MLP
    gemm1_kernel<<<dim3(512 / 64, NPTS / 64), 256>>>(x, W1, b1, ab_ptr);
    w2split_kernel<<<64, 256>>>(W2);
    edge_mma_kernel<<<NPTS / NODES_PB, EM_THREADS, SM_TOTAL>>>(ab_ptr, idx_ptr, b2, out);
}

// round 8
// speedup vs baseline: 2.0290x; 2.0290x over previous
#include <cuda_runtime.h>
#include <cuda_bf16.h>
#include <cstdint>

// ---------------------------------------------------------------------------
// Problem constants
// ---------------------------------------------------------------------------
#define NPTS   8192
#define CIN    128
#define DDIM   256
#define KNN    16

#define NODES_PB 8             // nodes per edge-MMA block (M = 8*16 = 128)
#define EM_THREADS 512         // 16 warps: 4 (m) x 4 (n)

// Grid kNN parameters
#define G    32
#define OXC  (-4.0f)
#define CSZ  0.25f
#define NCELL (G * G * G)

// Scratch (device globals — no allocation allowed)
__device__ float g_AB[NPTS * 512];
__device__ int   g_idx[NPTS * KNN];
__device__ uint32_t g_W2hi32[32768];        // bf16-hi image, row-major [k][n]
__device__ uint32_t g_W2lo32[32768];        // bf16-lo image
// grid structures
__device__ int    g_hist[NCELL];
__device__ int    g_cstart[NCELL];
__device__ int    g_cptr[NCELL];
__device__ int    g_pcell[NPTS];
__device__ float4 g_spos[NPTS];             // cell-sorted (x,y,z,sq)
__device__ int    g_sid[NPTS];              // sorted -> original index

// ---------------------------------------------------------------------------
// PTX helpers
// ---------------------------------------------------------------------------
__device__ __forceinline__ uint32_t smem_u32(const void* p) {
    uint32_t a;
    asm("{ .reg .u64 t; cvta.to.shared.u64 t, %1; cvt.u32.u64 %0, t; }"
        : "=r"(a) : "l"(p));
    return a;
}
__device__ __forceinline__ void ldsm_x4(uint32_t& r0, uint32_t& r1,
                                        uint32_t& r2, uint32_t& r3, uint32_t addr) {
    asm volatile("ldmatrix.sync.aligned.m8n8.x4.shared.b16 {%0,%1,%2,%3}, [%4];"
                 : "=r"(r0), "=r"(r1), "=r"(r2), "=r"(r3) : "r"(addr));
}
__device__ __forceinline__ void ldsm_x4_t(uint32_t& r0, uint32_t& r1,
                                          uint32_t& r2, uint32_t& r3, uint32_t addr) {
    asm volatile("ldmatrix.sync.aligned.m8n8.x4.trans.shared.b16 {%0,%1,%2,%3}, [%4];"
                 : "=r"(r0), "=r"(r1), "=r"(r2), "=r"(r3) : "r"(addr));
}
__device__ __forceinline__ void mma_bf16(float& d0, float& d1, float& d2, float& d3,
                                         uint32_t a0, uint32_t a1, uint32_t a2, uint32_t a3,
                                         uint32_t b0, uint32_t b1) {
    asm volatile("mma.sync.aligned.m16n8k16.row.col.f32.bf16.bf16.f32 "
                 "{%0,%1,%2,%3}, {%4,%5,%6,%7}, {%8,%9}, {%0,%1,%2,%3};"
                 : "+f"(d0), "+f"(d1), "+f"(d2), "+f"(d3)
                 : "r"(a0), "r"(a1), "r"(a2), "r"(a3), "r"(b0), "r"(b1));
}
__device__ __forceinline__ uint32_t pack_hi2(float v0, float v1) {
    return ((uint32_t)__bfloat16_as_ushort(__float2bfloat16_rn(v1)) << 16) |
           (uint32_t)__bfloat16_as_ushort(__float2bfloat16_rn(v0));
}

// ---------------------------------------------------------------------------
// Grid build kernels
// ---------------------------------------------------------------------------
__global__ void __launch_bounds__(1024)
zero_hist_kernel() {
    g_hist[blockIdx.x * 1024 + threadIdx.x] = 0;
}

__global__ void __launch_bounds__(256)
cell_assign_kernel(const float* __restrict__ pos) {
    const int i = blockIdx.x * 256 + threadIdx.x;
    const float x = pos[i * 3 + 0];
    const float y = pos[i * 3 + 1];
    const float z = pos[i * 3 + 2];
    const int cx = min(max(__float2int_rd((x - OXC) * (1.0f / CSZ)), 0), G - 1);
    const int cy = min(max(__float2int_rd((y - OXC) * (1.0f / CSZ)), 0), G - 1);
    const int cz = min(max(__float2int_rd((z - OXC) * (1.0f / CSZ)), 0), G - 1);
    const int c = (cz * G + cy) * G + cx;
    g_pcell[i] = c;
    atomicAdd(&g_hist[c], 1);
}

__global__ void __launch_bounds__(1024)
scan_kernel() {
    __shared__ int sd[1024];
    const int t = threadIdx.x;
    int sum = 0;
    for (int k = 0; k < 32; k++) sum += g_hist[t * 32 + k];
    sd[t] = sum;
    __syncthreads();
    for (int off = 1; off < 1024; off <<= 1) {
        const int v = (t >= off) ? sd[t - off] : 0;
        __syncthreads();
        sd[t] += v;
        __syncthreads();
    }
    int run = sd[t] - sum;
    for (int k = 0; k < 32; k++) {
        const int c = t * 32 + k;
        g_cstart[c] = run;
        g_cptr[c]   = run;
        run += g_hist[c];
    }
}

__global__ void __launch_bounds__(256)
scatter_kernel(const float* __restrict__ pos) {
    const int i = blockIdx.x * 256 + threadIdx.x;
    const int c = g_pcell[i];
    const int dst = atomicAdd(&g_cptr[c], 1);
    const float x = pos[i * 3 + 0];
    const float y = pos[i * 3 + 1];
    const float z = pos[i * 3 + 2];
    const float sq = fmaf(z, z, fmaf(y, y, x * x));
    g_spos[dst] = make_float4(x, y, z, sq);
    g_sid[dst] = i;
}

// ---------------------------------------------------------------------------
// Warp-cooperative exact grid kNN query. One warp per query.
// Lanes scan contiguous candidate runs coalesced; the warp maintains one
// replicated sorted top-16 (ballot -> serialized shfl insertions).
// ---------------------------------------------------------------------------
#define PROCESS_RUN(c0, c1) do {                                               \
    const int _st = g_cstart[(c0)];                                            \
    const int _en = g_cstart[(c1)] + g_hist[(c1)];                             \
    for (int _jb = _st; _jb < _en; _jb += 32) {                                \
        const int _j = _jb + lane;                                             \
        float _dist = 1e30f;                                                   \
        if (_j < _en) {                                                        \
            const float4 _p = g_spos[_j];                                      \
            const float _dot = fmaf(me.z, _p.z, fmaf(me.y, _p.y, me.x * _p.x));\
            _dist = fmaf(-2.0f, _dot, me.w + _p.w);                            \
            if (_j == q) _dist = 1e30f;                                        \
        }                                                                      \
        unsigned _m = __ballot_sync(0xffffffffu, _dist < bd[KNN - 1]);         \
        while (_m) {                                                           \
            const int _src = __ffs(_m) - 1; _m &= _m - 1;                      \
            const float _d = __shfl_sync(0xffffffffu, _dist, _src);            \
            if (_d < bd[KNN - 1]) {                                            \
                float _dd = _d; int _id = _jb + _src;                          \
                _Pragma("unroll")                                              \
                for (int _s = 0; _s < KNN; _s++) {                             \
                    const bool _sw = _dd < bd[_s];                             \
                    const float _td = bd[_s]; const int _ti = bj[_s];          \
                    bd[_s] = _sw ? _dd : _td; bj[_s] = _sw ? _id : _ti;        \
                    _dd    = _sw ? _td : _dd; _id    = _sw ? _ti : _id;        \
                }                                                              \
            }                                                                  \
        }                                                                      \
    }                                                                          \
} while (0)

__global__ void __launch_bounds__(256)
knn_query_kernel(int* __restrict__ idxout) {
    const int q    = (blockIdx.x * 256 + threadIdx.x) >> 5;   // one warp per query
    const int lane = threadIdx.x & 31;

    const float4 me = g_spos[q];
    const int cx = min(max(__float2int_rd((me.x - OXC) * (1.0f / CSZ)), 0), G - 1);
    const int cy = min(max(__float2int_rd((me.y - OXC) * (1.0f / CSZ)), 0), G - 1);
    const int cz = min(max(__float2int_rd((me.z - OXC) * (1.0f / CSZ)), 0), G - 1);

    float bd[KNN];
    int   bj[KNN];
#pragma unroll
    for (int s = 0; s < KNN; s++) { bd[s] = 1e30f; bj[s] = -1; }

    for (int R = 0; R < G; R++) {
        const int zlo = max(cz - R, 0), zhi = min(cz + R, G - 1);
        const int ylo = max(cy - R, 0), yhi = min(cy + R, G - 1);
        const int xlo = max(cx - R, 0), xhi = min(cx + R, G - 1);
        for (int z = zlo; z <= zhi; z++) {
            const int adz = (z > cz) ? (z - cz) : (cz - z);
            for (int y = ylo; y <= yhi; y++) {
                const int ady = (y > cy) ? (y - cy) : (cy - y);
                const int rowc = (z * G + y) * G;
                if (adz == R || ady == R) {
                    PROCESS_RUN(rowc + xlo, rowc + xhi);   // whole row, contiguous
                } else {
                    if (cx - R >= 0) PROCESS_RUN(rowc + cx - R, rowc + cx - R);
                    if (cx + R < G)  PROCESS_RUN(rowc + cx + R, rowc + cx + R);
                }
            }
        }
        // exact stop bound: distance to faces of the processed region
        // (faces at/beyond grid edge contribute +inf: no cells exist there)
        const float dxl = (cx - R > 0)     ? (me.x - (OXC + (cx - R) * CSZ))     : 1e30f;
        const float dxr = (cx + R + 1 < G) ? ((OXC + (cx + R + 1) * CSZ) - me.x) : 1e30f;
        const float dyl = (cy - R > 0)     ? (me.y - (OXC + (cy - R) * CSZ))     : 1e30f;
        const float dyr = (cy + R + 1 < G) ? ((OXC + (cy + R + 1) * CSZ) - me.y) : 1e30f;
        const float dzl = (cz - R > 0)     ? (me.z - (OXC + (cz - R) * CSZ))     : 1e30f;
        const float dzr = (cz + R + 1 < G) ? ((OXC + (cz + R + 1) * CSZ) - me.z) : 1e30f;
        const float dmin = fminf(fminf(fminf(dxl, dxr), fminf(dyl, dyr)),
                                 fminf(dzl, dzr));
        if (dmin * dmin >= bd[KNN - 1]) break;
    }

    // lists are warp-replicated; lanes 0..15 write the 16 neighbors
    if (lane < KNN) {
        const int orig = g_sid[q];
        idxout[orig * KNN + lane] = g_sid[bj[lane]];
    }
}

// ---------------------------------------------------------------------------
// Kernel 2: AB = X @ [W1top - W1bot | W1bot], b1 folded into A columns
// ---------------------------------------------------------------------------
__global__ void __launch_bounds__(256)
gemm1_kernel(const float* __restrict__ X,
             const float* __restrict__ W1,
             const float* __restrict__ b1,
             float* __restrict__ AB) {
    __shared__ float As[16][65];
    __shared__ float Bs[16][64];

    const int bm = blockIdx.y * 64;
    const int bn = blockIdx.x * 64;
    const int t  = threadIdx.x;
    const int tx = t & 15;
    const int ty = t >> 4;

    float acc[4][4];
#pragma unroll
    for (int a = 0; a < 4; a++)
#pragma unroll
        for (int b = 0; b < 4; b++) acc[a][b] = 0.0f;

    for (int k0 = 0; k0 < CIN; k0 += 16) {
#pragma unroll
        for (int r = 0; r < 4; r++) {
            const int e = t + r * 256;
            const int m = e >> 4, k = e & 15;
            As[k][m] = X[(bm + m) * CIN + k0 + k];
        }
#pragma unroll
        for (int r = 0; r < 4; r++) {
            const int e = t + r * 256;
            const int k = e >> 6, n = e & 63;
            const int gk = k0 + k, gn = bn + n;
            float v;
            if (gn < 256)
                v = W1[gk * 256 + gn] - W1[(gk + 128) * 256 + gn];
            else
                v = W1[(gk + 128) * 256 + (gn - 256)];
            Bs[k][n] = v;
        }
        __syncthreads();

#pragma unroll
        for (int k = 0; k < 16; k++) {
            float a0 = As[k][ty * 4 + 0];
            float a1 = As[k][ty * 4 + 1];
            float a2 = As[k][ty * 4 + 2];
            float a3 = As[k][ty * 4 + 3];
            float b0 = Bs[k][tx * 4 + 0];
            float c1 = Bs[k][tx * 4 + 1];
            float c2 = Bs[k][tx * 4 + 2];
            float b3 = Bs[k][tx * 4 + 3];
            acc[0][0] = fmaf(a0, b0, acc[0][0]); acc[0][1] = fmaf(a0, c1, acc[0][1]);
            acc[0][2] = fmaf(a0, c2, acc[0][2]); acc[0][3] = fmaf(a0, b3, acc[0][3]);
            acc[1][0] = fmaf(a1, b0, acc[1][0]); acc[1][1] = fmaf(a1, c1, acc[1][1]);
            acc[1][2] = fmaf(a1, c2, acc[1][2]); acc[1][3] = fmaf(a1, b3, acc[1][3]);
            acc[2][0] = fmaf(a2, b0, acc[2][0]); acc[2][1] = fmaf(a2, c1, acc[2][1]);
            acc[2][2] = fmaf(a2, c2, acc[2][2]); acc[2][3] = fmaf(a2, b3, acc[2][3]);
            acc[3][0] = fmaf(a3, b0, acc[3][0]); acc[3][1] = fmaf(a3, c1, acc[3][1]);
            acc[3][2] = fmaf(a3, c2, acc[3][2]); acc[3][3] = fmaf(a3, b3, acc[3][3]);
        }
        __syncthreads();
    }

#pragma unroll
    for (int ii = 0; ii < 4; ii++)
#pragma unroll
        for (int jj = 0; jj < 4; jj++) {
            const int gn = bn + tx * 4 + jj;
            const float bias = (gn < 256) ? b1[gn] : 0.0f;
            AB[(bm + ty * 4 + ii) * 512 + gn] = acc[ii][jj] + bias;
        }
}

// ---------------------------------------------------------------------------
// Kernel 2b: split W2 into bf16 hi/lo row-major [k][n] images
// ---------------------------------------------------------------------------
__global__ void __launch_bounds__(256)
w2split_kernel(const float* __restrict__ W2) {
    const int id = blockIdx.x * 256 + threadIdx.x;
    const float4 v = ((const float4*)W2)[id];

    const __nv_bfloat16 h0 = __float2bfloat16_rn(v.x);
    const __nv_bfloat16 h1 = __float2bfloat16_rn(v.y);
    const __nv_bfloat16 h2 = __float2bfloat16_rn(v.z);
    const __nv_bfloat16 h3 = __float2bfloat16_rn(v.w);

    g_W2hi32[id * 2 + 0] = ((uint32_t)__bfloat16_as_ushort(h1) << 16) |
                           (uint32_t)__bfloat16_as_ushort(h0);
    g_W2hi32[id * 2 + 1] = ((uint32_t)__bfloat16_as_ushort(h3) << 16) |
                           (uint32_t)__bfloat16_as_ushort(h2);
    g_W2lo32[id * 2 + 0] = pack_hi2(v.x - __bfloat162float(h0),
                                    v.y - __bfloat162float(h1));
    g_W2lo32[id * 2 + 1] = pack_hi2(v.z - __bfloat162float(h2),
                                    v.w - __bfloat162float(h3));
}

// ---------------------------------------------------------------------------
// Kernel 3: mma.sync bf16 edge GEMM (R5-proven version).
// Block = 8 nodes (M=128), N=256, K=256 in 4 chunks of 64.
// ---------------------------------------------------------------------------
#define SA_HI 0
#define SA_LO 65536
#define SB_HI 131072
#define SB_LO 163840
#define SM_TOTAL 196608

__global__ void __launch_bounds__(EM_THREADS, 1)
edge_mma_kernel(const float* __restrict__ AB,
                const int* __restrict__ idx,
                const float* __restrict__ b2,
                float* __restrict__ out) {
    extern __shared__ char smem[];
    const uint32_t sbase = smem_u32(smem);
    __shared__ int idxs[128];

    const int t    = threadIdx.x;
    const int lane = t & 31;
    const int wid  = t >> 5;
    const int wm   = wid & 3;
    const int wn   = wid >> 2;
    const int i0   = blockIdx.x * NODES_PB;

    if (t < 128) idxs[t] = idx[i0 * KNN + t];
    __syncthreads();

    // ---- Phase A: gather + relu + bf16 split -> smem (rows = edges) ----
    {
        const int r = t >> 2;
        const int q = t & 3;
        const int j = idxs[r];
        const float4* arow = (const float4*)(AB + (size_t)(i0 + (r >> 4)) * 512) + q * 16;
        const float4* brow = (const float4*)(AB + (size_t)j * 512 + 256) + q * 16;
        const int sw_r = r & 7;
        char* smem_c = smem;
#pragma unroll
        for (int w = 0; w < 8; w++) {
            const float4 a0 = arow[w * 2 + 0];
            const float4 a1 = arow[w * 2 + 1];
            const float4 e0 = brow[w * 2 + 0];
            const float4 e1 = brow[w * 2 + 1];
            const float v0 = fmaxf(a0.x + e0.x, 0.0f);
            const float v1 = fmaxf(a0.y + e0.y, 0.0f);
            const float v2 = fmaxf(a0.z + e0.z, 0.0f);
            const float v3 = fmaxf(a0.w + e0.w, 0.0f);
            const float v4 = fmaxf(a1.x + e1.x, 0.0f);
            const float v5 = fmaxf(a1.y + e1.y, 0.0f);
            const float v6 = fmaxf(a1.z + e1.z, 0.0f);
            const float v7 = fmaxf(a1.w + e1.w, 0.0f);
            const __nv_bfloat16 h0 = __float2bfloat16_rn(v0);
            const __nv_bfloat16 h1 = __float2bfloat16_rn(v1);
            const __nv_bfloat16 h2 = __float2bfloat16_rn(v2);
            const __nv_bfloat16 h3 = __float2bfloat16_rn(v3);
            const __nv_bfloat16 h4 = __float2bfloat16_rn(v4);
            const __nv_bfloat16 h5 = __float2bfloat16_rn(v5);
            const __nv_bfloat16 h6 = __float2bfloat16_rn(v6);
            const __nv_bfloat16 h7 = __float2bfloat16_rn(v7);
            uint4 H, L;
            H.x = ((uint32_t)__bfloat16_as_ushort(h1) << 16) | __bfloat16_as_ushort(h0);
            H.y = ((uint32_t)__bfloat16_as_ushort(h3) << 16) | __bfloat16_as_ushort(h2);
            H.z = ((uint32_t)__bfloat16_as_ushort(h5) << 16) | __bfloat16_as_ushort(h4);
            H.w = ((uint32_t)__bfloat16_as_ushort(h7) << 16) | __bfloat16_as_ushort(h6);
            L.x = pack_hi2(v0 - __bfloat162float(h0), v1 - __bfloat162float(h1));
            L.y = pack_hi2(v2 - __bfloat162float(h2), v3 - __bfloat162float(h3));
            L.z = pack_hi2(v4 - __bfloat162float(h4), v5 - __bfloat162float(h5));
            L.w = pack_hi2(v6 - __bfloat162float(h6), v7 - __bfloat162float(h7));
            const int c = (q * 8 + w) ^ sw_r;
            *(uint4*)(smem_c + SA_HI + r * 512 + c * 16) = H;
            *(uint4*)(smem_c + SA_LO + r * 512 + c * 16) = L;
        }
    }
    __syncthreads();

    // ---- Main loop: K=256 in 4 chunks of 64 ----
    float D[2][8][4];
#pragma unroll
    for (int mt = 0; mt < 2; mt++)
#pragma unroll
        for (int f = 0; f < 8; f++)
#pragma unroll
            for (int c = 0; c < 4; c++) D[mt][f][c] = 0.0f;

    const int a_row  = wm * 32 + (lane & 15);
    const int a_swz  = a_row & 7;
    const uint32_t a_base_hi = sbase + SA_HI + a_row * 512;
    const uint32_t a_base_lo = sbase + SA_LO + a_row * 512;
    const int b_krow  = lane & 15;
    const int b_cbase = wn * 8 + (lane >> 4);

    for (int kc = 0; kc < 4; kc++) {
        {
            char* smem_c = smem;
#pragma unroll
            for (int ii = 0; ii < 4; ii++) {
                const int e = t + ii * EM_THREADS;
                const int row = e >> 5, c = e & 31;
                const int src = (kc * 64 + row) * 32 + c;
                const int dst = row * 512 + ((c ^ (row & 7)) * 16);
                *(uint4*)(smem_c + SB_HI + dst) = ((const uint4*)g_W2hi32)[src];
                *(uint4*)(smem_c + SB_LO + dst) = ((const uint4*)g_W2lo32)[src];
            }
        }
        __syncthreads();

#pragma unroll
        for (int kt = 0; kt < 4; kt++) {
            const int kg = kc * 4 + kt;
            uint32_t ah[2][4], al[2][4];
#pragma unroll
            for (int mt = 0; mt < 2; mt++) {
                const uint32_t roff = mt * 16 * 512;
                const uint32_t c = (uint32_t)((kg * 2 + (lane >> 4)) ^ a_swz) * 16;
                ldsm_x4(ah[mt][0], ah[mt][1], ah[mt][2], ah[mt][3], a_base_hi + roff + c);
                ldsm_x4(al[mt][0], al[mt][1], al[mt][2], al[mt][3], a_base_lo + roff + c);
            }
#pragma unroll
            for (int g = 0; g < 4; g++) {
                const int krow = kt * 16 + b_krow;
                const uint32_t c = (uint32_t)((b_cbase + g * 2) ^ (krow & 7)) * 16;
                const uint32_t baddr = krow * 512 + c;
                uint32_t bh0, bh1, bh2, bh3, bl0, bl1, bl2, bl3;
                ldsm_x4_t(bh0, bh1, bh2, bh3, sbase + SB_HI + baddr);
                ldsm_x4_t(bl0, bl1, bl2, bl3, sbase + SB_LO + baddr);
#pragma unroll
                for (int mt = 0; mt < 2; mt++) {
                    float* d0 = D[mt][g * 2 + 0];
                    float* d1 = D[mt][g * 2 + 1];
                    mma_bf16(d0[0], d0[1], d0[2], d0[3],
                             ah[mt][0], ah[mt][1], ah[mt][2], ah[mt][3], bh0, bh1);
                    mma_bf16(d0[0], d0[1], d0[2], d0[3],
                             ah[mt][0], ah[mt][1], ah[mt][2], ah[mt][3], bl0, bl1);
                    mma_bf16(d0[0], d0[1], d0[2], d0[3],
                             al[mt][0], al[mt][1], al[mt][2], al[mt][3], bh0, bh1);
                    mma_bf16(d1[0], d1[1], d1[2], d1[3],
                             ah[mt][0], ah[mt][1], ah[mt][2], ah[mt][3], bh2, bh3);
                    mma_bf16(d1[0], d1[1], d1[2], d1[3],
                             ah[mt][0], ah[mt][1], ah[mt][2], ah[mt][3], bl2, bl3);
                    mma_bf16(d1[0], d1[1], d1[2], d1[3],
                             al[mt][0], al[mt][1], al[mt][2], al[mt][3], bh2, bh3);
                }
            }
        }
        __syncthreads();
    }

    // ---- Epilogue: max over each node's 16 rows (warp-local) + b2 ----
#pragma unroll
    for (int mt = 0; mt < 2; mt++) {
        const int node = i0 + wm * 2 + mt;
#pragma unroll
        for (int f = 0; f < 8; f++) {
            float m0 = fmaxf(D[mt][f][0], D[mt][f][2]);
            float m1 = fmaxf(D[mt][f][1], D[mt][f][3]);
            m0 = fmaxf(m0, __shfl_xor_sync(0xffffffffu, m0, 4));
            m1 = fmaxf(m1, __shfl_xor_sync(0xffffffffu, m1, 4));
            m0 = fmaxf(m0, __shfl_xor_sync(0xffffffffu, m0, 8));
            m1 = fmaxf(m1, __shfl_xor_sync(0xffffffffu, m1, 8));
            m0 = fmaxf(m0, __shfl_xor_sync(0xffffffffu, m0, 16));
            m1 = fmaxf(m1, __shfl_xor_sync(0xffffffffu, m1, 16));
            if ((lane >> 2) == 0) {
                const int col = wn * 64 + f * 8 + 2 * (lane & 3);
                float2 o;
                o.x = m0 + b2[col];
                o.y = m1 + b2[col + 1];
                *(float2*)(out + (size_t)node * DDIM + col) = o;
            }
        }
    }
}

// ---------------------------------------------------------------------------
// Launch
// ---------------------------------------------------------------------------
extern "C" void kernel_launch(void* const* d_in, const int* in_sizes, int n_in,
                              void* d_out, int out_size) {
    const float* x   = (const float*)d_in[0];
    const float* pos = (const float*)d_in[1];
    const float* W1  = (const float*)d_in[2];
    const float* b1  = (const float*)d_in[3];
    const float* W2  = (const float*)d_in[4];
    const float* b2  = (const float*)d_in[5];
    float* out = (float*)d_out;
    (void)in_sizes; (void)n_in; (void)out_size;

    int*   idx_ptr = nullptr;
    float* ab_ptr  = nullptr;
    cudaGetSymbolAddress((void**)&idx_ptr, g_idx);
    cudaGetSymbolAddress((void**)&ab_ptr, g_AB);

    static bool attr_done = false;
    if (!attr_done) {
        cudaFuncSetAttribute(edge_mma_kernel,
                             cudaFuncAttributeMaxDynamicSharedMemorySize, SM_TOTAL);
        attr_done = true;
    }

    // grid kNN build + warp-cooperative query
    zero_hist_kernel<<<NCELL / 1024, 1024>>>();
    cell_assign_kernel<<<NPTS / 256, 256>>>(pos);
    scan_kernel<<<1, 1024>>>();
    scatter_kernel<<<NPTS / 256, 256>>>(pos);
    knn_query_kernel<<<NPTS * 32 / 256, 256>>>(idx_ptr);

    // MLP
    gemm1_kernel<<<dim3(512 / 64, NPTS / 64), 256>>>(x, W1, b1, ab_ptr);
    w2split_kernel<<<64, 256>>>(W2);
    edge_mma_kernel<<<NPTS / NODES_PB, EM_THREADS, SM_TOTAL>>>(ab_ptr, idx_ptr, b2, out);
}

// round 9
// speedup vs baseline: 3.1349x; 1.5450x over previous
#include <cuda_runtime.h>
#include <cuda_bf16.h>
#include <cstdint>

// ---------------------------------------------------------------------------
// Problem constants
// ---------------------------------------------------------------------------
#define NPTS   8192
#define CIN    128
#define DDIM   256
#define KNN    16

#define NODES_PB 8             // nodes per edge-MMA block (M = 8*16 = 128)
#define EM_THREADS 512         // 16 warps: 4 (m) x 4 (n)

// Grid kNN parameters: fat cells so candidate runs are long/contiguous
#define G    16
#define OXC  (-4.0f)
#define CSZ  0.5f
#define NCELL (G * G * G)      // 4096

// Scratch (device globals — no allocation allowed)
__device__ float g_AB[NPTS * 512];
__device__ int   g_idx[NPTS * KNN];
__device__ uint32_t g_W2hi32[32768];        // bf16-hi image, row-major [k][n]
__device__ uint32_t g_W2lo32[32768];        // bf16-lo image
// grid structures
__device__ int    g_hist[NCELL];
__device__ int    g_cstart[NCELL];
__device__ int    g_cptr[NCELL];
__device__ int    g_pcell[NPTS];
__device__ float4 g_spos[NPTS];             // cell-sorted (x,y,z,sq)
__device__ int    g_sid[NPTS];              // sorted -> original index

// ---------------------------------------------------------------------------
// PTX helpers
// ---------------------------------------------------------------------------
__device__ __forceinline__ uint32_t smem_u32(const void* p) {
    uint32_t a;
    asm("{ .reg .u64 t; cvta.to.shared.u64 t, %1; cvt.u32.u64 %0, t; }"
        : "=r"(a) : "l"(p));
    return a;
}
__device__ __forceinline__ void ldsm_x4(uint32_t& r0, uint32_t& r1,
                                        uint32_t& r2, uint32_t& r3, uint32_t addr) {
    asm volatile("ldmatrix.sync.aligned.m8n8.x4.shared.b16 {%0,%1,%2,%3}, [%4];"
                 : "=r"(r0), "=r"(r1), "=r"(r2), "=r"(r3) : "r"(addr));
}
__device__ __forceinline__ void ldsm_x4_t(uint32_t& r0, uint32_t& r1,
                                          uint32_t& r2, uint32_t& r3, uint32_t addr) {
    asm volatile("ldmatrix.sync.aligned.m8n8.x4.trans.shared.b16 {%0,%1,%2,%3}, [%4];"
                 : "=r"(r0), "=r"(r1), "=r"(r2), "=r"(r3) : "r"(addr));
}
__device__ __forceinline__ void mma_bf16(float& d0, float& d1, float& d2, float& d3,
                                         uint32_t a0, uint32_t a1, uint32_t a2, uint32_t a3,
                                         uint32_t b0, uint32_t b1) {
    asm volatile("mma.sync.aligned.m16n8k16.row.col.f32.bf16.bf16.f32 "
                 "{%0,%1,%2,%3}, {%4,%5,%6,%7}, {%8,%9}, {%0,%1,%2,%3};"
                 : "+f"(d0), "+f"(d1), "+f"(d2), "+f"(d3)
                 : "r"(a0), "r"(a1), "r"(a2), "r"(a3), "r"(b0), "r"(b1));
}
__device__ __forceinline__ uint32_t pack_hi2(float v0, float v1) {
    return ((uint32_t)__bfloat16_as_ushort(__float2bfloat16_rn(v1)) << 16) |
           (uint32_t)__bfloat16_as_ushort(__float2bfloat16_rn(v0));
}

// ---------------------------------------------------------------------------
// Grid build kernels
// ---------------------------------------------------------------------------
__global__ void __launch_bounds__(1024)
zero_hist_kernel() {
    g_hist[blockIdx.x * 1024 + threadIdx.x] = 0;
}

__global__ void __launch_bounds__(256)
cell_assign_kernel(const float* __restrict__ pos) {
    const int i = blockIdx.x * 256 + threadIdx.x;
    const float x = pos[i * 3 + 0];
    const float y = pos[i * 3 + 1];
    const float z = pos[i * 3 + 2];
    const int cx = min(max(__float2int_rd((x - OXC) * (1.0f / CSZ)), 0), G - 1);
    const int cy = min(max(__float2int_rd((y - OXC) * (1.0f / CSZ)), 0), G - 1);
    const int cz = min(max(__float2int_rd((z - OXC) * (1.0f / CSZ)), 0), G - 1);
    const int c = (cz * G + cy) * G + cx;
    g_pcell[i] = c;
    atomicAdd(&g_hist[c], 1);
}

__global__ void __launch_bounds__(1024)
scan_kernel() {
    __shared__ int sd[1024];
    const int t = threadIdx.x;
    int sum = 0;
#pragma unroll
    for (int k = 0; k < NCELL / 1024; k++) sum += g_hist[t * (NCELL / 1024) + k];
    sd[t] = sum;
    __syncthreads();
    for (int off = 1; off < 1024; off <<= 1) {
        const int v = (t >= off) ? sd[t - off] : 0;
        __syncthreads();
        sd[t] += v;
        __syncthreads();
    }
    int run = sd[t] - sum;
#pragma unroll
    for (int k = 0; k < NCELL / 1024; k++) {
        const int c = t * (NCELL / 1024) + k;
        g_cstart[c] = run;
        g_cptr[c]   = run;
        run += g_hist[c];
    }
}

__global__ void __launch_bounds__(256)
scatter_kernel(const float* __restrict__ pos) {
    const int i = blockIdx.x * 256 + threadIdx.x;
    const int c = g_pcell[i];
    const int dst = atomicAdd(&g_cptr[c], 1);
    const float x = pos[i * 3 + 0];
    const float y = pos[i * 3 + 1];
    const float z = pos[i * 3 + 2];
    const float sq = fmaf(z, z, fmaf(y, y, x * x));
    g_spos[dst] = make_float4(x, y, z, sq);
    g_sid[dst] = i;
}

// ---------------------------------------------------------------------------
// Warp-cooperative exact grid kNN query. One warp per query.
// Lanes scan contiguous candidate runs coalesced; the warp maintains one
// replicated sorted top-16 (ballot -> serialized shfl insertions).
// ---------------------------------------------------------------------------
#define PROCESS_RUN(c0, c1) do {                                               \
    const int _st = g_cstart[(c0)];                                            \
    const int _en = g_cstart[(c1)] + g_hist[(c1)];                             \
    for (int _jb = _st; _jb < _en; _jb += 32) {                                \
        const int _j = _jb + lane;                                             \
        float _dist = 1e30f;                                                   \
        if (_j < _en) {                                                        \
            const float4 _p = g_spos[_j];                                      \
            const float _dot = fmaf(me.z, _p.z, fmaf(me.y, _p.y, me.x * _p.x));\
            _dist = fmaf(-2.0f, _dot, me.w + _p.w);                            \
            if (_j == q) _dist = 1e30f;                                        \
        }                                                                      \
        unsigned _m = __ballot_sync(0xffffffffu, _dist < bd[KNN - 1]);         \
        while (_m) {                                                           \
            const int _src = __ffs(_m) - 1; _m &= _m - 1;                      \
            const float _d = __shfl_sync(0xffffffffu, _dist, _src);            \
            if (_d < bd[KNN - 1]) {                                            \
                float _dd = _d; int _id = _jb + _src;                          \
                _Pragma("unroll")                                              \
                for (int _s = 0; _s < KNN; _s++) {                             \
                    const bool _sw = _dd < bd[_s];                             \
                    const float _td = bd[_s]; const int _ti = bj[_s];          \
                    bd[_s] = _sw ? _dd : _td; bj[_s] = _sw ? _id : _ti;        \
                    _dd    = _sw ? _td : _dd; _id    = _sw ? _ti : _id;        \
                }                                                              \
            }                                                                  \
        }                                                                      \
    }                                                                          \
} while (0)

__global__ void __launch_bounds__(256)
knn_query_kernel(int* __restrict__ idxout) {
    const int q    = (blockIdx.x * 256 + threadIdx.x) >> 5;   // one warp per query
    const int lane = threadIdx.x & 31;

    const float4 me = g_spos[q];
    const int cx = min(max(__float2int_rd((me.x - OXC) * (1.0f / CSZ)), 0), G - 1);
    const int cy = min(max(__float2int_rd((me.y - OXC) * (1.0f / CSZ)), 0), G - 1);
    const int cz = min(max(__float2int_rd((me.z - OXC) * (1.0f / CSZ)), 0), G - 1);

    float bd[KNN];
    int   bj[KNN];
#pragma unroll
    for (int s = 0; s < KNN; s++) { bd[s] = 1e30f; bj[s] = -1; }

    for (int R = 0; R < G; R++) {
        const int zlo = max(cz - R, 0), zhi = min(cz + R, G - 1);
        const int ylo = max(cy - R, 0), yhi = min(cy + R, G - 1);
        const int xlo = max(cx - R, 0), xhi = min(cx + R, G - 1);
        for (int z = zlo; z <= zhi; z++) {
            const int adz = (z > cz) ? (z - cz) : (cz - z);
            for (int y = ylo; y <= yhi; y++) {
                const int ady = (y > cy) ? (y - cy) : (cy - y);
                const int rowc = (z * G + y) * G;
                if (adz == R || ady == R) {
                    PROCESS_RUN(rowc + xlo, rowc + xhi);   // whole row, contiguous
                } else {
                    if (cx - R >= 0) PROCESS_RUN(rowc + cx - R, rowc + cx - R);
                    if (cx + R < G)  PROCESS_RUN(rowc + cx + R, rowc + cx + R);
                }
            }
        }
        // exact stop bound: distance to faces of the processed region
        // (faces at/beyond grid edge contribute +inf: no cells exist there)
        const float dxl = (cx - R > 0)     ? (me.x - (OXC + (cx - R) * CSZ))     : 1e30f;
        const float dxr = (cx + R + 1 < G) ? ((OXC + (cx + R + 1) * CSZ) - me.x) : 1e30f;
        const float dyl = (cy - R > 0)     ? (me.y - (OXC + (cy - R) * CSZ))     : 1e30f;
        const float dyr = (cy + R + 1 < G) ? ((OXC + (cy + R + 1) * CSZ) - me.y) : 1e30f;
        const float dzl = (cz - R > 0)     ? (me.z - (OXC + (cz - R) * CSZ))     : 1e30f;
        const float dzr = (cz + R + 1 < G) ? ((OXC + (cz + R + 1) * CSZ) - me.z) : 1e30f;
        const float dmin = fminf(fminf(fminf(dxl, dxr), fminf(dyl, dyr)),
                                 fminf(dzl, dzr));
        if (dmin * dmin >= bd[KNN - 1]) break;
    }

    // lists are warp-replicated; lanes 0..15 write the 16 neighbors
    if (lane < KNN) {
        const int orig = g_sid[q];
        idxout[orig * KNN + lane] = g_sid[bj[lane]];
    }
}

// ---------------------------------------------------------------------------
// Kernel 2: AB = X @ [W1top - W1bot | W1bot], b1 folded into A columns
// ---------------------------------------------------------------------------
__global__ void __launch_bounds__(256)
gemm1_kernel(const float* __restrict__ X,
             const float* __restrict__ W1,
             const float* __restrict__ b1,
             float* __restrict__ AB) {
    __shared__ float As[16][65];
    __shared__ float Bs[16][64];

    const int bm = blockIdx.y * 64;
    const int bn = blockIdx.x * 64;
    const int t  = threadIdx.x;
    const int tx = t & 15;
    const int ty = t >> 4;

    float acc[4][4];
#pragma unroll
    for (int a = 0; a < 4; a++)
#pragma unroll
        for (int b = 0; b < 4; b++) acc[a][b] = 0.0f;

    for (int k0 = 0; k0 < CIN; k0 += 16) {
#pragma unroll
        for (int r = 0; r < 4; r++) {
            const int e = t + r * 256;
            const int m = e >> 4, k = e & 15;
            As[k][m] = X[(bm + m) * CIN + k0 + k];
        }
#pragma unroll
        for (int r = 0; r < 4; r++) {
            const int e = t + r * 256;
            const int k = e >> 6, n = e & 63;
            const int gk = k0 + k, gn = bn + n;
            float v;
            if (gn < 256)
                v = W1[gk * 256 + gn] - W1[(gk + 128) * 256 + gn];
            else
                v = W1[(gk + 128) * 256 + (gn - 256)];
            Bs[k][n] = v;
        }
        __syncthreads();

#pragma unroll
        for (int k = 0; k < 16; k++) {
            float a0 = As[k][ty * 4 + 0];
            float a1 = As[k][ty * 4 + 1];
            float a2 = As[k][ty * 4 + 2];
            float a3 = As[k][ty * 4 + 3];
            float b0 = Bs[k][tx * 4 + 0];
            float c1 = Bs[k][tx * 4 + 1];
            float c2 = Bs[k][tx * 4 + 2];
            float b3 = Bs[k][tx * 4 + 3];
            acc[0][0] = fmaf(a0, b0, acc[0][0]); acc[0][1] = fmaf(a0, c1, acc[0][1]);
            acc[0][2] = fmaf(a0, c2, acc[0][2]); acc[0][3] = fmaf(a0, b3, acc[0][3]);
            acc[1][0] = fmaf(a1, b0, acc[1][0]); acc[1][1] = fmaf(a1, c1, acc[1][1]);
            acc[1][2] = fmaf(a1, c2, acc[1][2]); acc[1][3] = fmaf(a1, b3, acc[1][3]);
            acc[2][0] = fmaf(a2, b0, acc[2][0]); acc[2][1] = fmaf(a2, c1, acc[2][1]);
            acc[2][2] = fmaf(a2, c2, acc[2][2]); acc[2][3] = fmaf(a2, b3, acc[2][3]);
            acc[3][0] = fmaf(a3, b0, acc[3][0]); acc[3][1] = fmaf(a3, c1, acc[3][1]);
            acc[3][2] = fmaf(a3, c2, acc[3][2]); acc[3][3] = fmaf(a3, b3, acc[3][3]);
        }
        __syncthreads();
    }

#pragma unroll
    for (int ii = 0; ii < 4; ii++)
#pragma unroll
        for (int jj = 0; jj < 4; jj++) {
            const int gn = bn + tx * 4 + jj;
            const float bias = (gn < 256) ? b1[gn] : 0.0f;
            AB[(bm + ty * 4 + ii) * 512 + gn] = acc[ii][jj] + bias;
        }
}

// ---------------------------------------------------------------------------
// Kernel 2b: split W2 into bf16 hi/lo row-major [k][n] images
// ---------------------------------------------------------------------------
__global__ void __launch_bounds__(256)
w2split_kernel(const float* __restrict__ W2) {
    const int id = blockIdx.x * 256 + threadIdx.x;
    const float4 v = ((const float4*)W2)[id];

    const __nv_bfloat16 h0 = __float2bfloat16_rn(v.x);
    const __nv_bfloat16 h1 = __float2bfloat16_rn(v.y);
    const __nv_bfloat16 h2 = __float2bfloat16_rn(v.z);
    const __nv_bfloat16 h3 = __float2bfloat16_rn(v.w);

    g_W2hi32[id * 2 + 0] = ((uint32_t)__bfloat16_as_ushort(h1) << 16) |
                           (uint32_t)__bfloat16_as_ushort(h0);
    g_W2hi32[id * 2 + 1] = ((uint32_t)__bfloat16_as_ushort(h3) << 16) |
                           (uint32_t)__bfloat16_as_ushort(h2);
    g_W2lo32[id * 2 + 0] = pack_hi2(v.x - __bfloat162float(h0),
                                    v.y - __bfloat162float(h1));
    g_W2lo32[id * 2 + 1] = pack_hi2(v.z - __bfloat162float(h2),
                                    v.w - __bfloat162float(h3));
}

// ---------------------------------------------------------------------------
// Kernel 3: mma.sync bf16 edge GEMM (R5-proven version).
// Block = 8 nodes (M=128), N=256, K=256 in 4 chunks of 64.
// ---------------------------------------------------------------------------
#define SA_HI 0
#define SA_LO 65536
#define SB_HI 131072
#define SB_LO 163840
#define SM_TOTAL 196608

__global__ void __launch_bounds__(EM_THREADS, 1)
edge_mma_kernel(const float* __restrict__ AB,
                const int* __restrict__ idx,
                const float* __restrict__ b2,
                float* __restrict__ out) {
    extern __shared__ char smem[];
    const uint32_t sbase = smem_u32(smem);
    __shared__ int idxs[128];

    const int t    = threadIdx.x;
    const int lane = t & 31;
    const int wid  = t >> 5;
    const int wm   = wid & 3;
    const int wn   = wid >> 2;
    const int i0   = blockIdx.x * NODES_PB;

    if (t < 128) idxs[t] = idx[i0 * KNN + t];
    __syncthreads();

    // ---- Phase A: gather + relu + bf16 split -> smem (rows = edges) ----
    {
        const int r = t >> 2;
        const int q = t & 3;
        const int j = idxs[r];
        const float4* arow = (const float4*)(AB + (size_t)(i0 + (r >> 4)) * 512) + q * 16;
        const float4* brow = (const float4*)(AB + (size_t)j * 512 + 256) + q * 16;
        const int sw_r = r & 7;
        char* smem_c = smem;
#pragma unroll
        for (int w = 0; w < 8; w++) {
            const float4 a0 = arow[w * 2 + 0];
            const float4 a1 = arow[w * 2 + 1];
            const float4 e0 = brow[w * 2 + 0];
            const float4 e1 = brow[w * 2 + 1];
            const float v0 = fmaxf(a0.x + e0.x, 0.0f);
            const float v1 = fmaxf(a0.y + e0.y, 0.0f);
            const float v2 = fmaxf(a0.z + e0.z, 0.0f);
            const float v3 = fmaxf(a0.w + e0.w, 0.0f);
            const float v4 = fmaxf(a1.x + e1.x, 0.0f);
            const float v5 = fmaxf(a1.y + e1.y, 0.0f);
            const float v6 = fmaxf(a1.z + e1.z, 0.0f);
            const float v7 = fmaxf(a1.w + e1.w, 0.0f);
            const __nv_bfloat16 h0 = __float2bfloat16_rn(v0);
            const __nv_bfloat16 h1 = __float2bfloat16_rn(v1);
            const __nv_bfloat16 h2 = __float2bfloat16_rn(v2);
            const __nv_bfloat16 h3 = __float2bfloat16_rn(v3);
            const __nv_bfloat16 h4 = __float2bfloat16_rn(v4);
            const __nv_bfloat16 h5 = __float2bfloat16_rn(v5);
            const __nv_bfloat16 h6 = __float2bfloat16_rn(v6);
            const __nv_bfloat16 h7 = __float2bfloat16_rn(v7);
            uint4 H, L;
            H.x = ((uint32_t)__bfloat16_as_ushort(h1) << 16) | __bfloat16_as_ushort(h0);
            H.y = ((uint32_t)__bfloat16_as_ushort(h3) << 16) | __bfloat16_as_ushort(h2);
            H.z = ((uint32_t)__bfloat16_as_ushort(h5) << 16) | __bfloat16_as_ushort(h4);
            H.w = ((uint32_t)__bfloat16_as_ushort(h7) << 16) | __bfloat16_as_ushort(h6);
            L.x = pack_hi2(v0 - __bfloat162float(h0), v1 - __bfloat162float(h1));
            L.y = pack_hi2(v2 - __bfloat162float(h2), v3 - __bfloat162float(h3));
            L.z = pack_hi2(v4 - __bfloat162float(h4), v5 - __bfloat162float(h5));
            L.w = pack_hi2(v6 - __bfloat162float(h6), v7 - __bfloat162float(h7));
            const int c = (q * 8 + w) ^ sw_r;
            *(uint4*)(smem_c + SA_HI + r * 512 + c * 16) = H;
            *(uint4*)(smem_c + SA_LO + r * 512 + c * 16) = L;
        }
    }
    __syncthreads();

    // ---- Main loop: K=256 in 4 chunks of 64 ----
    float D[2][8][4];
#pragma unroll
    for (int mt = 0; mt < 2; mt++)
#pragma unroll
        for (int f = 0; f < 8; f++)
#pragma unroll
            for (int c = 0; c < 4; c++) D[mt][f][c] = 0.0f;

    const int a_row  = wm * 32 + (lane & 15);
    const int a_swz  = a_row & 7;
    const uint32_t a_base_hi = sbase + SA_HI + a_row * 512;
    const uint32_t a_base_lo = sbase + SA_LO + a_row * 512;
    const int b_krow  = lane & 15;
    const int b_cbase = wn * 8 + (lane >> 4);

    for (int kc = 0; kc < 4; kc++) {
        {
            char* smem_c = smem;
#pragma unroll
            for (int ii = 0; ii < 4; ii++) {
                const int e = t + ii * EM_THREADS;
                const int row = e >> 5, c = e & 31;
                const int src = (kc * 64 + row) * 32 + c;
                const int dst = row * 512 + ((c ^ (row & 7)) * 16);
                *(uint4*)(smem_c + SB_HI + dst) = ((const uint4*)g_W2hi32)[src];
                *(uint4*)(smem_c + SB_LO + dst) = ((const uint4*)g_W2lo32)[src];
            }
        }
        __syncthreads();

#pragma unroll
        for (int kt = 0; kt < 4; kt++) {
            const int kg = kc * 4 + kt;
            uint32_t ah[2][4], al[2][4];
#pragma unroll
            for (int mt = 0; mt < 2; mt++) {
                const uint32_t roff = mt * 16 * 512;
                const uint32_t c = (uint32_t)((kg * 2 + (lane >> 4)) ^ a_swz) * 16;
                ldsm_x4(ah[mt][0], ah[mt][1], ah[mt][2], ah[mt][3], a_base_hi + roff + c);
                ldsm_x4(al[mt][0], al[mt][1], al[mt][2], al[mt][3], a_base_lo + roff + c);
            }
#pragma unroll
            for (int g = 0; g < 4; g++) {
                const int krow = kt * 16 + b_krow;
                const uint32_t c = (uint32_t)((b_cbase + g * 2) ^ (krow & 7)) * 16;
                const uint32_t baddr = krow * 512 + c;
                uint32_t bh0, bh1, bh2, bh3, bl0, bl1, bl2, bl3;
                ldsm_x4_t(bh0, bh1, bh2, bh3, sbase + SB_HI + baddr);
                ldsm_x4_t(bl0, bl1, bl2, bl3, sbase + SB_LO + baddr);
#pragma unroll
                for (int mt = 0; mt < 2; mt++) {
                    float* d0 = D[mt][g * 2 + 0];
                    float* d1 = D[mt][g * 2 + 1];
                    mma_bf16(d0[0], d0[1], d0[2], d0[3],
                             ah[mt][0], ah[mt][1], ah[mt][2], ah[mt][3], bh0, bh1);
                    mma_bf16(d0[0], d0[1], d0[2], d0[3],
                             ah[mt][0], ah[mt][1], ah[mt][2], ah[mt][3], bl0, bl1);
                    mma_bf16(d0[0], d0[1], d0[2], d0[3],
                             al[mt][0], al[mt][1], al[mt][2], al[mt][3], bh0, bh1);
                    mma_bf16(d1[0], d1[1], d1[2], d1[3],
                             ah[mt][0], ah[mt][1], ah[mt][2], ah[mt][3], bh2, bh3);
                    mma_bf16(d1[0], d1[1], d1[2], d1[3],
                             ah[mt][0], ah[mt][1], ah[mt][2], ah[mt][3], bl2, bl3);
                    mma_bf16(d1[0], d1[1], d1[2], d1[3],
                             al[mt][0], al[mt][1], al[mt][2], al[mt][3], bh2, bh3);
                }
            }
        }
        __syncthreads();
    }

    // ---- Epilogue: max over each node's 16 rows (warp-local) + b2 ----
#pragma unroll
    for (int mt = 0; mt < 2; mt++) {
        const int node = i0 + wm * 2 + mt;
#pragma unroll
        for (int f = 0; f < 8; f++) {
            float m0 = fmaxf(D[mt][f][0], D[mt][f][2]);
            float m1 = fmaxf(D[mt][f][1], D[mt][f][3]);
            m0 = fmaxf(m0, __shfl_xor_sync(0xffffffffu, m0, 4));
            m1 = fmaxf(m1, __shfl_xor_sync(0xffffffffu, m1, 4));
            m0 = fmaxf(m0, __shfl_xor_sync(0xffffffffu, m0, 8));
            m1 = fmaxf(m1, __shfl_xor_sync(0xffffffffu, m1, 8));
            m0 = fmaxf(m0, __shfl_xor_sync(0xffffffffu, m0, 16));
            m1 = fmaxf(m1, __shfl_xor_sync(0xffffffffu, m1, 16));
            if ((lane >> 2) == 0) {
                const int col = wn * 64 + f * 8 + 2 * (lane & 3);
                float2 o;
                o.x = m0 + b2[col];
                o.y = m1 + b2[col + 1];
                *(float2*)(out + (size_t)node * DDIM + col) = o;
            }
        }
    }
}

// ---------------------------------------------------------------------------
// Launch
// ---------------------------------------------------------------------------
extern "C" void kernel_launch(void* const* d_in, const int* in_sizes, int n_in,
                              void* d_out, int out_size) {
    const float* x   = (const float*)d_in[0];
    const float* pos = (const float*)d_in[1];
    const float* W1  = (const float*)d_in[2];
    const float* b1  = (const float*)d_in[3];
    const float* W2  = (const float*)d_in[4];
    const float* b2  = (const float*)d_in[5];
    float* out = (float*)d_out;
    (void)in_sizes; (void)n_in; (void)out_size;

    int*   idx_ptr = nullptr;
    float* ab_ptr  = nullptr;
    cudaGetSymbolAddress((void**)&idx_ptr, g_idx);
    cudaGetSymbolAddress((void**)&ab_ptr, g_AB);

    static bool attr_done = false;
    if (!attr_done) {
        cudaFuncSetAttribute(edge_mma_kernel,
                             cudaFuncAttributeMaxDynamicSharedMemorySize, SM_TOTAL);
        attr_done = true;
    }

    // grid kNN build + warp-cooperative query
    zero_hist_kernel<<<NCELL / 1024, 1024>>>();
    cell_assign_kernel<<<NPTS / 256, 256>>>(pos);
    scan_kernel<<<1, 1024>>>();
    scatter_kernel<<<NPTS / 256, 256>>>(pos);
    knn_query_kernel<<<NPTS * 32 / 256, 256>>>(idx_ptr);

    // MLP
    gemm1_kernel<<<dim3(512 / 64, NPTS / 64), 256>>>(x, W1, b1, ab_ptr);
    w2split_kernel<<<64, 256>>>(W2);
    edge_mma_kernel<<<NPTS / NODES_PB, EM_THREADS, SM_TOTAL>>>(ab_ptr, idx_ptr, b2, out);
}

// round 10
// speedup vs baseline: 3.3800x; 1.0782x over previous
#include <cuda_runtime.h>
#include <cuda_bf16.h>
#include <cstdint>

// ---------------------------------------------------------------------------
// Problem constants
// ---------------------------------------------------------------------------
#define NPTS   8192
#define CIN    128
#define DDIM   256
#define KNN    16

#define NODES_PB 8             // nodes per edge-MMA block (M = 8*16 = 128)
#define EM_THREADS 512         // 16 warps: 4 (m) x 4 (n)

// Grid kNN parameters: fat cells so candidate runs are long/contiguous
#define G    16
#define OXC  (-4.0f)
#define CSZ  0.5f
#define NCELL (G * G * G)      // 4096

// Scratch (device globals — no allocation allowed)
__device__ float g_AB[NPTS * 512];
__device__ int   g_idx[NPTS * KNN];
__device__ uint32_t g_W2hi32[32768];        // bf16-hi image, row-major [k][n]
__device__ uint32_t g_W2lo32[32768];        // bf16-lo image
// grid structures
__device__ int    g_hist[NCELL];
__device__ int    g_cstart[NCELL];
__device__ int    g_cptr[NCELL];
__device__ int    g_pcell[NPTS];
__device__ float4 g_spos[NPTS];             // cell-sorted (x,y,z,sq)
__device__ int    g_sid[NPTS];              // sorted -> original index

// ---------------------------------------------------------------------------
// PTX helpers
// ---------------------------------------------------------------------------
__device__ __forceinline__ uint32_t smem_u32(const void* p) {
    uint32_t a;
    asm("{ .reg .u64 t; cvta.to.shared.u64 t, %1; cvt.u32.u64 %0, t; }"
        : "=r"(a) : "l"(p));
    return a;
}
__device__ __forceinline__ void ldsm_x4(uint32_t& r0, uint32_t& r1,
                                        uint32_t& r2, uint32_t& r3, uint32_t addr) {
    asm volatile("ldmatrix.sync.aligned.m8n8.x4.shared.b16 {%0,%1,%2,%3}, [%4];"
                 : "=r"(r0), "=r"(r1), "=r"(r2), "=r"(r3) : "r"(addr));
}
__device__ __forceinline__ void ldsm_x4_t(uint32_t& r0, uint32_t& r1,
                                          uint32_t& r2, uint32_t& r3, uint32_t addr) {
    asm volatile("ldmatrix.sync.aligned.m8n8.x4.trans.shared.b16 {%0,%1,%2,%3}, [%4];"
                 : "=r"(r0), "=r"(r1), "=r"(r2), "=r"(r3) : "r"(addr));
}
__device__ __forceinline__ void mma_bf16(float& d0, float& d1, float& d2, float& d3,
                                         uint32_t a0, uint32_t a1, uint32_t a2, uint32_t a3,
                                         uint32_t b0, uint32_t b1) {
    asm volatile("mma.sync.aligned.m16n8k16.row.col.f32.bf16.bf16.f32 "
                 "{%0,%1,%2,%3}, {%4,%5,%6,%7}, {%8,%9}, {%0,%1,%2,%3};"
                 : "+f"(d0), "+f"(d1), "+f"(d2), "+f"(d3)
                 : "r"(a0), "r"(a1), "r"(a2), "r"(a3), "r"(b0), "r"(b1));
}
__device__ __forceinline__ uint32_t pack_hi2(float v0, float v1) {
    return ((uint32_t)__bfloat16_as_ushort(__float2bfloat16_rn(v1)) << 16) |
           (uint32_t)__bfloat16_as_ushort(__float2bfloat16_rn(v0));
}
#define CP_ASYNC16(dst, src) \
    asm volatile("cp.async.cg.shared.global [%0], [%1], 16;" \
                 :: "r"(dst), "l"(src) : "memory")
#define CP_ASYNC_COMMIT() asm volatile("cp.async.commit_group;" ::: "memory")
#define CP_ASYNC_WAIT(n)  asm volatile("cp.async.wait_group %0;" :: "n"(n) : "memory")

// ---------------------------------------------------------------------------
// Grid build kernels
// ---------------------------------------------------------------------------
__global__ void __launch_bounds__(1024)
zero_hist_kernel() {
    g_hist[blockIdx.x * 1024 + threadIdx.x] = 0;
}

__global__ void __launch_bounds__(256)
cell_assign_kernel(const float* __restrict__ pos) {
    const int i = blockIdx.x * 256 + threadIdx.x;
    const float x = pos[i * 3 + 0];
    const float y = pos[i * 3 + 1];
    const float z = pos[i * 3 + 2];
    const int cx = min(max(__float2int_rd((x - OXC) * (1.0f / CSZ)), 0), G - 1);
    const int cy = min(max(__float2int_rd((y - OXC) * (1.0f / CSZ)), 0), G - 1);
    const int cz = min(max(__float2int_rd((z - OXC) * (1.0f / CSZ)), 0), G - 1);
    const int c = (cz * G + cy) * G + cx;
    g_pcell[i] = c;
    atomicAdd(&g_hist[c], 1);
}

__global__ void __launch_bounds__(1024)
scan_kernel() {
    __shared__ int sd[1024];
    const int t = threadIdx.x;
    int sum = 0;
#pragma unroll
    for (int k = 0; k < NCELL / 1024; k++) sum += g_hist[t * (NCELL / 1024) + k];
    sd[t] = sum;
    __syncthreads();
    for (int off = 1; off < 1024; off <<= 1) {
        const int v = (t >= off) ? sd[t - off] : 0;
        __syncthreads();
        sd[t] += v;
        __syncthreads();
    }
    int run = sd[t] - sum;
#pragma unroll
    for (int k = 0; k < NCELL / 1024; k++) {
        const int c = t * (NCELL / 1024) + k;
        g_cstart[c] = run;
        g_cptr[c]   = run;
        run += g_hist[c];
    }
}

__global__ void __launch_bounds__(256)
scatter_kernel(const float* __restrict__ pos) {
    const int i = blockIdx.x * 256 + threadIdx.x;
    const int c = g_pcell[i];
    const int dst = atomicAdd(&g_cptr[c], 1);
    const float x = pos[i * 3 + 0];
    const float y = pos[i * 3 + 1];
    const float z = pos[i * 3 + 2];
    const float sq = fmaf(z, z, fmaf(y, y, x * x));
    g_spos[dst] = make_float4(x, y, z, sq);
    g_sid[dst] = i;
}

// ---------------------------------------------------------------------------
// Warp-cooperative exact grid kNN query. One warp per query.
// ---------------------------------------------------------------------------
#define PROCESS_RUN(c0, c1) do {                                               \
    const int _st = g_cstart[(c0)];                                            \
    const int _en = g_cstart[(c1)] + g_hist[(c1)];                             \
    for (int _jb = _st; _jb < _en; _jb += 32) {                                \
        const int _j = _jb + lane;                                             \
        float _dist = 1e30f;                                                   \
        if (_j < _en) {                                                        \
            const float4 _p = g_spos[_j];                                      \
            const float _dot = fmaf(me.z, _p.z, fmaf(me.y, _p.y, me.x * _p.x));\
            _dist = fmaf(-2.0f, _dot, me.w + _p.w);                            \
            if (_j == q) _dist = 1e30f;                                        \
        }                                                                      \
        unsigned _m = __ballot_sync(0xffffffffu, _dist < bd[KNN - 1]);         \
        while (_m) {                                                           \
            const int _src = __ffs(_m) - 1; _m &= _m - 1;                      \
            const float _d = __shfl_sync(0xffffffffu, _dist, _src);            \
            if (_d < bd[KNN - 1]) {                                            \
                float _dd = _d; int _id = _jb + _src;                          \
                _Pragma("unroll")                                              \
                for (int _s = 0; _s < KNN; _s++) {                             \
                    const bool _sw = _dd < bd[_s];                             \
                    const float _td = bd[_s]; const int _ti = bj[_s];          \
                    bd[_s] = _sw ? _dd : _td; bj[_s] = _sw ? _id : _ti;        \
                    _dd    = _sw ? _td : _dd; _id    = _sw ? _ti : _id;        \
                }                                                              \
            }                                                                  \
        }                                                                      \
    }                                                                          \
} while (0)

__global__ void __launch_bounds__(256)
knn_query_kernel(int* __restrict__ idxout) {
    const int q    = (blockIdx.x * 256 + threadIdx.x) >> 5;   // one warp per query
    const int lane = threadIdx.x & 31;

    const float4 me = g_spos[q];
    const int cx = min(max(__float2int_rd((me.x - OXC) * (1.0f / CSZ)), 0), G - 1);
    const int cy = min(max(__float2int_rd((me.y - OXC) * (1.0f / CSZ)), 0), G - 1);
    const int cz = min(max(__float2int_rd((me.z - OXC) * (1.0f / CSZ)), 0), G - 1);

    float bd[KNN];
    int   bj[KNN];
#pragma unroll
    for (int s = 0; s < KNN; s++) { bd[s] = 1e30f; bj[s] = -1; }

    for (int R = 0; R < G; R++) {
        const int zlo = max(cz - R, 0), zhi = min(cz + R, G - 1);
        const int ylo = max(cy - R, 0), yhi = min(cy + R, G - 1);
        const int xlo = max(cx - R, 0), xhi = min(cx + R, G - 1);
        for (int z = zlo; z <= zhi; z++) {
            const int adz = (z > cz) ? (z - cz) : (cz - z);
            for (int y = ylo; y <= yhi; y++) {
                const int ady = (y > cy) ? (y - cy) : (cy - y);
                const int rowc = (z * G + y) * G;
                if (adz == R || ady == R) {
                    PROCESS_RUN(rowc + xlo, rowc + xhi);   // whole row, contiguous
                } else {
                    if (cx - R >= 0) PROCESS_RUN(rowc + cx - R, rowc + cx - R);
                    if (cx + R < G)  PROCESS_RUN(rowc + cx + R, rowc + cx + R);
                }
            }
        }
        // exact stop bound: distance to faces of the processed region
        const float dxl = (cx - R > 0)     ? (me.x - (OXC + (cx - R) * CSZ))     : 1e30f;
        const float dxr = (cx + R + 1 < G) ? ((OXC + (cx + R + 1) * CSZ) - me.x) : 1e30f;
        const float dyl = (cy - R > 0)     ? (me.y - (OXC + (cy - R) * CSZ))     : 1e30f;
        const float dyr = (cy + R + 1 < G) ? ((OXC + (cy + R + 1) * CSZ) - me.y) : 1e30f;
        const float dzl = (cz - R > 0)     ? (me.z - (OXC + (cz - R) * CSZ))     : 1e30f;
        const float dzr = (cz + R + 1 < G) ? ((OXC + (cz + R + 1) * CSZ) - me.z) : 1e30f;
        const float dmin = fminf(fminf(fminf(dxl, dxr), fminf(dyl, dyr)),
                                 fminf(dzl, dzr));
        if (dmin * dmin >= bd[KNN - 1]) break;
    }

    if (lane < KNN) {
        const int orig = g_sid[q];
        idxout[orig * KNN + lane] = g_sid[bj[lane]];
    }
}

// ---------------------------------------------------------------------------
// Kernel 2: AB = X @ [W1top - W1bot | W1bot], b1 folded into A columns
// ---------------------------------------------------------------------------
__global__ void __launch_bounds__(256)
gemm1_kernel(const float* __restrict__ X,
             const float* __restrict__ W1,
             const float* __restrict__ b1,
             float* __restrict__ AB) {
    __shared__ float As[16][65];
    __shared__ float Bs[16][64];

    const int bm = blockIdx.y * 64;
    const int bn = blockIdx.x * 64;
    const int t  = threadIdx.x;
    const int tx = t & 15;
    const int ty = t >> 4;

    float acc[4][4];
#pragma unroll
    for (int a = 0; a < 4; a++)
#pragma unroll
        for (int b = 0; b < 4; b++) acc[a][b] = 0.0f;

    for (int k0 = 0; k0 < CIN; k0 += 16) {
#pragma unroll
        for (int r = 0; r < 4; r++) {
            const int e = t + r * 256;
            const int m = e >> 4, k = e & 15;
            As[k][m] = X[(bm + m) * CIN + k0 + k];
        }
#pragma unroll
        for (int r = 0; r < 4; r++) {
            const int e = t + r * 256;
            const int k = e >> 6, n = e & 63;
            const int gk = k0 + k, gn = bn + n;
            float v;
            if (gn < 256)
                v = W1[gk * 256 + gn] - W1[(gk + 128) * 256 + gn];
            else
                v = W1[(gk + 128) * 256 + (gn - 256)];
            Bs[k][n] = v;
        }
        __syncthreads();

#pragma unroll
        for (int k = 0; k < 16; k++) {
            float a0 = As[k][ty * 4 + 0];
            float a1 = As[k][ty * 4 + 1];
            float a2 = As[k][ty * 4 + 2];
            float a3 = As[k][ty * 4 + 3];
            float b0 = Bs[k][tx * 4 + 0];
            float c1 = Bs[k][tx * 4 + 1];
            float c2 = Bs[k][tx * 4 + 2];
            float b3 = Bs[k][tx * 4 + 3];
            acc[0][0] = fmaf(a0, b0, acc[0][0]); acc[0][1] = fmaf(a0, c1, acc[0][1]);
            acc[0][2] = fmaf(a0, c2, acc[0][2]); acc[0][3] = fmaf(a0, b3, acc[0][3]);
            acc[1][0] = fmaf(a1, b0, acc[1][0]); acc[1][1] = fmaf(a1, c1, acc[1][1]);
            acc[1][2] = fmaf(a1, c2, acc[1][2]); acc[1][3] = fmaf(a1, b3, acc[1][3]);
            acc[2][0] = fmaf(a2, b0, acc[2][0]); acc[2][1] = fmaf(a2, c1, acc[2][1]);
            acc[2][2] = fmaf(a2, c2, acc[2][2]); acc[2][3] = fmaf(a2, b3, acc[2][3]);
            acc[3][0] = fmaf(a3, b0, acc[3][0]); acc[3][1] = fmaf(a3, c1, acc[3][1]);
            acc[3][2] = fmaf(a3, c2, acc[3][2]); acc[3][3] = fmaf(a3, b3, acc[3][3]);
        }
        __syncthreads();
    }

#pragma unroll
    for (int ii = 0; ii < 4; ii++)
#pragma unroll
        for (int jj = 0; jj < 4; jj++) {
            const int gn = bn + tx * 4 + jj;
            const float bias = (gn < 256) ? b1[gn] : 0.0f;
            AB[(bm + ty * 4 + ii) * 512 + gn] = acc[ii][jj] + bias;
        }
}

// ---------------------------------------------------------------------------
// Kernel 2b: split W2 into bf16 hi/lo row-major [k][n] images
// ---------------------------------------------------------------------------
__global__ void __launch_bounds__(256)
w2split_kernel(const float* __restrict__ W2) {
    const int id = blockIdx.x * 256 + threadIdx.x;
    const float4 v = ((const float4*)W2)[id];

    const __nv_bfloat16 h0 = __float2bfloat16_rn(v.x);
    const __nv_bfloat16 h1 = __float2bfloat16_rn(v.y);
    const __nv_bfloat16 h2 = __float2bfloat16_rn(v.z);
    const __nv_bfloat16 h3 = __float2bfloat16_rn(v.w);

    g_W2hi32[id * 2 + 0] = ((uint32_t)__bfloat16_as_ushort(h1) << 16) |
                           (uint32_t)__bfloat16_as_ushort(h0);
    g_W2hi32[id * 2 + 1] = ((uint32_t)__bfloat16_as_ushort(h3) << 16) |
                           (uint32_t)__bfloat16_as_ushort(h2);
    g_W2lo32[id * 2 + 0] = pack_hi2(v.x - __bfloat162float(h0),
                                    v.y - __bfloat162float(h1));
    g_W2lo32[id * 2 + 1] = pack_hi2(v.z - __bfloat162float(h2),
                                    v.w - __bfloat162float(h3));
}

// ---------------------------------------------------------------------------
// Kernel 3: mma.sync bf16 edge GEMM with cp.async double-buffered W2 stream.
// Block = 8 nodes (M=128), N=256, K=256 in 8 chunks of k=32, 2 smem buffers.
// (correctness field-verified in R6)
// ---------------------------------------------------------------------------
#define SA_HI   0
#define SA_LO   65536
#define SB_BASE 131072
#define SB_BUF  32768          // per buffer: hi 16KB + lo 16KB
#define SM_TOTAL 196608

__global__ void __launch_bounds__(EM_THREADS, 1)
edge_mma_kernel(const float* __restrict__ AB,
                const int* __restrict__ idx,
                const float* __restrict__ b2,
                float* __restrict__ out) {
    extern __shared__ char smem[];
    const uint32_t sbase = smem_u32(smem);
    __shared__ int idxs[128];

    const int t    = threadIdx.x;
    const int lane = t & 31;
    const int wid  = t >> 5;
    const int wm   = wid & 3;
    const int wn   = wid >> 2;
    const int i0   = blockIdx.x * NODES_PB;

    if (t < 128) idxs[t] = idx[i0 * KNN + t];
    __syncthreads();

    // ---- prologue: async-load W2 chunk 0 (overlaps gather phase) ----
    {
#pragma unroll
        for (int ii = 0; ii < 2; ii++) {
            const int e = t + ii * EM_THREADS;       // 0..1023
            const int row = e >> 5, c = e & 31;
            const uint32_t dst = sbase + SB_BASE + row * 512 + ((c ^ (row & 7)) * 16);
            const int src = row * 32 + c;
            CP_ASYNC16(dst, (const uint4*)g_W2hi32 + src);
            CP_ASYNC16(dst + 16384, (const uint4*)g_W2lo32 + src);
        }
        CP_ASYNC_COMMIT();
    }

    // ---- Phase A: gather + relu + bf16 split -> smem (rows = edges) ----
    {
        const int r = t >> 2;
        const int q = t & 3;
        const int j = idxs[r];
        const float4* arow = (const float4*)(AB + (size_t)(i0 + (r >> 4)) * 512) + q * 16;
        const float4* brow = (const float4*)(AB + (size_t)j * 512 + 256) + q * 16;
        const int sw_r = r & 7;
        char* smem_c = smem;
#pragma unroll
        for (int w = 0; w < 8; w++) {
            const float4 a0 = arow[w * 2 + 0];
            const float4 a1 = arow[w * 2 + 1];
            const float4 e0 = brow[w * 2 + 0];
            const float4 e1 = brow[w * 2 + 1];
            const float v0 = fmaxf(a0.x + e0.x, 0.0f);
            const float v1 = fmaxf(a0.y + e0.y, 0.0f);
            const float v2 = fmaxf(a0.z + e0.z, 0.0f);
            const float v3 = fmaxf(a0.w + e0.w, 0.0f);
            const float v4 = fmaxf(a1.x + e1.x, 0.0f);
            const float v5 = fmaxf(a1.y + e1.y, 0.0f);
            const float v6 = fmaxf(a1.z + e1.z, 0.0f);
            const float v7 = fmaxf(a1.w + e1.w, 0.0f);
            const __nv_bfloat16 h0 = __float2bfloat16_rn(v0);
            const __nv_bfloat16 h1 = __float2bfloat16_rn(v1);
            const __nv_bfloat16 h2 = __float2bfloat16_rn(v2);
            const __nv_bfloat16 h3 = __float2bfloat16_rn(v3);
            const __nv_bfloat16 h4 = __float2bfloat16_rn(v4);
            const __nv_bfloat16 h5 = __float2bfloat16_rn(v5);
            const __nv_bfloat16 h6 = __float2bfloat16_rn(v6);
            const __nv_bfloat16 h7 = __float2bfloat16_rn(v7);
            uint4 H, L;
            H.x = ((uint32_t)__bfloat16_as_ushort(h1) << 16) | __bfloat16_as_ushort(h0);
            H.y = ((uint32_t)__bfloat16_as_ushort(h3) << 16) | __bfloat16_as_ushort(h2);
            H.z = ((uint32_t)__bfloat16_as_ushort(h5) << 16) | __bfloat16_as_ushort(h4);
            H.w = ((uint32_t)__bfloat16_as_ushort(h7) << 16) | __bfloat16_as_ushort(h6);
            L.x = pack_hi2(v0 - __bfloat162float(h0), v1 - __bfloat162float(h1));
            L.y = pack_hi2(v2 - __bfloat162float(h2), v3 - __bfloat162float(h3));
            L.z = pack_hi2(v4 - __bfloat162float(h4), v5 - __bfloat162float(h5));
            L.w = pack_hi2(v6 - __bfloat162float(h6), v7 - __bfloat162float(h7));
            const int c = (q * 8 + w) ^ sw_r;
            *(uint4*)(smem_c + SA_HI + r * 512 + c * 16) = H;
            *(uint4*)(smem_c + SA_LO + r * 512 + c * 16) = L;
        }
    }
    __syncthreads();

    // ---- Main loop: 8 chunks of k=32, double-buffered ----
    float D[2][8][4];
#pragma unroll
    for (int mt = 0; mt < 2; mt++)
#pragma unroll
        for (int f = 0; f < 8; f++)
#pragma unroll
            for (int c = 0; c < 4; c++) D[mt][f][c] = 0.0f;

    const int a_row  = wm * 32 + (lane & 15);
    const int a_swz  = a_row & 7;
    const uint32_t a_base_hi = sbase + SA_HI + a_row * 512;
    const uint32_t a_base_lo = sbase + SA_LO + a_row * 512;
    const int b_krow  = lane & 15;
    const int b_cbase = wn * 8 + (lane >> 4);

    for (int kc = 0; kc < 8; kc++) {
        if (kc < 7) {
            const int b = (kc + 1) & 1;
#pragma unroll
            for (int ii = 0; ii < 2; ii++) {
                const int e = t + ii * EM_THREADS;
                const int row = e >> 5, c = e & 31;
                const uint32_t dst = sbase + SB_BASE + b * SB_BUF +
                                     row * 512 + ((c ^ (row & 7)) * 16);
                const int src = ((kc + 1) * 32 + row) * 32 + c;
                CP_ASYNC16(dst, (const uint4*)g_W2hi32 + src);
                CP_ASYNC16(dst + 16384, (const uint4*)g_W2lo32 + src);
            }
            CP_ASYNC_COMMIT();
            CP_ASYNC_WAIT(1);
        } else {
            CP_ASYNC_WAIT(0);
        }
        __syncthreads();

        const uint32_t sb = sbase + SB_BASE + (kc & 1) * SB_BUF;
#pragma unroll
        for (int kt = 0; kt < 2; kt++) {
            const int kg = kc * 2 + kt;
            uint32_t ah[2][4], al[2][4];
#pragma unroll
            for (int mt = 0; mt < 2; mt++) {
                const uint32_t roff = mt * 16 * 512;
                const uint32_t c = (uint32_t)((kg * 2 + (lane >> 4)) ^ a_swz) * 16;
                ldsm_x4(ah[mt][0], ah[mt][1], ah[mt][2], ah[mt][3], a_base_hi + roff + c);
                ldsm_x4(al[mt][0], al[mt][1], al[mt][2], al[mt][3], a_base_lo + roff + c);
            }
#pragma unroll
            for (int g = 0; g < 4; g++) {
                const int krow = kt * 16 + b_krow;
                const uint32_t c = (uint32_t)((b_cbase + g * 2) ^ (krow & 7)) * 16;
                const uint32_t baddr = sb + krow * 512 + c;
                uint32_t bh0, bh1, bh2, bh3, bl0, bl1, bl2, bl3;
                ldsm_x4_t(bh0, bh1, bh2, bh3, baddr);
                ldsm_x4_t(bl0, bl1, bl2, bl3, baddr + 16384);
#pragma unroll
                for (int mt = 0; mt < 2; mt++) {
                    float* d0 = D[mt][g * 2 + 0];
                    float* d1 = D[mt][g * 2 + 1];
                    mma_bf16(d0[0], d0[1], d0[2], d0[3],
                             ah[mt][0], ah[mt][1], ah[mt][2], ah[mt][3], bh0, bh1);
                    mma_bf16(d0[0], d0[1], d0[2], d0[3],
                             ah[mt][0], ah[mt][1], ah[mt][2], ah[mt][3], bl0, bl1);
                    mma_bf16(d0[0], d0[1], d0[2], d0[3],
                             al[mt][0], al[mt][1], al[mt][2], al[mt][3], bh0, bh1);
                    mma_bf16(d1[0], d1[1], d1[2], d1[3],
                             ah[mt][0], ah[mt][1], ah[mt][2], ah[mt][3], bh2, bh3);
                    mma_bf16(d1[0], d1[1], d1[2], d1[3],
                             ah[mt][0], ah[mt][1], ah[mt][2], ah[mt][3], bl2, bl3);
                    mma_bf16(d1[0], d1[1], d1[2], d1[3],
                             al[mt][0], al[mt][1], al[mt][2], al[mt][3], bh2, bh3);
                }
            }
        }
        __syncthreads();
    }

    // ---- Epilogue: max over each node's 16 rows (warp-local) + b2 ----
#pragma unroll
    for (int mt = 0; mt < 2; mt++) {
        const int node = i0 + wm * 2 + mt;
#pragma unroll
        for (int f = 0; f < 8; f++) {
            float m0 = fmaxf(D[mt][f][0], D[mt][f][2]);
            float m1 = fmaxf(D[mt][f][1], D[mt][f][3]);
            m0 = fmaxf(m0, __shfl_xor_sync(0xffffffffu, m0, 4));
            m1 = fmaxf(m1, __shfl_xor_sync(0xffffffffu, m1, 4));
            m0 = fmaxf(m0, __shfl_xor_sync(0xffffffffu, m0, 8));
            m1 = fmaxf(m1, __shfl_xor_sync(0xffffffffu, m1, 8));
            m0 = fmaxf(m0, __shfl_xor_sync(0xffffffffu, m0, 16));
            m1 = fmaxf(m1, __shfl_xor_sync(0xffffffffu, m1, 16));
            if ((lane >> 2) == 0) {
                const int col = wn * 64 + f * 8 + 2 * (lane & 3);
                float2 o;
                o.x = m0 + b2[col];
                o.y = m1 + b2[col + 1];
                *(float2*)(out + (size_t)node * DDIM + col) = o;
            }
        }
    }
}

// ---------------------------------------------------------------------------
// Launch: fork gemm1/w2split onto a side stream so they overlap the kNN
// chain in the captured graph (independent until edge_mma joins both).
// ---------------------------------------------------------------------------
extern "C" void kernel_launch(void* const* d_in, const int* in_sizes, int n_in,
                              void* d_out, int out_size) {
    const float* x   = (const float*)d_in[0];
    const float* pos = (const float*)d_in[1];
    const float* W1  = (const float*)d_in[2];
    const float* b1  = (const float*)d_in[3];
    const float* W2  = (const float*)d_in[4];
    const float* b2  = (const float*)d_in[5];
    float* out = (float*)d_out;
    (void)in_sizes; (void)n_in; (void)out_size;

    int*   idx_ptr = nullptr;
    float* ab_ptr  = nullptr;
    cudaGetSymbolAddress((void**)&idx_ptr, g_idx);
    cudaGetSymbolAddress((void**)&ab_ptr, g_AB);

    static bool init_done = false;
    static cudaStream_t s2 = nullptr;
    static cudaEvent_t ev_fork = nullptr, ev_join = nullptr;
    if (!init_done) {
        cudaFuncSetAttribute(edge_mma_kernel,
                             cudaFuncAttributeMaxDynamicSharedMemorySize, SM_TOTAL);
        cudaStreamCreateWithFlags(&s2, cudaStreamNonBlocking);
        cudaEventCreateWithFlags(&ev_fork, cudaEventDisableTiming);
        cudaEventCreateWithFlags(&ev_join, cudaEventDisableTiming);
        init_done = true;
    }

    // fork: side stream runs gemm1 + w2split concurrently with kNN chain
    cudaEventRecord(ev_fork, 0);
    cudaStreamWaitEvent(s2, ev_fork, 0);

    // main stream: grid kNN build + warp-cooperative query
    zero_hist_kernel<<<NCELL / 1024, 1024>>>();
    cell_assign_kernel<<<NPTS / 256, 256>>>(pos);
    scan_kernel<<<1, 1024>>>();
    scatter_kernel<<<NPTS / 256, 256>>>(pos);
    knn_query_kernel<<<NPTS * 32 / 256, 256>>>(idx_ptr);

    // side stream: MLP prep
    gemm1_kernel<<<dim3(512 / 64, NPTS / 64), 256, 0, s2>>>(x, W1, b1, ab_ptr);
    w2split_kernel<<<64, 256, 0, s2>>>(W2);
    cudaEventRecord(ev_join, s2);

    // join, then fused edge GEMM
    cudaStreamWaitEvent(0, ev_join, 0);
    edge_mma_kernel<<<NPTS / NODES_PB, EM_THREADS, SM_TOTAL>>>(ab_ptr, idx_ptr, b2, out);
}

// round 11
// speedup vs baseline: 3.8216x; 1.1307x over previous
#include <cuda_runtime.h>
#include <cuda_bf16.h>
#include <cstdint>

// ---------------------------------------------------------------------------
// Problem constants
// ---------------------------------------------------------------------------
#define NPTS   8192
#define CIN    128
#define DDIM   256
#define KNN    16

#define NODES_PB 8             // nodes per edge-MMA block (M = 8*16 = 128)
#define EM_THREADS 512         // 16 warps: 4 (m) x 4 (n)

// Grid kNN parameters: fat cells so candidate runs are long/contiguous
#define G    16
#define OXC  (-4.0f)
#define CSZ  0.5f
#define NCELL (G * G * G)      // 4096

// Scratch (device globals — no allocation allowed)
__device__ float g_AB[NPTS * 512];
__device__ int   g_idx[NPTS * KNN];
__device__ uint32_t g_W2hi32[32768];        // bf16-hi image, row-major [k][n]
__device__ uint32_t g_W2lo32[32768];        // bf16-lo image
// grid structures
__device__ int    g_hist[NCELL];
__device__ int    g_cstart[NCELL];
__device__ int    g_cptr[NCELL];
__device__ int    g_pcell[NPTS];
__device__ float4 g_spos[NPTS];             // cell-sorted (x,y,z,sq)
__device__ int    g_sid[NPTS];              // sorted -> original index

// ---------------------------------------------------------------------------
// PTX helpers
// ---------------------------------------------------------------------------
__device__ __forceinline__ uint32_t smem_u32(const void* p) {
    uint32_t a;
    asm("{ .reg .u64 t; cvta.to.shared.u64 t, %1; cvt.u32.u64 %0, t; }"
        : "=r"(a) : "l"(p));
    return a;
}
__device__ __forceinline__ void ldsm_x4(uint32_t& r0, uint32_t& r1,
                                        uint32_t& r2, uint32_t& r3, uint32_t addr) {
    asm volatile("ldmatrix.sync.aligned.m8n8.x4.shared.b16 {%0,%1,%2,%3}, [%4];"
                 : "=r"(r0), "=r"(r1), "=r"(r2), "=r"(r3) : "r"(addr));
}
__device__ __forceinline__ void ldsm_x4_t(uint32_t& r0, uint32_t& r1,
                                          uint32_t& r2, uint32_t& r3, uint32_t addr) {
    asm volatile("ldmatrix.sync.aligned.m8n8.x4.trans.shared.b16 {%0,%1,%2,%3}, [%4];"
                 : "=r"(r0), "=r"(r1), "=r"(r2), "=r"(r3) : "r"(addr));
}
__device__ __forceinline__ void mma_bf16(float& d0, float& d1, float& d2, float& d3,
                                         uint32_t a0, uint32_t a1, uint32_t a2, uint32_t a3,
                                         uint32_t b0, uint32_t b1) {
    asm volatile("mma.sync.aligned.m16n8k16.row.col.f32.bf16.bf16.f32 "
                 "{%0,%1,%2,%3}, {%4,%5,%6,%7}, {%8,%9}, {%0,%1,%2,%3};"
                 : "+f"(d0), "+f"(d1), "+f"(d2), "+f"(d3)
                 : "r"(a0), "r"(a1), "r"(a2), "r"(a3), "r"(b0), "r"(b1));
}
__device__ __forceinline__ uint32_t pack_hi2(float v0, float v1) {
    return ((uint32_t)__bfloat16_as_ushort(__float2bfloat16_rn(v1)) << 16) |
           (uint32_t)__bfloat16_as_ushort(__float2bfloat16_rn(v0));
}
#define CP_ASYNC16(dst, src) \
    asm volatile("cp.async.cg.shared.global [%0], [%1], 16;" \
                 :: "r"(dst), "l"(src) : "memory")
#define CP_ASYNC_COMMIT() asm volatile("cp.async.commit_group;" ::: "memory")
#define CP_ASYNC_WAIT(n)  asm volatile("cp.async.wait_group %0;" :: "n"(n) : "memory")

// ---------------------------------------------------------------------------
// Grid build kernels
// ---------------------------------------------------------------------------
__global__ void __launch_bounds__(1024)
zero_hist_kernel() {
    g_hist[blockIdx.x * 1024 + threadIdx.x] = 0;
}

__global__ void __launch_bounds__(256)
cell_assign_kernel(const float* __restrict__ pos) {
    const int i = blockIdx.x * 256 + threadIdx.x;
    const float x = pos[i * 3 + 0];
    const float y = pos[i * 3 + 1];
    const float z = pos[i * 3 + 2];
    const int cx = min(max(__float2int_rd((x - OXC) * (1.0f / CSZ)), 0), G - 1);
    const int cy = min(max(__float2int_rd((y - OXC) * (1.0f / CSZ)), 0), G - 1);
    const int cz = min(max(__float2int_rd((z - OXC) * (1.0f / CSZ)), 0), G - 1);
    const int c = (cz * G + cy) * G + cx;
    g_pcell[i] = c;
    atomicAdd(&g_hist[c], 1);
}

__global__ void __launch_bounds__(1024)
scan_kernel() {
    __shared__ int sd[1024];
    const int t = threadIdx.x;
    int sum = 0;
#pragma unroll
    for (int k = 0; k < NCELL / 1024; k++) sum += g_hist[t * (NCELL / 1024) + k];
    sd[t] = sum;
    __syncthreads();
    for (int off = 1; off < 1024; off <<= 1) {
        const int v = (t >= off) ? sd[t - off] : 0;
        __syncthreads();
        sd[t] += v;
        __syncthreads();
    }
    int run = sd[t] - sum;
#pragma unroll
    for (int k = 0; k < NCELL / 1024; k++) {
        const int c = t * (NCELL / 1024) + k;
        g_cstart[c] = run;
        g_cptr[c]   = run;
        run += g_hist[c];
    }
}

__global__ void __launch_bounds__(256)
scatter_kernel(const float* __restrict__ pos) {
    const int i = blockIdx.x * 256 + threadIdx.x;
    const int c = g_pcell[i];
    const int dst = atomicAdd(&g_cptr[c], 1);
    const float x = pos[i * 3 + 0];
    const float y = pos[i * 3 + 1];
    const float z = pos[i * 3 + 2];
    const float sq = fmaf(z, z, fmaf(y, y, x * x));
    g_spos[dst] = make_float4(x, y, z, sq);
    g_sid[dst] = i;
}

// ---------------------------------------------------------------------------
// Warp-cooperative exact grid kNN query. One warp per query.
// Top-16 kept LANE-DISTRIBUTED: lane l (0..15) holds the l-th smallest
// (bd,bj); lanes 16..31 hold +inf sentinels. Insertion = ballot + ffs +
// one shfl_up shift (~12 instr vs 64 for a replicated network).
// Strict '<' placement: equal elements keep precedence (same order as the
// replicated network that matched the reference).
// ---------------------------------------------------------------------------
#define PROCESS_RUN(c0, c1) do {                                               \
    const int _st = g_cstart[(c0)];                                            \
    const int _en = g_cstart[(c1)] + g_hist[(c1)];                             \
    for (int _jb = _st; _jb < _en; _jb += 32) {                                \
        const int _j = _jb + lane;                                             \
        float _dist = 1e30f;                                                   \
        if (_j < _en) {                                                        \
            const float4 _p = g_spos[_j];                                      \
            const float _dot = fmaf(me.z, _p.z, fmaf(me.y, _p.y, me.x * _p.x));\
            _dist = fmaf(-2.0f, _dot, me.w + _p.w);                            \
            if (_j == q) _dist = 1e30f;                                        \
        }                                                                      \
        unsigned _m = __ballot_sync(0xffffffffu, _dist < kth);                 \
        while (_m) {                                                           \
            const int _src = __ffs(_m) - 1; _m &= _m - 1;                      \
            const float _d = __shfl_sync(0xffffffffu, _dist, _src);            \
            if (_d < kth) {                                                    \
                const int _id = _jb + _src;                                    \
                const unsigned _mk =                                           \
                    __ballot_sync(0xffffffffu, bd > _d) & 0xFFFFu;             \
                const int _pos = __ffs(_mk) - 1;   /* nonzero: bd15=kth>_d */  \
                const float _bdu = __shfl_up_sync(0xffffffffu, bd, 1);         \
                const int   _bju = __shfl_up_sync(0xffffffffu, bj, 1);         \
                if (lane >= _pos && lane < KNN) { bd = _bdu; bj = _bju; }      \
                if (lane == _pos) { bd = _d; bj = _id; }                       \
                kth = __shfl_sync(0xffffffffu, bd, KNN - 1);                   \
            }                                                                  \
        }                                                                      \
    }                                                                          \
} while (0)

__global__ void __launch_bounds__(256)
knn_query_kernel(int* __restrict__ idxout) {
    const int q    = (blockIdx.x * 256 + threadIdx.x) >> 5;   // one warp per query
    const int lane = threadIdx.x & 31;

    const float4 me = g_spos[q];
    const int cx = min(max(__float2int_rd((me.x - OXC) * (1.0f / CSZ)), 0), G - 1);
    const int cy = min(max(__float2int_rd((me.y - OXC) * (1.0f / CSZ)), 0), G - 1);
    const int cz = min(max(__float2int_rd((me.z - OXC) * (1.0f / CSZ)), 0), G - 1);

    float bd  = 1e30f;   // lane-distributed sorted list (lanes 0..15)
    int   bj  = -1;
    float kth = 1e30f;   // current 16th-best (lane 15's bd), warp-uniform

    for (int R = 0; R < G; R++) {
        const int zlo = max(cz - R, 0), zhi = min(cz + R, G - 1);
        const int ylo = max(cy - R, 0), yhi = min(cy + R, G - 1);
        const int xlo = max(cx - R, 0), xhi = min(cx + R, G - 1);
        for (int z = zlo; z <= zhi; z++) {
            const int adz = (z > cz) ? (z - cz) : (cz - z);
            for (int y = ylo; y <= yhi; y++) {
                const int ady = (y > cy) ? (y - cy) : (cy - y);
                const int rowc = (z * G + y) * G;
                if (adz == R || ady == R) {
                    PROCESS_RUN(rowc + xlo, rowc + xhi);   // whole row, contiguous
                } else {
                    if (cx - R >= 0) PROCESS_RUN(rowc + cx - R, rowc + cx - R);
                    if (cx + R < G)  PROCESS_RUN(rowc + cx + R, rowc + cx + R);
                }
            }
        }
        // exact stop bound: distance to faces of the processed region
        const float dxl = (cx - R > 0)     ? (me.x - (OXC + (cx - R) * CSZ))     : 1e30f;
        const float dxr = (cx + R + 1 < G) ? ((OXC + (cx + R + 1) * CSZ) - me.x) : 1e30f;
        const float dyl = (cy - R > 0)     ? (me.y - (OXC + (cy - R) * CSZ))     : 1e30f;
        const float dyr = (cy + R + 1 < G) ? ((OXC + (cy + R + 1) * CSZ) - me.y) : 1e30f;
        const float dzl = (cz - R > 0)     ? (me.z - (OXC + (cz - R) * CSZ))     : 1e30f;
        const float dzr = (cz + R + 1 < G) ? ((OXC + (cz + R + 1) * CSZ) - me.z) : 1e30f;
        const float dmin = fminf(fminf(fminf(dxl, dxr), fminf(dyl, dyr)),
                                 fminf(dzl, dzr));
        if (dmin * dmin >= kth) break;
    }

    if (lane < KNN) {
        const int orig = g_sid[q];
        idxout[orig * KNN + lane] = g_sid[bj];
    }
}

// ---------------------------------------------------------------------------
// Kernel 2: AB = X @ [W1top - W1bot | W1bot], b1 folded into A columns
// ---------------------------------------------------------------------------
__global__ void __launch_bounds__(256)
gemm1_kernel(const float* __restrict__ X,
             const float* __restrict__ W1,
             const float* __restrict__ b1,
             float* __restrict__ AB) {
    __shared__ float As[16][65];
    __shared__ float Bs[16][64];

    const int bm = blockIdx.y * 64;
    const int bn = blockIdx.x * 64;
    const int t  = threadIdx.x;
    const int tx = t & 15;
    const int ty = t >> 4;

    float acc[4][4];
#pragma unroll
    for (int a = 0; a < 4; a++)
#pragma unroll
        for (int b = 0; b < 4; b++) acc[a][b] = 0.0f;

    for (int k0 = 0; k0 < CIN; k0 += 16) {
#pragma unroll
        for (int r = 0; r < 4; r++) {
            const int e = t + r * 256;
            const int m = e >> 4, k = e & 15;
            As[k][m] = X[(bm + m) * CIN + k0 + k];
        }
#pragma unroll
        for (int r = 0; r < 4; r++) {
            const int e = t + r * 256;
            const int k = e >> 6, n = e & 63;
            const int gk = k0 + k, gn = bn + n;
            float v;
            if (gn < 256)
                v = W1[gk * 256 + gn] - W1[(gk + 128) * 256 + gn];
            else
                v = W1[(gk + 128) * 256 + (gn - 256)];
            Bs[k][n] = v;
        }
        __syncthreads();

#pragma unroll
        for (int k = 0; k < 16; k++) {
            float a0 = As[k][ty * 4 + 0];
            float a1 = As[k][ty * 4 + 1];
            float a2 = As[k][ty * 4 + 2];
            float a3 = As[k][ty * 4 + 3];
            float b0 = Bs[k][tx * 4 + 0];
            float c1 = Bs[k][tx * 4 + 1];
            float c2 = Bs[k][tx * 4 + 2];
            float b3 = Bs[k][tx * 4 + 3];
            acc[0][0] = fmaf(a0, b0, acc[0][0]); acc[0][1] = fmaf(a0, c1, acc[0][1]);
            acc[0][2] = fmaf(a0, c2, acc[0][2]); acc[0][3] = fmaf(a0, b3, acc[0][3]);
            acc[1][0] = fmaf(a1, b0, acc[1][0]); acc[1][1] = fmaf(a1, c1, acc[1][1]);
            acc[1][2] = fmaf(a1, c2, acc[1][2]); acc[1][3] = fmaf(a1, b3, acc[1][3]);
            acc[2][0] = fmaf(a2, b0, acc[2][0]); acc[2][1] = fmaf(a2, c1, acc[2][1]);
            acc[2][2] = fmaf(a2, c2, acc[2][2]); acc[2][3] = fmaf(a2, b3, acc[2][3]);
            acc[3][0] = fmaf(a3, b0, acc[3][0]); acc[3][1] = fmaf(a3, c1, acc[3][1]);
            acc[3][2] = fmaf(a3, c2, acc[3][2]); acc[3][3] = fmaf(a3, b3, acc[3][3]);
        }
        __syncthreads();
    }

#pragma unroll
    for (int ii = 0; ii < 4; ii++)
#pragma unroll
        for (int jj = 0; jj < 4; jj++) {
            const int gn = bn + tx * 4 + jj;
            const float bias = (gn < 256) ? b1[gn] : 0.0f;
            AB[(bm + ty * 4 + ii) * 512 + gn] = acc[ii][jj] + bias;
        }
}

// ---------------------------------------------------------------------------
// Kernel 2b: split W2 into bf16 hi/lo row-major [k][n] images
// ---------------------------------------------------------------------------
__global__ void __launch_bounds__(256)
w2split_kernel(const float* __restrict__ W2) {
    const int id = blockIdx.x * 256 + threadIdx.x;
    const float4 v = ((const float4*)W2)[id];

    const __nv_bfloat16 h0 = __float2bfloat16_rn(v.x);
    const __nv_bfloat16 h1 = __float2bfloat16_rn(v.y);
    const __nv_bfloat16 h2 = __float2bfloat16_rn(v.z);
    const __nv_bfloat16 h3 = __float2bfloat16_rn(v.w);

    g_W2hi32[id * 2 + 0] = ((uint32_t)__bfloat16_as_ushort(h1) << 16) |
                           (uint32_t)__bfloat16_as_ushort(h0);
    g_W2hi32[id * 2 + 1] = ((uint32_t)__bfloat16_as_ushort(h3) << 16) |
                           (uint32_t)__bfloat16_as_ushort(h2);
    g_W2lo32[id * 2 + 0] = pack_hi2(v.x - __bfloat162float(h0),
                                    v.y - __bfloat162float(h1));
    g_W2lo32[id * 2 + 1] = pack_hi2(v.z - __bfloat162float(h2),
                                    v.w - __bfloat162float(h3));
}

// ---------------------------------------------------------------------------
// Kernel 3: mma.sync bf16 edge GEMM with cp.async double-buffered W2 stream.
// Block = 8 nodes (M=128), N=256, K=256 in 8 chunks of k=32, 2 smem buffers.
// ---------------------------------------------------------------------------
#define SA_HI   0
#define SA_LO   65536
#define SB_BASE 131072
#define SB_BUF  32768          // per buffer: hi 16KB + lo 16KB
#define SM_TOTAL 196608

__global__ void __launch_bounds__(EM_THREADS, 1)
edge_mma_kernel(const float* __restrict__ AB,
                const int* __restrict__ idx,
                const float* __restrict__ b2,
                float* __restrict__ out) {
    extern __shared__ char smem[];
    const uint32_t sbase = smem_u32(smem);
    __shared__ int idxs[128];

    const int t    = threadIdx.x;
    const int lane = t & 31;
    const int wid  = t >> 5;
    const int wm   = wid & 3;
    const int wn   = wid >> 2;
    const int i0   = blockIdx.x * NODES_PB;

    if (t < 128) idxs[t] = idx[i0 * KNN + t];
    __syncthreads();

    // ---- prologue: async-load W2 chunk 0 (overlaps gather phase) ----
    {
#pragma unroll
        for (int ii = 0; ii < 2; ii++) {
            const int e = t + ii * EM_THREADS;       // 0..1023
            const int row = e >> 5, c = e & 31;
            const uint32_t dst = sbase + SB_BASE + row * 512 + ((c ^ (row & 7)) * 16);
            const int src = row * 32 + c;
            CP_ASYNC16(dst, (const uint4*)g_W2hi32 + src);
            CP_ASYNC16(dst + 16384, (const uint4*)g_W2lo32 + src);
        }
        CP_ASYNC_COMMIT();
    }

    // ---- Phase A: gather + relu + bf16 split -> smem (rows = edges) ----
    {
        const int r = t >> 2;
        const int q = t & 3;
        const int j = idxs[r];
        const float4* arow = (const float4*)(AB + (size_t)(i0 + (r >> 4)) * 512) + q * 16;
        const float4* brow = (const float4*)(AB + (size_t)j * 512 + 256) + q * 16;
        const int sw_r = r & 7;
        char* smem_c = smem;
#pragma unroll
        for (int w = 0; w < 8; w++) {
            const float4 a0 = arow[w * 2 + 0];
            const float4 a1 = arow[w * 2 + 1];
            const float4 e0 = brow[w * 2 + 0];
            const float4 e1 = brow[w * 2 + 1];
            const float v0 = fmaxf(a0.x + e0.x, 0.0f);
            const float v1 = fmaxf(a0.y + e0.y, 0.0f);
            const float v2 = fmaxf(a0.z + e0.z, 0.0f);
            const float v3 = fmaxf(a0.w + e0.w, 0.0f);
            const float v4 = fmaxf(a1.x + e1.x, 0.0f);
            const float v5 = fmaxf(a1.y + e1.y, 0.0f);
            const float v6 = fmaxf(a1.z + e1.z, 0.0f);
            const float v7 = fmaxf(a1.w + e1.w, 0.0f);
            const __nv_bfloat16 h0 = __float2bfloat16_rn(v0);
            const __nv_bfloat16 h1 = __float2bfloat16_rn(v1);
            const __nv_bfloat16 h2 = __float2bfloat16_rn(v2);
            const __nv_bfloat16 h3 = __float2bfloat16_rn(v3);
            const __nv_bfloat16 h4 = __float2bfloat16_rn(v4);
            const __nv_bfloat16 h5 = __float2bfloat16_rn(v5);
            const __nv_bfloat16 h6 = __float2bfloat16_rn(v6);
            const __nv_bfloat16 h7 = __float2bfloat16_rn(v7);
            uint4 H, L;
            H.x = ((uint32_t)__bfloat16_as_ushort(h1) << 16) | __bfloat16_as_ushort(h0);
            H.y = ((uint32_t)__bfloat16_as_ushort(h3) << 16) | __bfloat16_as_ushort(h2);
            H.z = ((uint32_t)__bfloat16_as_ushort(h5) << 16) | __bfloat16_as_ushort(h4);
            H.w = ((uint32_t)__bfloat16_as_ushort(h7) << 16) | __bfloat16_as_ushort(h6);
            L.x = pack_hi2(v0 - __bfloat162float(h0), v1 - __bfloat162float(h1));
            L.y = pack_hi2(v2 - __bfloat162float(h2), v3 - __bfloat162float(h3));
            L.z = pack_hi2(v4 - __bfloat162float(h4), v5 - __bfloat162float(h5));
            L.w = pack_hi2(v6 - __bfloat162float(h6), v7 - __bfloat162float(h7));
            const int c = (q * 8 + w) ^ sw_r;
            *(uint4*)(smem_c + SA_HI + r * 512 + c * 16) = H;
            *(uint4*)(smem_c + SA_LO + r * 512 + c * 16) = L;
        }
    }
    __syncthreads();

    // ---- Main loop: 8 chunks of k=32, double-buffered ----
    float D[2][8][4];
#pragma unroll
    for (int mt = 0; mt < 2; mt++)
#pragma unroll
        for (int f = 0; f < 8; f++)
#pragma unroll
            for (int c = 0; c < 4; c++) D[mt][f][c] = 0.0f;

    const int a_row  = wm * 32 + (lane & 15);
    const int a_swz  = a_row & 7;
    const uint32_t a_base_hi = sbase + SA_HI + a_row * 512;
    const uint32_t a_base_lo = sbase + SA_LO + a_row * 512;
    const int b_krow  = lane & 15;
    const int b_cbase = wn * 8 + (lane >> 4);

    for (int kc = 0; kc < 8; kc++) {
        if (kc < 7) {
            const int b = (kc + 1) & 1;
#pragma unroll
            for (int ii = 0; ii < 2; ii++) {
                const int e = t + ii * EM_THREADS;
                const int row = e >> 5, c = e & 31;
                const uint32_t dst = sbase + SB_BASE + b * SB_BUF +
                                     row * 512 + ((c ^ (row & 7)) * 16);
                const int src = ((kc + 1) * 32 + row) * 32 + c;
                CP_ASYNC16(dst, (const uint4*)g_W2hi32 + src);
                CP_ASYNC16(dst + 16384, (const uint4*)g_W2lo32 + src);
            }
            CP_ASYNC_COMMIT();
            CP_ASYNC_WAIT(1);
        } else {
            CP_ASYNC_WAIT(0);
        }
        __syncthreads();

        const uint32_t sb = sbase + SB_BASE + (kc & 1) * SB_BUF;
#pragma unroll
        for (int kt = 0; kt < 2; kt++) {
            const int kg = kc * 2 + kt;
            uint32_t ah[2][4], al[2][4];
#pragma unroll
            for (int mt = 0; mt < 2; mt++) {
                const uint32_t roff = mt * 16 * 512;
                const uint32_t c = (uint32_t)((kg * 2 + (lane >> 4)) ^ a_swz) * 16;
                ldsm_x4(ah[mt][0], ah[mt][1], ah[mt][2], ah[mt][3], a_base_hi + roff + c);
                ldsm_x4(al[mt][0], al[mt][1], al[mt][2], al[mt][3], a_base_lo + roff + c);
            }
#pragma unroll
            for (int g = 0; g < 4; g++) {
                const int krow = kt * 16 + b_krow;
                const uint32_t c = (uint32_t)((b_cbase + g * 2) ^ (krow & 7)) * 16;
                const uint32_t baddr = sb + krow * 512 + c;
                uint32_t bh0, bh1, bh2, bh3, bl0, bl1, bl2, bl3;
                ldsm_x4_t(bh0, bh1, bh2, bh3, baddr);
                ldsm_x4_t(bl0, bl1, bl2, bl3, baddr + 16384);
#pragma unroll
                for (int mt = 0; mt < 2; mt++) {
                    float* d0 = D[mt][g * 2 + 0];
                    float* d1 = D[mt][g * 2 + 1];
                    mma_bf16(d0[0], d0[1], d0[2], d0[3],
                             ah[mt][0], ah[mt][1], ah[mt][2], ah[mt][3], bh0, bh1);
                    mma_bf16(d0[0], d0[1], d0[2], d0[3],
                             ah[mt][0], ah[mt][1], ah[mt][2], ah[mt][3], bl0, bl1);
                    mma_bf16(d0[0], d0[1], d0[2], d0[3],
                             al[mt][0], al[mt][1], al[mt][2], al[mt][3], bh0, bh1);
                    mma_bf16(d1[0], d1[1], d1[2], d1[3],
                             ah[mt][0], ah[mt][1], ah[mt][2], ah[mt][3], bh2, bh3);
                    mma_bf16(d1[0], d1[1], d1[2], d1[3],
                             ah[mt][0], ah[mt][1], ah[mt][2], ah[mt][3], bl2, bl3);
                    mma_bf16(d1[0], d1[1], d1[2], d1[3],
                             al[mt][0], al[mt][1], al[mt][2], al[mt][3], bh2, bh3);
                }
            }
        }
        __syncthreads();
    }

    // ---- Epilogue: max over each node's 16 rows (warp-local) + b2 ----
#pragma unroll
    for (int mt = 0; mt < 2; mt++) {
        const int node = i0 + wm * 2 + mt;
#pragma unroll
        for (int f = 0; f < 8; f++) {
            float m0 = fmaxf(D[mt][f][0], D[mt][f][2]);
            float m1 = fmaxf(D[mt][f][1], D[mt][f][3]);
            m0 = fmaxf(m0, __shfl_xor_sync(0xffffffffu, m0, 4));
            m1 = fmaxf(m1, __shfl_xor_sync(0xffffffffu, m1, 4));
            m0 = fmaxf(m0, __shfl_xor_sync(0xffffffffu, m0, 8));
            m1 = fmaxf(m1, __shfl_xor_sync(0xffffffffu, m1, 8));
            m0 = fmaxf(m0, __shfl_xor_sync(0xffffffffu, m0, 16));
            m1 = fmaxf(m1, __shfl_xor_sync(0xffffffffu, m1, 16));
            if ((lane >> 2) == 0) {
                const int col = wn * 64 + f * 8 + 2 * (lane & 3);
                float2 o;
                o.x = m0 + b2[col];
                o.y = m1 + b2[col + 1];
                *(float2*)(out + (size_t)node * DDIM + col) = o;
            }
        }
    }
}

// ---------------------------------------------------------------------------
// Launch: fork gemm1/w2split onto a side stream so they overlap the kNN
// chain in the captured graph (independent until edge_mma joins both).
// ---------------------------------------------------------------------------
extern "C" void kernel_launch(void* const* d_in, const int* in_sizes, int n_in,
                              void* d_out, int out_size) {
    const float* x   = (const float*)d_in[0];
    const float* pos = (const float*)d_in[1];
    const float* W1  = (const float*)d_in[2];
    const float* b1  = (const float*)d_in[3];
    const float* W2  = (const float*)d_in[4];
    const float* b2  = (const float*)d_in[5];
    float* out = (float*)d_out;
    (void)in_sizes; (void)n_in; (void)out_size;

    int*   idx_ptr = nullptr;
    float* ab_ptr  = nullptr;
    cudaGetSymbolAddress((void**)&idx_ptr, g_idx);
    cudaGetSymbolAddress((void**)&ab_ptr, g_AB);

    static bool init_done = false;
    static cudaStream_t s2 = nullptr;
    static cudaEvent_t ev_fork = nullptr, ev_join = nullptr;
    if (!init_done) {
        cudaFuncSetAttribute(edge_mma_kernel,
                             cudaFuncAttributeMaxDynamicSharedMemorySize, SM_TOTAL);
        cudaStreamCreateWithFlags(&s2, cudaStreamNonBlocking);
        cudaEventCreateWithFlags(&ev_fork, cudaEventDisableTiming);
        cudaEventCreateWithFlags(&ev_join, cudaEventDisableTiming);
        init_done = true;
    }

    // fork: side stream runs gemm1 + w2split concurrently with kNN chain
    cudaEventRecord(ev_fork, 0);
    cudaStreamWaitEvent(s2, ev_fork, 0);

    // main stream: grid kNN build + warp-cooperative query
    zero_hist_kernel<<<NCELL / 1024, 1024>>>();
    cell_assign_kernel<<<NPTS / 256, 256>>>(pos);
    scan_kernel<<<1, 1024>>>();
    scatter_kernel<<<NPTS / 256, 256>>>(pos);
    knn_query_kernel<<<NPTS * 32 / 256, 256>>>(idx_ptr);

    // side stream: MLP prep
    gemm1_kernel<<<dim3(512 / 64, NPTS / 64), 256, 0, s2>>>(x, W1, b1, ab_ptr);
    w2split_kernel<<<64, 256, 0, s2>>>(W2);
    cudaEventRecord(ev_join, s2);

    // join, then fused edge GEMM
    cudaStreamWaitEvent(0, ev_join, 0);
    edge_mma_kernel<<<NPTS / NODES_PB, EM_THREADS, SM_TOTAL>>>(ab_ptr, idx_ptr, b2, out);
}

// round 12
// speedup vs baseline: 4.4260x; 1.1581x over previous
#include <cuda_runtime.h>
#include <cuda_bf16.h>
#include <cuda_fp16.h>
#include <cstdint>

// ---------------------------------------------------------------------------
// Problem constants
// ---------------------------------------------------------------------------
#define NPTS   8192
#define CIN    128
#define DDIM   256
#define KNN    16

#define NODES_PB 8             // nodes per edge-MMA block (M = 8*16 = 128)
#define EM_THREADS 512         // 16 warps: 4 (m) x 4 (n)

// Grid kNN parameters: fat cells so candidate runs are long/contiguous
#define G    16
#define OXC  (-4.0f)
#define CSZ  0.5f
#define NCELL (G * G * G)      // 4096

// Scratch (device globals — no allocation allowed)
__device__ float g_AB[NPTS * 512];
__device__ int   g_idx[NPTS * KNN];
__device__ uint32_t g_W2hi32[32768];        // fp16-hi image, row-major [k][n]
__device__ uint32_t g_W2lo32[32768];        // fp16-lo image (W2 - hi)
// grid structures
__device__ int    g_hist[NCELL];
__device__ int    g_cstart[NCELL];
__device__ int    g_cptr[NCELL];
__device__ int    g_pcell[NPTS];
__device__ float4 g_spos[NPTS];             // cell-sorted (x,y,z,sq)
__device__ int    g_sid[NPTS];              // sorted -> original index

// ---------------------------------------------------------------------------
// PTX helpers
// ---------------------------------------------------------------------------
__device__ __forceinline__ uint32_t smem_u32(const void* p) {
    uint32_t a;
    asm("{ .reg .u64 t; cvta.to.shared.u64 t, %1; cvt.u32.u64 %0, t; }"
        : "=r"(a) : "l"(p));
    return a;
}
__device__ __forceinline__ void ldsm_x4(uint32_t& r0, uint32_t& r1,
                                        uint32_t& r2, uint32_t& r3, uint32_t addr) {
    asm volatile("ldmatrix.sync.aligned.m8n8.x4.shared.b16 {%0,%1,%2,%3}, [%4];"
                 : "=r"(r0), "=r"(r1), "=r"(r2), "=r"(r3) : "r"(addr));
}
__device__ __forceinline__ void ldsm_x4_t(uint32_t& r0, uint32_t& r1,
                                          uint32_t& r2, uint32_t& r3, uint32_t addr) {
    asm volatile("ldmatrix.sync.aligned.m8n8.x4.trans.shared.b16 {%0,%1,%2,%3}, [%4];"
                 : "=r"(r0), "=r"(r1), "=r"(r2), "=r"(r3) : "r"(addr));
}
__device__ __forceinline__ void mma_f16(float& d0, float& d1, float& d2, float& d3,
                                        uint32_t a0, uint32_t a1, uint32_t a2, uint32_t a3,
                                        uint32_t b0, uint32_t b1) {
    asm volatile("mma.sync.aligned.m16n8k16.row.col.f32.f16.f16.f32 "
                 "{%0,%1,%2,%3}, {%4,%5,%6,%7}, {%8,%9}, {%0,%1,%2,%3};"
                 : "+f"(d0), "+f"(d1), "+f"(d2), "+f"(d3)
                 : "r"(a0), "r"(a1), "r"(a2), "r"(a3), "r"(b0), "r"(b1));
}
__device__ __forceinline__ uint32_t pack_h2(float v0, float v1) {
    return ((uint32_t)__half_as_ushort(__float2half_rn(v1)) << 16) |
           (uint32_t)__half_as_ushort(__float2half_rn(v0));
}
#define CP_ASYNC16(dst, src) \
    asm volatile("cp.async.cg.shared.global [%0], [%1], 16;" \
                 :: "r"(dst), "l"(src) : "memory")
#define CP_ASYNC_COMMIT() asm volatile("cp.async.commit_group;" ::: "memory")
#define CP_ASYNC_WAIT(n)  asm volatile("cp.async.wait_group %0;" :: "n"(n) : "memory")

// ---------------------------------------------------------------------------
// Grid build kernels
// ---------------------------------------------------------------------------
__global__ void __launch_bounds__(1024)
zero_hist_kernel() {
    g_hist[blockIdx.x * 1024 + threadIdx.x] = 0;
}

__global__ void __launch_bounds__(256)
cell_assign_kernel(const float* __restrict__ pos) {
    const int i = blockIdx.x * 256 + threadIdx.x;
    const float x = pos[i * 3 + 0];
    const float y = pos[i * 3 + 1];
    const float z = pos[i * 3 + 2];
    const int cx = min(max(__float2int_rd((x - OXC) * (1.0f / CSZ)), 0), G - 1);
    const int cy = min(max(__float2int_rd((y - OXC) * (1.0f / CSZ)), 0), G - 1);
    const int cz = min(max(__float2int_rd((z - OXC) * (1.0f / CSZ)), 0), G - 1);
    const int c = (cz * G + cy) * G + cx;
    g_pcell[i] = c;
    atomicAdd(&g_hist[c], 1);
}

__global__ void __launch_bounds__(1024)
scan_kernel() {
    __shared__ int sd[1024];
    const int t = threadIdx.x;
    int sum = 0;
#pragma unroll
    for (int k = 0; k < NCELL / 1024; k++) sum += g_hist[t * (NCELL / 1024) + k];
    sd[t] = sum;
    __syncthreads();
    for (int off = 1; off < 1024; off <<= 1) {
        const int v = (t >= off) ? sd[t - off] : 0;
        __syncthreads();
        sd[t] += v;
        __syncthreads();
    }
    int run = sd[t] - sum;
#pragma unroll
    for (int k = 0; k < NCELL / 1024; k++) {
        const int c = t * (NCELL / 1024) + k;
        g_cstart[c] = run;
        g_cptr[c]   = run;
        run += g_hist[c];
    }
}

__global__ void __launch_bounds__(256)
scatter_kernel(const float* __restrict__ pos) {
    const int i = blockIdx.x * 256 + threadIdx.x;
    const int c = g_pcell[i];
    const int dst = atomicAdd(&g_cptr[c], 1);
    const float x = pos[i * 3 + 0];
    const float y = pos[i * 3 + 1];
    const float z = pos[i * 3 + 2];
    const float sq = fmaf(z, z, fmaf(y, y, x * x));
    g_spos[dst] = make_float4(x, y, z, sq);
    g_sid[dst] = i;
}

// ---------------------------------------------------------------------------
// Warp-cooperative exact grid kNN query. One warp per query.
// Lane-distributed sorted top-16 (lanes 0..15), ballot+ffs+shfl_up insertion.
// ---------------------------------------------------------------------------
#define PROCESS_RUN(c0, c1) do {                                               \
    const int _st = g_cstart[(c0)];                                            \
    const int _en = g_cstart[(c1)] + g_hist[(c1)];                             \
    for (int _jb = _st; _jb < _en; _jb += 32) {                                \
        const int _j = _jb + lane;                                             \
        float _dist = 1e30f;                                                   \
        if (_j < _en) {                                                        \
            const float4 _p = g_spos[_j];                                      \
            const float _dot = fmaf(me.z, _p.z, fmaf(me.y, _p.y, me.x * _p.x));\
            _dist = fmaf(-2.0f, _dot, me.w + _p.w);                            \
            if (_j == q) _dist = 1e30f;                                        \
        }                                                                      \
        unsigned _m = __ballot_sync(0xffffffffu, _dist < kth);                 \
        while (_m) {                                                           \
            const int _src = __ffs(_m) - 1; _m &= _m - 1;                      \
            const float _d = __shfl_sync(0xffffffffu, _dist, _src);            \
            if (_d < kth) {                                                    \
                const int _id = _jb + _src;                                    \
                const unsigned _mk =                                           \
                    __ballot_sync(0xffffffffu, bd > _d) & 0xFFFFu;             \
                const int _pos = __ffs(_mk) - 1;   /* nonzero: bd15=kth>_d */  \
                const float _bdu = __shfl_up_sync(0xffffffffu, bd, 1);         \
                const int   _bju = __shfl_up_sync(0xffffffffu, bj, 1);         \
                if (lane >= _pos && lane < KNN) { bd = _bdu; bj = _bju; }      \
                if (lane == _pos) { bd = _d; bj = _id; }                       \
                kth = __shfl_sync(0xffffffffu, bd, KNN - 1);                   \
            }                                                                  \
        }                                                                      \
    }                                                                          \
} while (0)

__global__ void __launch_bounds__(256)
knn_query_kernel(int* __restrict__ idxout) {
    const int q    = (blockIdx.x * 256 + threadIdx.x) >> 5;   // one warp per query
    const int lane = threadIdx.x & 31;

    const float4 me = g_spos[q];
    const int cx = min(max(__float2int_rd((me.x - OXC) * (1.0f / CSZ)), 0), G - 1);
    const int cy = min(max(__float2int_rd((me.y - OXC) * (1.0f / CSZ)), 0), G - 1);
    const int cz = min(max(__float2int_rd((me.z - OXC) * (1.0f / CSZ)), 0), G - 1);

    float bd  = 1e30f;   // lane-distributed sorted list (lanes 0..15)
    int   bj  = -1;
    float kth = 1e30f;   // current 16th-best, warp-uniform

    for (int R = 0; R < G; R++) {
        const int zlo = max(cz - R, 0), zhi = min(cz + R, G - 1);
        const int ylo = max(cy - R, 0), yhi = min(cy + R, G - 1);
        const int xlo = max(cx - R, 0), xhi = min(cx + R, G - 1);
        for (int z = zlo; z <= zhi; z++) {
            const int adz = (z > cz) ? (z - cz) : (cz - z);
            for (int y = ylo; y <= yhi; y++) {
                const int ady = (y > cy) ? (y - cy) : (cy - y);
                const int rowc = (z * G + y) * G;
                if (adz == R || ady == R) {
                    PROCESS_RUN(rowc + xlo, rowc + xhi);   // whole row, contiguous
                } else {
                    if (cx - R >= 0) PROCESS_RUN(rowc + cx - R, rowc + cx - R);
                    if (cx + R < G)  PROCESS_RUN(rowc + cx + R, rowc + cx + R);
                }
            }
        }
        // exact stop bound: distance to faces of the processed region
        const float dxl = (cx - R > 0)     ? (me.x - (OXC + (cx - R) * CSZ))     : 1e30f;
        const float dxr = (cx + R + 1 < G) ? ((OXC + (cx + R + 1) * CSZ) - me.x) : 1e30f;
        const float dyl = (cy - R > 0)     ? (me.y - (OXC + (cy - R) * CSZ))     : 1e30f;
        const float dyr = (cy + R + 1 < G) ? ((OXC + (cy + R + 1) * CSZ) - me.y) : 1e30f;
        const float dzl = (cz - R > 0)     ? (me.z - (OXC + (cz - R) * CSZ))     : 1e30f;
        const float dzr = (cz + R + 1 < G) ? ((OXC + (cz + R + 1) * CSZ) - me.z) : 1e30f;
        const float dmin = fminf(fminf(fminf(dxl, dxr), fminf(dyl, dyr)),
                                 fminf(dzl, dzr));
        if (dmin * dmin >= kth) break;
    }

    if (lane < KNN) {
        const int orig = g_sid[q];
        idxout[orig * KNN + lane] = g_sid[bj];
    }
}

// ---------------------------------------------------------------------------
// Kernel 2: AB = X @ [W1top - W1bot | W1bot], b1 folded into A columns
// ---------------------------------------------------------------------------
__global__ void __launch_bounds__(256)
gemm1_kernel(const float* __restrict__ X,
             const float* __restrict__ W1,
             const float* __restrict__ b1,
             float* __restrict__ AB) {
    __shared__ float As[16][65];
    __shared__ float Bs[16][64];

    const int bm = blockIdx.y * 64;
    const int bn = blockIdx.x * 64;
    const int t  = threadIdx.x;
    const int tx = t & 15;
    const int ty = t >> 4;

    float acc[4][4];
#pragma unroll
    for (int a = 0; a < 4; a++)
#pragma unroll
        for (int b = 0; b < 4; b++) acc[a][b] = 0.0f;

    for (int k0 = 0; k0 < CIN; k0 += 16) {
#pragma unroll
        for (int r = 0; r < 4; r++) {
            const int e = t + r * 256;
            const int m = e >> 4, k = e & 15;
            As[k][m] = X[(bm + m) * CIN + k0 + k];
        }
#pragma unroll
        for (int r = 0; r < 4; r++) {
            const int e = t + r * 256;
            const int k = e >> 6, n = e & 63;
            const int gk = k0 + k, gn = bn + n;
            float v;
            if (gn < 256)
                v = W1[gk * 256 + gn] - W1[(gk + 128) * 256 + gn];
            else
                v = W1[(gk + 128) * 256 + (gn - 256)];
            Bs[k][n] = v;
        }
        __syncthreads();

#pragma unroll
        for (int k = 0; k < 16; k++) {
            float a0 = As[k][ty * 4 + 0];
            float a1 = As[k][ty * 4 + 1];
            float a2 = As[k][ty * 4 + 2];
            float a3 = As[k][ty * 4 + 3];
            float b0 = Bs[k][tx * 4 + 0];
            float c1 = Bs[k][tx * 4 + 1];
            float c2 = Bs[k][tx * 4 + 2];
            float b3 = Bs[k][tx * 4 + 3];
            acc[0][0] = fmaf(a0, b0, acc[0][0]); acc[0][1] = fmaf(a0, c1, acc[0][1]);
            acc[0][2] = fmaf(a0, c2, acc[0][2]); acc[0][3] = fmaf(a0, b3, acc[0][3]);
            acc[1][0] = fmaf(a1, b0, acc[1][0]); acc[1][1] = fmaf(a1, c1, acc[1][1]);
            acc[1][2] = fmaf(a1, c2, acc[1][2]); acc[1][3] = fmaf(a1, b3, acc[1][3]);
            acc[2][0] = fmaf(a2, b0, acc[2][0]); acc[2][1] = fmaf(a2, c1, acc[2][1]);
            acc[2][2] = fmaf(a2, c2, acc[2][2]); acc[2][3] = fmaf(a2, b3, acc[2][3]);
            acc[3][0] = fmaf(a3, b0, acc[3][0]); acc[3][1] = fmaf(a3, c1, acc[3][1]);
            acc[3][2] = fmaf(a3, c2, acc[3][2]); acc[3][3] = fmaf(a3, b3, acc[3][3]);
        }
        __syncthreads();
    }

#pragma unroll
    for (int ii = 0; ii < 4; ii++)
#pragma unroll
        for (int jj = 0; jj < 4; jj++) {
            const int gn = bn + tx * 4 + jj;
            const float bias = (gn < 256) ? b1[gn] : 0.0f;
            AB[(bm + ty * 4 + ii) * 512 + gn] = acc[ii][jj] + bias;
        }
}

// ---------------------------------------------------------------------------
// Kernel 2b: split W2 into fp16 hi/lo row-major [k][n] images
// ---------------------------------------------------------------------------
__global__ void __launch_bounds__(256)
w2split_kernel(const float* __restrict__ W2) {
    const int id = blockIdx.x * 256 + threadIdx.x;
    const float4 v = ((const float4*)W2)[id];

    const __half h0 = __float2half_rn(v.x);
    const __half h1 = __float2half_rn(v.y);
    const __half h2 = __float2half_rn(v.z);
    const __half h3 = __float2half_rn(v.w);

    g_W2hi32[id * 2 + 0] = ((uint32_t)__half_as_ushort(h1) << 16) |
                           (uint32_t)__half_as_ushort(h0);
    g_W2hi32[id * 2 + 1] = ((uint32_t)__half_as_ushort(h3) << 16) |
                           (uint32_t)__half_as_ushort(h2);
    g_W2lo32[id * 2 + 0] = pack_h2(v.x - __half2float(h0),
                                   v.y - __half2float(h1));
    g_W2lo32[id * 2 + 1] = pack_h2(v.z - __half2float(h2),
                                   v.w - __half2float(h3));
}

// ---------------------------------------------------------------------------
// Kernel 3: mma.sync fp16 edge GEMM, 2-term split (A_fp16 * (Bhi + Blo)).
// Block = 8 nodes (M=128), N=256, K=256 in 8 chunks of k=32, double-buffered
// cp.async W2 stream. A held in smem as fp16 only (no lo image).
// ---------------------------------------------------------------------------
#define SA_HI   0
#define SB_BASE 65536
#define SB_BUF  32768          // per buffer: hi 16KB + lo 16KB
#define SM_TOTAL 131072

__global__ void __launch_bounds__(EM_THREADS, 1)
edge_mma_kernel(const float* __restrict__ AB,
                const int* __restrict__ idx,
                const float* __restrict__ b2,
                float* __restrict__ out) {
    extern __shared__ char smem[];
    const uint32_t sbase = smem_u32(smem);
    __shared__ int idxs[128];

    const int t    = threadIdx.x;
    const int lane = t & 31;
    const int wid  = t >> 5;
    const int wm   = wid & 3;
    const int wn   = wid >> 2;
    const int i0   = blockIdx.x * NODES_PB;

    if (t < 128) idxs[t] = idx[i0 * KNN + t];
    __syncthreads();

    // ---- prologue: async-load W2 chunk 0 (overlaps gather phase) ----
    {
#pragma unroll
        for (int ii = 0; ii < 2; ii++) {
            const int e = t + ii * EM_THREADS;       // 0..1023
            const int row = e >> 5, c = e & 31;
            const uint32_t dst = sbase + SB_BASE + row * 512 + ((c ^ (row & 7)) * 16);
            const int src = row * 32 + c;
            CP_ASYNC16(dst, (const uint4*)g_W2hi32 + src);
            CP_ASYNC16(dst + 16384, (const uint4*)g_W2lo32 + src);
        }
        CP_ASYNC_COMMIT();
    }

    // ---- Phase A: gather + relu + fp16 convert -> smem (rows = edges) ----
    {
        const int r = t >> 2;
        const int q = t & 3;
        const int j = idxs[r];
        const float4* arow = (const float4*)(AB + (size_t)(i0 + (r >> 4)) * 512) + q * 16;
        const float4* brow = (const float4*)(AB + (size_t)j * 512 + 256) + q * 16;
        const int sw_r = r & 7;
        char* smem_c = smem;
#pragma unroll
        for (int w = 0; w < 8; w++) {
            const float4 a0 = arow[w * 2 + 0];
            const float4 a1 = arow[w * 2 + 1];
            const float4 e0 = brow[w * 2 + 0];
            const float4 e1 = brow[w * 2 + 1];
            uint4 H;
            H.x = pack_h2(fmaxf(a0.x + e0.x, 0.0f), fmaxf(a0.y + e0.y, 0.0f));
            H.y = pack_h2(fmaxf(a0.z + e0.z, 0.0f), fmaxf(a0.w + e0.w, 0.0f));
            H.z = pack_h2(fmaxf(a1.x + e1.x, 0.0f), fmaxf(a1.y + e1.y, 0.0f));
            H.w = pack_h2(fmaxf(a1.z + e1.z, 0.0f), fmaxf(a1.w + e1.w, 0.0f));
            const int c = (q * 8 + w) ^ sw_r;
            *(uint4*)(smem_c + SA_HI + r * 512 + c * 16) = H;
        }
    }
    __syncthreads();

    // ---- Main loop: 8 chunks of k=32, double-buffered ----
    float D[2][8][4];
#pragma unroll
    for (int mt = 0; mt < 2; mt++)
#pragma unroll
        for (int f = 0; f < 8; f++)
#pragma unroll
            for (int c = 0; c < 4; c++) D[mt][f][c] = 0.0f;

    const int a_row  = wm * 32 + (lane & 15);
    const int a_swz  = a_row & 7;
    const uint32_t a_base = sbase + SA_HI + a_row * 512;
    const int b_krow  = lane & 15;
    const int b_cbase = wn * 8 + (lane >> 4);

    for (int kc = 0; kc < 8; kc++) {
        if (kc < 7) {
            const int b = (kc + 1) & 1;
#pragma unroll
            for (int ii = 0; ii < 2; ii++) {
                const int e = t + ii * EM_THREADS;
                const int row = e >> 5, c = e & 31;
                const uint32_t dst = sbase + SB_BASE + b * SB_BUF +
                                     row * 512 + ((c ^ (row & 7)) * 16);
                const int src = ((kc + 1) * 32 + row) * 32 + c;
                CP_ASYNC16(dst, (const uint4*)g_W2hi32 + src);
                CP_ASYNC16(dst + 16384, (const uint4*)g_W2lo32 + src);
            }
            CP_ASYNC_COMMIT();
            CP_ASYNC_WAIT(1);
        } else {
            CP_ASYNC_WAIT(0);
        }
        __syncthreads();

        const uint32_t sb = sbase + SB_BASE + (kc & 1) * SB_BUF;
#pragma unroll
        for (int kt = 0; kt < 2; kt++) {
            const int kg = kc * 2 + kt;
            uint32_t ah[2][4];
#pragma unroll
            for (int mt = 0; mt < 2; mt++) {
                const uint32_t roff = mt * 16 * 512;
                const uint32_t c = (uint32_t)((kg * 2 + (lane >> 4)) ^ a_swz) * 16;
                ldsm_x4(ah[mt][0], ah[mt][1], ah[mt][2], ah[mt][3], a_base + roff + c);
            }
#pragma unroll
            for (int g = 0; g < 4; g++) {
                const int krow = kt * 16 + b_krow;
                const uint32_t c = (uint32_t)((b_cbase + g * 2) ^ (krow & 7)) * 16;
                const uint32_t baddr = sb + krow * 512 + c;
                uint32_t bh0, bh1, bh2, bh3, bl0, bl1, bl2, bl3;
                ldsm_x4_t(bh0, bh1, bh2, bh3, baddr);
                ldsm_x4_t(bl0, bl1, bl2, bl3, baddr + 16384);
#pragma unroll
                for (int mt = 0; mt < 2; mt++) {
                    float* d0 = D[mt][g * 2 + 0];
                    float* d1 = D[mt][g * 2 + 1];
                    mma_f16(d0[0], d0[1], d0[2], d0[3],
                            ah[mt][0], ah[mt][1], ah[mt][2], ah[mt][3], bh0, bh1);
                    mma_f16(d0[0], d0[1], d0[2], d0[3],
                            ah[mt][0], ah[mt][1], ah[mt][2], ah[mt][3], bl0, bl1);
                    mma_f16(d1[0], d1[1], d1[2], d1[3],
                            ah[mt][0], ah[mt][1], ah[mt][2], ah[mt][3], bh2, bh3);
                    mma_f16(d1[0], d1[1], d1[2], d1[3],
                            ah[mt][0], ah[mt][1], ah[mt][2], ah[mt][3], bl2, bl3);
                }
            }
        }
        __syncthreads();
    }

    // ---- Epilogue: max over each node's 16 rows (warp-local) + b2 ----
#pragma unroll
    for (int mt = 0; mt < 2; mt++) {
        const int node = i0 + wm * 2 + mt;
#pragma unroll
        for (int f = 0; f < 8; f++) {
            float m0 = fmaxf(D[mt][f][0], D[mt][f][2]);
            float m1 = fmaxf(D[mt][f][1], D[mt][f][3]);
            m0 = fmaxf(m0, __shfl_xor_sync(0xffffffffu, m0, 4));
            m1 = fmaxf(m1, __shfl_xor_sync(0xffffffffu, m1, 4));
            m0 = fmaxf(m0, __shfl_xor_sync(0xffffffffu, m0, 8));
            m1 = fmaxf(m1, __shfl_xor_sync(0xffffffffu, m1, 8));
            m0 = fmaxf(m0, __shfl_xor_sync(0xffffffffu, m0, 16));
            m1 = fmaxf(m1, __shfl_xor_sync(0xffffffffu, m1, 16));
            if ((lane >> 2) == 0) {
                const int col = wn * 64 + f * 8 + 2 * (lane & 3);
                float2 o;
                o.x = m0 + b2[col];
                o.y = m1 + b2[col + 1];
                *(float2*)(out + (size_t)node * DDIM + col) = o;
            }
        }
    }
}

// ---------------------------------------------------------------------------
// Launch: fork gemm1/w2split onto a side stream so they overlap the kNN
// chain in the captured graph (independent until edge_mma joins both).
// ---------------------------------------------------------------------------
extern "C" void kernel_launch(void* const* d_in, const int* in_sizes, int n_in,
                              void* d_out, int out_size) {
    const float* x   = (const float*)d_in[0];
    const float* pos = (const float*)d_in[1];
    const float* W1  = (const float*)d_in[2];
    const float* b1  = (const float*)d_in[3];
    const float* W2  = (const float*)d_in[4];
    const float* b2  = (const float*)d_in[5];
    float* out = (float*)d_out;
    (void)in_sizes; (void)n_in; (void)out_size;

    int*   idx_ptr = nullptr;
    float* ab_ptr  = nullptr;
    cudaGetSymbolAddress((void**)&idx_ptr, g_idx);
    cudaGetSymbolAddress((void**)&ab_ptr, g_AB);

    static bool init_done = false;
    static cudaStream_t s2 = nullptr;
    static cudaEvent_t ev_fork = nullptr, ev_join = nullptr;
    if (!init_done) {
        cudaFuncSetAttribute(edge_mma_kernel,
                             cudaFuncAttributeMaxDynamicSharedMemorySize, SM_TOTAL);
        cudaStreamCreateWithFlags(&s2, cudaStreamNonBlocking);
        cudaEventCreateWithFlags(&ev_fork, cudaEventDisableTiming);
        cudaEventCreateWithFlags(&ev_join, cudaEventDisableTiming);
        init_done = true;
    }

    // fork: side stream runs gemm1 + w2split concurrently with kNN chain
    cudaEventRecord(ev_fork, 0);
    cudaStreamWaitEvent(s2, ev_fork, 0);

    // main stream: grid kNN build + warp-cooperative query
    zero_hist_kernel<<<NCELL / 1024, 1024>>>();
    cell_assign_kernel<<<NPTS / 256, 256>>>(pos);
    scan_kernel<<<1, 1024>>>();
    scatter_kernel<<<NPTS / 256, 256>>>(pos);
    knn_query_kernel<<<NPTS * 32 / 256, 256>>>(idx_ptr);

    // side stream: MLP prep
    gemm1_kernel<<<dim3(512 / 64, NPTS / 64), 256, 0, s2>>>(x, W1, b1, ab_ptr);
    w2split_kernel<<<64, 256, 0, s2>>>(W2);
    cudaEventRecord(ev_join, s2);

    // join, then fused edge GEMM
    cudaStreamWaitEvent(0, ev_join, 0);
    edge_mma_kernel<<<NPTS / NODES_PB, EM_THREADS, SM_TOTAL>>>(ab_ptr, idx_ptr, b2, out);
}

// round 14
// speedup vs baseline: 5.3487x; 1.2085x over previous
#include <cuda_runtime.h>
#include <cuda_bf16.h>
#include <cuda_fp16.h>
#include <cstdint>

// ---------------------------------------------------------------------------
// Problem constants
// ---------------------------------------------------------------------------
#define NPTS   8192
#define CIN    128
#define DDIM   256
#define KNN    16

#define NODES_PB 8             // nodes per edge-MMA block (M = 8*16 = 128)
#define EM_THREADS 512         // 16 warps: 4 (m) x 4 (n)

// Grid kNN parameters: fat cells so candidate runs are long/contiguous
#define G    16
#define OXC  (-4.0f)
#define CSZ  0.5f
#define NCELL (G * G * G)      // 4096

// Scratch (device globals — no allocation allowed)
__device__ float g_AB[NPTS * 512];
__device__ int   g_idx[NPTS * KNN];
__device__ uint32_t g_W2h32[32768];         // fp16 W2 image, row-major [k][n]
// grid structures
__device__ int    g_hist[NCELL];
__device__ int    g_cstart[NCELL];
__device__ int    g_cptr[NCELL];
__device__ int    g_pcell[NPTS];
__device__ float4 g_spos[NPTS];             // cell-sorted (x,y,z,sq)
__device__ int    g_sid[NPTS];              // sorted -> original index

// ---------------------------------------------------------------------------
// PTX helpers
// ---------------------------------------------------------------------------
__device__ __forceinline__ uint32_t smem_u32(const void* p) {
    uint32_t a;
    asm("{ .reg .u64 t; cvta.to.shared.u64 t, %1; cvt.u32.u64 %0, t; }"
        : "=r"(a) : "l"(p));
    return a;
}
__device__ __forceinline__ void ldsm_x4(uint32_t& r0, uint32_t& r1,
                                        uint32_t& r2, uint32_t& r3, uint32_t addr) {
    asm volatile("ldmatrix.sync.aligned.m8n8.x4.shared.b16 {%0,%1,%2,%3}, [%4];"
                 : "=r"(r0), "=r"(r1), "=r"(r2), "=r"(r3) : "r"(addr));
}
__device__ __forceinline__ void ldsm_x4_t(uint32_t& r0, uint32_t& r1,
                                          uint32_t& r2, uint32_t& r3, uint32_t addr) {
    asm volatile("ldmatrix.sync.aligned.m8n8.x4.trans.shared.b16 {%0,%1,%2,%3}, [%4];"
                 : "=r"(r0), "=r"(r1), "=r"(r2), "=r"(r3) : "r"(addr));
}
__device__ __forceinline__ void mma_f16(float& d0, float& d1, float& d2, float& d3,
                                        uint32_t a0, uint32_t a1, uint32_t a2, uint32_t a3,
                                        uint32_t b0, uint32_t b1) {
    asm volatile("mma.sync.aligned.m16n8k16.row.col.f32.f16.f16.f32 "
                 "{%0,%1,%2,%3}, {%4,%5,%6,%7}, {%8,%9}, {%0,%1,%2,%3};"
                 : "+f"(d0), "+f"(d1), "+f"(d2), "+f"(d3)
                 : "r"(a0), "r"(a1), "r"(a2), "r"(a3), "r"(b0), "r"(b1));
}
__device__ __forceinline__ uint32_t pack_h2(float v0, float v1) {
    return ((uint32_t)__half_as_ushort(__float2half_rn(v1)) << 16) |
           (uint32_t)__half_as_ushort(__float2half_rn(v0));
}
#define CP_ASYNC16(dst, src) \
    asm volatile("cp.async.cg.shared.global [%0], [%1], 16;" \
                 :: "r"(dst), "l"(src) : "memory")
#define CP_ASYNC_COMMIT() asm volatile("cp.async.commit_group;" ::: "memory")
#define CP_ASYNC_WAIT(n)  asm volatile("cp.async.wait_group %0;" :: "n"(n) : "memory")

// ---------------------------------------------------------------------------
// Grid build kernels
// ---------------------------------------------------------------------------
__global__ void __launch_bounds__(1024)
zero_hist_kernel() {
    g_hist[blockIdx.x * 1024 + threadIdx.x] = 0;
}

__global__ void __launch_bounds__(256)
cell_assign_kernel(const float* __restrict__ pos) {
    const int i = blockIdx.x * 256 + threadIdx.x;
    const float x = pos[i * 3 + 0];
    const float y = pos[i * 3 + 1];
    const float z = pos[i * 3 + 2];
    const int cx = min(max(__float2int_rd((x - OXC) * (1.0f / CSZ)), 0), G - 1);
    const int cy = min(max(__float2int_rd((y - OXC) * (1.0f / CSZ)), 0), G - 1);
    const int cz = min(max(__float2int_rd((z - OXC) * (1.0f / CSZ)), 0), G - 1);
    const int c = (cz * G + cy) * G + cx;
    g_pcell[i] = c;
    atomicAdd(&g_hist[c], 1);
}

__global__ void __launch_bounds__(1024)
scan_kernel() {
    __shared__ int sd[1024];
    const int t = threadIdx.x;
    int sum = 0;
#pragma unroll
    for (int k = 0; k < NCELL / 1024; k++) sum += g_hist[t * (NCELL / 1024) + k];
    sd[t] = sum;
    __syncthreads();
    for (int off = 1; off < 1024; off <<= 1) {
        const int v = (t >= off) ? sd[t - off] : 0;
        __syncthreads();
        sd[t] += v;
        __syncthreads();
    }
    int run = sd[t] - sum;
#pragma unroll
    for (int k = 0; k < NCELL / 1024; k++) {
        const int c = t * (NCELL / 1024) + k;
        g_cstart[c] = run;
        g_cptr[c]   = run;
        run += g_hist[c];
    }
}

__global__ void __launch_bounds__(256)
scatter_kernel(const float* __restrict__ pos) {
    const int i = blockIdx.x * 256 + threadIdx.x;
    const int c = g_pcell[i];
    const int dst = atomicAdd(&g_cptr[c], 1);
    const float x = pos[i * 3 + 0];
    const float y = pos[i * 3 + 1];
    const float z = pos[i * 3 + 2];
    const float sq = fmaf(z, z, fmaf(y, y, x * x));
    g_spos[dst] = make_float4(x, y, z, sq);
    g_sid[dst] = i;
}

// ---------------------------------------------------------------------------
// Warp-cooperative exact grid kNN query. One warp per query.
// Lane-distributed sorted top-16 (lanes 0..15), ballot+ffs+shfl_up insertion.
// ---------------------------------------------------------------------------
#define PROCESS_RUN(c0, c1) do {                                               \
    const int _st = g_cstart[(c0)];                                            \
    const int _en = g_cstart[(c1)] + g_hist[(c1)];                             \
    for (int _jb = _st; _jb < _en; _jb += 32) {                                \
        const int _j = _jb + lane;                                             \
        float _dist = 1e30f;                                                   \
        if (_j < _en) {                                                        \
            const float4 _p = g_spos[_j];                                      \
            const float _dot = fmaf(me.z, _p.z, fmaf(me.y, _p.y, me.x * _p.x));\
            _dist = fmaf(-2.0f, _dot, me.w + _p.w);                            \
            if (_j == q) _dist = 1e30f;                                        \
        }                                                                      \
        unsigned _m = __ballot_sync(0xffffffffu, _dist < kth);                 \
        while (_m) {                                                           \
            const int _src = __ffs(_m) - 1; _m &= _m - 1;                      \
            const float _d = __shfl_sync(0xffffffffu, _dist, _src);            \
            if (_d < kth) {                                                    \
                const int _id = _jb + _src;                                    \
                const unsigned _mk =                                           \
                    __ballot_sync(0xffffffffu, bd > _d) & 0xFFFFu;             \
                const int _pos = __ffs(_mk) - 1;   /* nonzero: bd15=kth>_d */  \
                const float _bdu = __shfl_up_sync(0xffffffffu, bd, 1);         \
                const int   _bju = __shfl_up_sync(0xffffffffu, bj, 1);         \
                if (lane >= _pos && lane < KNN) { bd = _bdu; bj = _bju; }      \
                if (lane == _pos) { bd = _d; bj = _id; }                       \
                kth = __shfl_sync(0xffffffffu, bd, KNN - 1);                   \
            }                                                                  \
        }                                                                      \
    }                                                                          \
} while (0)

__global__ void __launch_bounds__(256)
knn_query_kernel(int* __restrict__ idxout) {
    const int q    = (blockIdx.x * 256 + threadIdx.x) >> 5;   // one warp per query
    const int lane = threadIdx.x & 31;

    const float4 me = g_spos[q];
    const int cx = min(max(__float2int_rd((me.x - OXC) * (1.0f / CSZ)), 0), G - 1);
    const int cy = min(max(__float2int_rd((me.y - OXC) * (1.0f / CSZ)), 0), G - 1);
    const int cz = min(max(__float2int_rd((me.z - OXC) * (1.0f / CSZ)), 0), G - 1);

    float bd  = 1e30f;   // lane-distributed sorted list (lanes 0..15)
    int   bj  = -1;
    float kth = 1e30f;   // current 16th-best, warp-uniform

    for (int R = 0; R < G; R++) {
        const int zlo = max(cz - R, 0), zhi = min(cz + R, G - 1);
        const int ylo = max(cy - R, 0), yhi = min(cy + R, G - 1);
        const int xlo = max(cx - R, 0), xhi = min(cx + R, G - 1);
        for (int z = zlo; z <= zhi; z++) {
            const int adz = (z > cz) ? (z - cz) : (cz - z);
            for (int y = ylo; y <= yhi; y++) {
                const int ady = (y > cy) ? (y - cy) : (cy - y);
                const int rowc = (z * G + y) * G;
                if (adz == R || ady == R) {
                    PROCESS_RUN(rowc + xlo, rowc + xhi);   // whole row, contiguous
                } else {
                    if (cx - R >= 0) PROCESS_RUN(rowc + cx - R, rowc + cx - R);
                    if (cx + R < G)  PROCESS_RUN(rowc + cx + R, rowc + cx + R);
                }
            }
        }
        // exact stop bound: distance to faces of the processed region
        const float dxl = (cx - R > 0)     ? (me.x - (OXC + (cx - R) * CSZ))     : 1e30f;
        const float dxr = (cx + R + 1 < G) ? ((OXC + (cx + R + 1) * CSZ) - me.x) : 1e30f;
        const float dyl = (cy - R > 0)     ? (me.y - (OXC + (cy - R) * CSZ))     : 1e30f;
        const float dyr = (cy + R + 1 < G) ? ((OXC + (cy + R + 1) * CSZ) - me.y) : 1e30f;
        const float dzl = (cz - R > 0)     ? (me.z - (OXC + (cz - R) * CSZ))     : 1e30f;
        const float dzr = (cz + R + 1 < G) ? ((OXC + (cz + R + 1) * CSZ) - me.z) : 1e30f;
        const float dmin = fminf(fminf(fminf(dxl, dxr), fminf(dyl, dyr)),
                                 fminf(dzl, dzr));
        if (dmin * dmin >= kth) break;
    }

    if (lane < KNN) {
        const int orig = g_sid[q];
        idxout[orig * KNN + lane] = g_sid[bj];
    }
}

// ---------------------------------------------------------------------------
// Kernel 2: AB = X @ [W1top - W1bot | W1bot], b1 folded into A columns
// ---------------------------------------------------------------------------
__global__ void __launch_bounds__(256)
gemm1_kernel(const float* __restrict__ X,
             const float* __restrict__ W1,
             const float* __restrict__ b1,
             float* __restrict__ AB) {
    __shared__ float As[16][65];
    __shared__ float Bs[16][64];

    const int bm = blockIdx.y * 64;
    const int bn = blockIdx.x * 64;
    const int t  = threadIdx.x;
    const int tx = t & 15;
    const int ty = t >> 4;

    float acc[4][4];
#pragma unroll
    for (int a = 0; a < 4; a++)
#pragma unroll
        for (int b = 0; b < 4; b++) acc[a][b] = 0.0f;

    for (int k0 = 0; k0 < CIN; k0 += 16) {
#pragma unroll
        for (int r = 0; r < 4; r++) {
            const int e = t + r * 256;
            const int m = e >> 4, k = e & 15;
            As[k][m] = X[(bm + m) * CIN + k0 + k];
        }
#pragma unroll
        for (int r = 0; r < 4; r++) {
            const int e = t + r * 256;
            const int k = e >> 6, n = e & 63;
            const int gk = k0 + k, gn = bn + n;
            float v;
            if (gn < 256)
                v = W1[gk * 256 + gn] - W1[(gk + 128) * 256 + gn];
            else
                v = W1[(gk + 128) * 256 + (gn - 256)];
            Bs[k][n] = v;
        }
        __syncthreads();

#pragma unroll
        for (int k = 0; k < 16; k++) {
            float a0 = As[k][ty * 4 + 0];
            float a1 = As[k][ty * 4 + 1];
            float a2 = As[k][ty * 4 + 2];
            float a3 = As[k][ty * 4 + 3];
            float b0 = Bs[k][tx * 4 + 0];
            float c1 = Bs[k][tx * 4 + 1];
            float c2 = Bs[k][tx * 4 + 2];
            float b3 = Bs[k][tx * 4 + 3];
            acc[0][0] = fmaf(a0, b0, acc[0][0]); acc[0][1] = fmaf(a0, c1, acc[0][1]);
            acc[0][2] = fmaf(a0, c2, acc[0][2]); acc[0][3] = fmaf(a0, b3, acc[0][3]);
            acc[1][0] = fmaf(a1, b0, acc[1][0]); acc[1][1] = fmaf(a1, c1, acc[1][1]);
            acc[1][2] = fmaf(a1, c2, acc[1][2]); acc[1][3] = fmaf(a1, b3, acc[1][3]);
            acc[2][0] = fmaf(a2, b0, acc[2][0]); acc[2][1] = fmaf(a2, c1, acc[2][1]);
            acc[2][2] = fmaf(a2, c2, acc[2][2]); acc[2][3] = fmaf(a2, b3, acc[2][3]);
            acc[3][0] = fmaf(a3, b0, acc[3][0]); acc[3][1] = fmaf(a3, c1, acc[3][1]);
            acc[3][2] = fmaf(a3, c2, acc[3][2]); acc[3][3] = fmaf(a3, b3, acc[3][3]);
        }
        __syncthreads();
    }

#pragma unroll
    for (int ii = 0; ii < 4; ii++)
#pragma unroll
        for (int jj = 0; jj < 4; jj++) {
            const int gn = bn + tx * 4 + jj;
            const float bias = (gn < 256) ? b1[gn] : 0.0f;
            AB[(bm + ty * 4 + ii) * 512 + gn] = acc[ii][jj] + bias;
        }
}

// ---------------------------------------------------------------------------
// Kernel 2b: convert W2 into a single fp16 row-major [k][n] image
// ---------------------------------------------------------------------------
__global__ void __launch_bounds__(256)
w2split_kernel(const float* __restrict__ W2) {
    const int id = blockIdx.x * 256 + threadIdx.x;
    const float4 v = ((const float4*)W2)[id];
    g_W2h32[id * 2 + 0] = pack_h2(v.x, v.y);
    g_W2h32[id * 2 + 1] = pack_h2(v.z, v.w);
}

// ---------------------------------------------------------------------------
// Kernel 3: mma.sync fp16 edge GEMM, single-term (A_fp16 * B_fp16).
// Block = 8 nodes (M=128), N=256, K=256 in 8 chunks of k=32, double-buffered
// cp.async W2 stream. smem: A 64KB + 2 x 16KB B buffers = 96KB.
// ---------------------------------------------------------------------------
#define SA_HI   0
#define SB_BASE 65536
#define SB_BUF  16384          // per buffer: 32 rows x 256 cols fp16
#define SM_TOTAL 98304

__global__ void __launch_bounds__(EM_THREADS, 1)
edge_mma_kernel(const float* __restrict__ AB,
                const int* __restrict__ idx,
                const float* __restrict__ b2,
                float* __restrict__ out) {
    extern __shared__ char smem[];
    const uint32_t sbase = smem_u32(smem);
    __shared__ int idxs[128];

    const int t    = threadIdx.x;
    const int lane = t & 31;
    const int wid  = t >> 5;
    const int wm   = wid & 3;
    const int wn   = wid >> 2;
    const int i0   = blockIdx.x * NODES_PB;

    if (t < 128) idxs[t] = idx[i0 * KNN + t];
    __syncthreads();

    // ---- prologue: async-load W2 chunk 0 (overlaps gather phase) ----
    {
#pragma unroll
        for (int ii = 0; ii < 2; ii++) {
            const int e = t + ii * EM_THREADS;       // 0..1023
            const int row = e >> 5, c = e & 31;
            const uint32_t dst = sbase + SB_BASE + row * 512 + ((c ^ (row & 7)) * 16);
            const int src = row * 32 + c;
            CP_ASYNC16(dst, (const uint4*)g_W2h32 + src);
        }
        CP_ASYNC_COMMIT();
    }

    // ---- Phase A: gather + relu + fp16 convert -> smem (rows = edges) ----
    {
        const int r = t >> 2;
        const int q = t & 3;
        const int j = idxs[r];
        const float4* arow = (const float4*)(AB + (size_t)(i0 + (r >> 4)) * 512) + q * 16;
        const float4* brow = (const float4*)(AB + (size_t)j * 512 + 256) + q * 16;
        const int sw_r = r & 7;
        char* smem_c = smem;
#pragma unroll
        for (int w = 0; w < 8; w++) {
            const float4 a0 = arow[w * 2 + 0];
            const float4 a1 = arow[w * 2 + 1];
            const float4 e0 = brow[w * 2 + 0];
            const float4 e1 = brow[w * 2 + 1];
            uint4 H;
            H.x = pack_h2(fmaxf(a0.x + e0.x, 0.0f), fmaxf(a0.y + e0.y, 0.0f));
            H.y = pack_h2(fmaxf(a0.z + e0.z, 0.0f), fmaxf(a0.w + e0.w, 0.0f));
            H.z = pack_h2(fmaxf(a1.x + e1.x, 0.0f), fmaxf(a1.y + e1.y, 0.0f));
            H.w = pack_h2(fmaxf(a1.z + e1.z, 0.0f), fmaxf(a1.w + e1.w, 0.0f));
            const int c = (q * 8 + w) ^ sw_r;
            *(uint4*)(smem_c + SA_HI + r * 512 + c * 16) = H;
        }
    }
    __syncthreads();

    // ---- Main loop: 8 chunks of k=32, double-buffered ----
    float D[2][8][4];
#pragma unroll
    for (int mt = 0; mt < 2; mt++)
#pragma unroll
        for (int f = 0; f < 8; f++)
#pragma unroll
            for (int c = 0; c < 4; c++) D[mt][f][c] = 0.0f;

    const int a_row  = wm * 32 + (lane & 15);
    const int a_swz  = a_row & 7;
    const uint32_t a_base = sbase + SA_HI + a_row * 512;
    const int b_krow  = lane & 15;
    const int b_cbase = wn * 8 + (lane >> 4);

    for (int kc = 0; kc < 8; kc++) {
        if (kc < 7) {
            const int b = (kc + 1) & 1;
#pragma unroll
            for (int ii = 0; ii < 2; ii++) {
                const int e = t + ii * EM_THREADS;
                const int row = e >> 5, c = e & 31;
                const uint32_t dst = sbase + SB_BASE + b * SB_BUF +
                                     row * 512 + ((c ^ (row & 7)) * 16);
                const int src = ((kc + 1) * 32 + row) * 32 + c;
                CP_ASYNC16(dst, (const uint4*)g_W2h32 + src);
            }
            CP_ASYNC_COMMIT();
            CP_ASYNC_WAIT(1);
        } else {
            CP_ASYNC_WAIT(0);
        }
        __syncthreads();

        const uint32_t sb = sbase + SB_BASE + (kc & 1) * SB_BUF;
#pragma unroll
        for (int kt = 0; kt < 2; kt++) {
            const int kg = kc * 2 + kt;
            uint32_t ah[2][4];
#pragma unroll
            for (int mt = 0; mt < 2; mt++) {
                const uint32_t roff = mt * 16 * 512;
                const uint32_t c = (uint32_t)((kg * 2 + (lane >> 4)) ^ a_swz) * 16;
                ldsm_x4(ah[mt][0], ah[mt][1], ah[mt][2], ah[mt][3], a_base + roff + c);
            }
#pragma unroll
            for (int g = 0; g < 4; g++) {
                const int krow = kt * 16 + b_krow;
                const uint32_t c = (uint32_t)((b_cbase + g * 2) ^ (krow & 7)) * 16;
                const uint32_t baddr = sb + krow * 512 + c;
                uint32_t bh0, bh1, bh2, bh3;
                ldsm_x4_t(bh0, bh1, bh2, bh3, baddr);
#pragma unroll
                for (int mt = 0; mt < 2; mt++) {
                    float* d0 = D[mt][g * 2 + 0];
                    float* d1 = D[mt][g * 2 + 1];
                    mma_f16(d0[0], d0[1], d0[2], d0[3],
                            ah[mt][0], ah[mt][1], ah[mt][2], ah[mt][3], bh0, bh1);
                    mma_f16(d1[0], d1[1], d1[2], d1[3],
                            ah[mt][0], ah[mt][1], ah[mt][2], ah[mt][3], bh2, bh3);
                }
            }
        }
        __syncthreads();
    }

    // ---- Epilogue: max over each node's 16 rows (warp-local) + b2 ----
#pragma unroll
    for (int mt = 0; mt < 2; mt++) {
        const int node = i0 + wm * 2 + mt;
#pragma unroll
        for (int f = 0; f < 8; f++) {
            float m0 = fmaxf(D[mt][f][0], D[mt][f][2]);
            float m1 = fmaxf(D[mt][f][1], D[mt][f][3]);
            m0 = fmaxf(m0, __shfl_xor_sync(0xffffffffu, m0, 4));
            m1 = fmaxf(m1, __shfl_xor_sync(0xffffffffu, m1, 4));
            m0 = fmaxf(m0, __shfl_xor_sync(0xffffffffu, m0, 8));
            m1 = fmaxf(m1, __shfl_xor_sync(0xffffffffu, m1, 8));
            m0 = fmaxf(m0, __shfl_xor_sync(0xffffffffu, m0, 16));
            m1 = fmaxf(m1, __shfl_xor_sync(0xffffffffu, m1, 16));
            if ((lane >> 2) == 0) {
                const int col = wn * 64 + f * 8 + 2 * (lane & 3);
                float2 o;
                o.x = m0 + b2[col];
                o.y = m1 + b2[col + 1];
                *(float2*)(out + (size_t)node * DDIM + col) = o;
            }
        }
    }
}

// ---------------------------------------------------------------------------
// Launch: fork gemm1/w2split onto a side stream so they overlap the kNN
// chain in the captured graph (independent until edge_mma joins both).
// ---------------------------------------------------------------------------
extern "C" void kernel_launch(void* const* d_in, const int* in_sizes, int n_in,
                              void* d_out, int out_size) {
    const float* x   = (const float*)d_in[0];
    const float* pos = (const float*)d_in[1];
    const float* W1  = (const float*)d_in[2];
    const float* b1  = (const float*)d_in[3];
    const float* W2  = (const float*)d_in[4];
    const float* b2  = (const float*)d_in[5];
    float* out = (float*)d_out;
    (void)in_sizes; (void)n_in; (void)out_size;

    int*   idx_ptr = nullptr;
    float* ab_ptr  = nullptr;
    cudaGetSymbolAddress((void**)&idx_ptr, g_idx);
    cudaGetSymbolAddress((void**)&ab_ptr, g_AB);

    static bool init_done = false;
    static cudaStream_t s2 = nullptr;
    static cudaEvent_t ev_fork = nullptr, ev_join = nullptr;
    if (!init_done) {
        cudaGetLastError();  // clear any stale sticky error before first use
        cudaFuncSetAttribute(edge_mma_kernel,
                             cudaFuncAttributeMaxDynamicSharedMemorySize, SM_TOTAL);
        cudaStreamCreateWithFlags(&s2, cudaStreamNonBlocking);
        cudaEventCreateWithFlags(&ev_fork, cudaEventDisableTiming);
        cudaEventCreateWithFlags(&ev_join, cudaEventDisableTiming);
        init_done = true;
    }

    // fork: side stream runs gemm1 + w2split concurrently with kNN chain
    cudaEventRecord(ev_fork, 0);
    cudaStreamWaitEvent(s2, ev_fork, 0);

    // main stream: grid kNN build + warp-cooperative query
    zero_hist_kernel<<<NCELL / 1024, 1024>>>();
    cell_assign_kernel<<<NPTS / 256, 256>>>(pos);
    scan_kernel<<<1, 1024>>>();
    scatter_kernel<<<NPTS / 256, 256>>>(pos);
    knn_query_kernel<<<NPTS * 32 / 256, 256>>>(idx_ptr);

    // side stream: MLP prep
    gemm1_kernel<<<dim3(512 / 64, NPTS / 64), 256, 0, s2>>>(x, W1, b1, ab_ptr);
    w2split_kernel<<<64, 256, 0, s2>>>(W2);
    cudaEventRecord(ev_join, s2);

    // join, then fused edge GEMM
    cudaStreamWaitEvent(0, ev_join, 0);
    edge_mma_kernel<<<NPTS / NODES_PB, EM_THREADS, SM_TOTAL>>>(ab_ptr, idx_ptr, b2, out);
}

// round 15
// speedup vs baseline: 5.5045x; 1.0291x over previous
#include <cuda_runtime.h>
#include <cuda_bf16.h>
#include <cuda_fp16.h>
#include <cstdint>

// ---------------------------------------------------------------------------
// Problem constants
// ---------------------------------------------------------------------------
#define NPTS   8192
#define CIN    128
#define DDIM   256
#define KNN    16

#define NODES_PB 4             // nodes per edge-MMA block (M = 4*16 = 64)
#define EM_THREADS 256         // 8 warps: 2 (m) x 4 (n)

// Grid kNN parameters: fat cells so candidate runs are long/contiguous
#define G    16
#define OXC  (-4.0f)
#define CSZ  0.5f
#define NCELL (G * G * G)      // 4096

// Scratch (device globals — no allocation allowed)
__device__ float g_AB[NPTS * 512];
__device__ int   g_idx[NPTS * KNN];
__device__ uint32_t g_W2h32[32768];         // fp16 W2 image, row-major [k][n]
// grid structures
__device__ int    g_hist[NCELL];
__device__ int    g_cstart[NCELL];
__device__ int    g_cptr[NCELL];
__device__ int    g_pcell[NPTS];
__device__ float4 g_spos[NPTS];             // cell-sorted (x,y,z,sq)
__device__ int    g_sid[NPTS];              // sorted -> original index

// ---------------------------------------------------------------------------
// PTX helpers
// ---------------------------------------------------------------------------
__device__ __forceinline__ uint32_t smem_u32(const void* p) {
    uint32_t a;
    asm("{ .reg .u64 t; cvta.to.shared.u64 t, %1; cvt.u32.u64 %0, t; }"
        : "=r"(a) : "l"(p));
    return a;
}
__device__ __forceinline__ void ldsm_x4(uint32_t& r0, uint32_t& r1,
                                        uint32_t& r2, uint32_t& r3, uint32_t addr) {
    asm volatile("ldmatrix.sync.aligned.m8n8.x4.shared.b16 {%0,%1,%2,%3}, [%4];"
                 : "=r"(r0), "=r"(r1), "=r"(r2), "=r"(r3) : "r"(addr));
}
__device__ __forceinline__ void ldsm_x4_t(uint32_t& r0, uint32_t& r1,
                                          uint32_t& r2, uint32_t& r3, uint32_t addr) {
    asm volatile("ldmatrix.sync.aligned.m8n8.x4.trans.shared.b16 {%0,%1,%2,%3}, [%4];"
                 : "=r"(r0), "=r"(r1), "=r"(r2), "=r"(r3) : "r"(addr));
}
__device__ __forceinline__ void mma_f16(float& d0, float& d1, float& d2, float& d3,
                                        uint32_t a0, uint32_t a1, uint32_t a2, uint32_t a3,
                                        uint32_t b0, uint32_t b1) {
    asm volatile("mma.sync.aligned.m16n8k16.row.col.f32.f16.f16.f32 "
                 "{%0,%1,%2,%3}, {%4,%5,%6,%7}, {%8,%9}, {%0,%1,%2,%3};"
                 : "+f"(d0), "+f"(d1), "+f"(d2), "+f"(d3)
                 : "r"(a0), "r"(a1), "r"(a2), "r"(a3), "r"(b0), "r"(b1));
}
__device__ __forceinline__ uint32_t pack_h2(float v0, float v1) {
    return ((uint32_t)__half_as_ushort(__float2half_rn(v1)) << 16) |
           (uint32_t)__half_as_ushort(__float2half_rn(v0));
}
#define CP_ASYNC16(dst, src) \
    asm volatile("cp.async.cg.shared.global [%0], [%1], 16;" \
                 :: "r"(dst), "l"(src) : "memory")
#define CP_ASYNC_COMMIT() asm volatile("cp.async.commit_group;" ::: "memory")
#define CP_ASYNC_WAIT(n)  asm volatile("cp.async.wait_group %0;" :: "n"(n) : "memory")

// ---------------------------------------------------------------------------
// Grid build kernels
// ---------------------------------------------------------------------------
__global__ void __launch_bounds__(1024)
zero_hist_kernel() {
    g_hist[blockIdx.x * 1024 + threadIdx.x] = 0;
}

__global__ void __launch_bounds__(256)
cell_assign_kernel(const float* __restrict__ pos) {
    const int i = blockIdx.x * 256 + threadIdx.x;
    const float x = pos[i * 3 + 0];
    const float y = pos[i * 3 + 1];
    const float z = pos[i * 3 + 2];
    const int cx = min(max(__float2int_rd((x - OXC) * (1.0f / CSZ)), 0), G - 1);
    const int cy = min(max(__float2int_rd((y - OXC) * (1.0f / CSZ)), 0), G - 1);
    const int cz = min(max(__float2int_rd((z - OXC) * (1.0f / CSZ)), 0), G - 1);
    const int c = (cz * G + cy) * G + cx;
    g_pcell[i] = c;
    atomicAdd(&g_hist[c], 1);
}

__global__ void __launch_bounds__(1024)
scan_kernel() {
    __shared__ int sd[1024];
    const int t = threadIdx.x;
    int sum = 0;
#pragma unroll
    for (int k = 0; k < NCELL / 1024; k++) sum += g_hist[t * (NCELL / 1024) + k];
    sd[t] = sum;
    __syncthreads();
    for (int off = 1; off < 1024; off <<= 1) {
        const int v = (t >= off) ? sd[t - off] : 0;
        __syncthreads();
        sd[t] += v;
        __syncthreads();
    }
    int run = sd[t] - sum;
#pragma unroll
    for (int k = 0; k < NCELL / 1024; k++) {
        const int c = t * (NCELL / 1024) + k;
        g_cstart[c] = run;
        g_cptr[c]   = run;
        run += g_hist[c];
    }
}

__global__ void __launch_bounds__(256)
scatter_kernel(const float* __restrict__ pos) {
    const int i = blockIdx.x * 256 + threadIdx.x;
    const int c = g_pcell[i];
    const int dst = atomicAdd(&g_cptr[c], 1);
    const float x = pos[i * 3 + 0];
    const float y = pos[i * 3 + 1];
    const float z = pos[i * 3 + 2];
    const float sq = fmaf(z, z, fmaf(y, y, x * x));
    g_spos[dst] = make_float4(x, y, z, sq);
    g_sid[dst] = i;
}

// ---------------------------------------------------------------------------
// Warp-cooperative exact grid kNN query. One warp per query.
// Lane-distributed sorted top-16 (lanes 0..15), ballot+ffs+shfl_up insertion.
// ---------------------------------------------------------------------------
#define PROCESS_RUN(c0, c1) do {                                               \
    const int _st = g_cstart[(c0)];                                            \
    const int _en = g_cstart[(c1)] + g_hist[(c1)];                             \
    for (int _jb = _st; _jb < _en; _jb += 32) {                                \
        const int _j = _jb + lane;                                             \
        float _dist = 1e30f;                                                   \
        if (_j < _en) {                                                        \
            const float4 _p = g_spos[_j];                                      \
            const float _dot = fmaf(me.z, _p.z, fmaf(me.y, _p.y, me.x * _p.x));\
            _dist = fmaf(-2.0f, _dot, me.w + _p.w);                            \
            if (_j == q) _dist = 1e30f;                                        \
        }                                                                      \
        unsigned _m = __ballot_sync(0xffffffffu, _dist < kth);                 \
        while (_m) {                                                           \
            const int _src = __ffs(_m) - 1; _m &= _m - 1;                      \
            const float _d = __shfl_sync(0xffffffffu, _dist, _src);            \
            if (_d < kth) {                                                    \
                const int _id = _jb + _src;                                    \
                const unsigned _mk =                                           \
                    __ballot_sync(0xffffffffu, bd > _d) & 0xFFFFu;             \
                const int _pos = __ffs(_mk) - 1;   /* nonzero: bd15=kth>_d */  \
                const float _bdu = __shfl_up_sync(0xffffffffu, bd, 1);         \
                const int   _bju = __shfl_up_sync(0xffffffffu, bj, 1);         \
                if (lane >= _pos && lane < KNN) { bd = _bdu; bj = _bju; }      \
                if (lane == _pos) { bd = _d; bj = _id; }                       \
                kth = __shfl_sync(0xffffffffu, bd, KNN - 1);                   \
            }                                                                  \
        }                                                                      \
    }                                                                          \
} while (0)

__global__ void __launch_bounds__(256)
knn_query_kernel(int* __restrict__ idxout) {
    const int q    = (blockIdx.x * 256 + threadIdx.x) >> 5;   // one warp per query
    const int lane = threadIdx.x & 31;

    const float4 me = g_spos[q];
    const int cx = min(max(__float2int_rd((me.x - OXC) * (1.0f / CSZ)), 0), G - 1);
    const int cy = min(max(__float2int_rd((me.y - OXC) * (1.0f / CSZ)), 0), G - 1);
    const int cz = min(max(__float2int_rd((me.z - OXC) * (1.0f / CSZ)), 0), G - 1);

    float bd  = 1e30f;   // lane-distributed sorted list (lanes 0..15)
    int   bj  = -1;
    float kth = 1e30f;   // current 16th-best, warp-uniform

    for (int R = 0; R < G; R++) {
        const int zlo = max(cz - R, 0), zhi = min(cz + R, G - 1);
        const int ylo = max(cy - R, 0), yhi = min(cy + R, G - 1);
        const int xlo = max(cx - R, 0), xhi = min(cx + R, G - 1);
        for (int z = zlo; z <= zhi; z++) {
            const int adz = (z > cz) ? (z - cz) : (cz - z);
            for (int y = ylo; y <= yhi; y++) {
                const int ady = (y > cy) ? (y - cy) : (cy - y);
                const int rowc = (z * G + y) * G;
                if (adz == R || ady == R) {
                    PROCESS_RUN(rowc + xlo, rowc + xhi);   // whole row, contiguous
                } else {
                    if (cx - R >= 0) PROCESS_RUN(rowc + cx - R, rowc + cx - R);
                    if (cx + R < G)  PROCESS_RUN(rowc + cx + R, rowc + cx + R);
                }
            }
        }
        // exact stop bound: distance to faces of the processed region
        const float dxl = (cx - R > 0)     ? (me.x - (OXC + (cx - R) * CSZ))     : 1e30f;
        const float dxr = (cx + R + 1 < G) ? ((OXC + (cx + R + 1) * CSZ) - me.x) : 1e30f;
        const float dyl = (cy - R > 0)     ? (me.y - (OXC + (cy - R) * CSZ))     : 1e30f;
        const float dyr = (cy + R + 1 < G) ? ((OXC + (cy + R + 1) * CSZ) - me.y) : 1e30f;
        const float dzl = (cz - R > 0)     ? (me.z - (OXC + (cz - R) * CSZ))     : 1e30f;
        const float dzr = (cz + R + 1 < G) ? ((OXC + (cz + R + 1) * CSZ) - me.z) : 1e30f;
        const float dmin = fminf(fminf(fminf(dxl, dxr), fminf(dyl, dyr)),
                                 fminf(dzl, dzr));
        if (dmin * dmin >= kth) break;
    }

    if (lane < KNN) {
        const int orig = g_sid[q];
        idxout[orig * KNN + lane] = g_sid[bj];
    }
}

// ---------------------------------------------------------------------------
// Kernel 2: AB = X @ [W1top - W1bot | W1bot], b1 folded into A columns
// ---------------------------------------------------------------------------
__global__ void __launch_bounds__(256)
gemm1_kernel(const float* __restrict__ X,
             const float* __restrict__ W1,
             const float* __restrict__ b1,
             float* __restrict__ AB) {
    __shared__ float As[16][65];
    __shared__ float Bs[16][64];

    const int bm = blockIdx.y * 64;
    const int bn = blockIdx.x * 64;
    const int t  = threadIdx.x;
    const int tx = t & 15;
    const int ty = t >> 4;

    float acc[4][4];
#pragma unroll
    for (int a = 0; a < 4; a++)
#pragma unroll
        for (int b = 0; b < 4; b++) acc[a][b] = 0.0f;

    for (int k0 = 0; k0 < CIN; k0 += 16) {
#pragma unroll
        for (int r = 0; r < 4; r++) {
            const int e = t + r * 256;
            const int m = e >> 4, k = e & 15;
            As[k][m] = X[(bm + m) * CIN + k0 + k];
        }
#pragma unroll
        for (int r = 0; r < 4; r++) {
            const int e = t + r * 256;
            const int k = e >> 6, n = e & 63;
            const int gk = k0 + k, gn = bn + n;
            float v;
            if (gn < 256)
                v = W1[gk * 256 + gn] - W1[(gk + 128) * 256 + gn];
            else
                v = W1[(gk + 128) * 256 + (gn - 256)];
            Bs[k][n] = v;
        }
        __syncthreads();

#pragma unroll
        for (int k = 0; k < 16; k++) {
            float a0 = As[k][ty * 4 + 0];
            float a1 = As[k][ty * 4 + 1];
            float a2 = As[k][ty * 4 + 2];
            float a3 = As[k][ty * 4 + 3];
            float b0 = Bs[k][tx * 4 + 0];
            float c1 = Bs[k][tx * 4 + 1];
            float c2 = Bs[k][tx * 4 + 2];
            float b3 = Bs[k][tx * 4 + 3];
            acc[0][0] = fmaf(a0, b0, acc[0][0]); acc[0][1] = fmaf(a0, c1, acc[0][1]);
            acc[0][2] = fmaf(a0, c2, acc[0][2]); acc[0][3] = fmaf(a0, b3, acc[0][3]);
            acc[1][0] = fmaf(a1, b0, acc[1][0]); acc[1][1] = fmaf(a1, c1, acc[1][1]);
            acc[1][2] = fmaf(a1, c2, acc[1][2]); acc[1][3] = fmaf(a1, b3, acc[1][3]);
            acc[2][0] = fmaf(a2, b0, acc[2][0]); acc[2][1] = fmaf(a2, c1, acc[2][1]);
            acc[2][2] = fmaf(a2, c2, acc[2][2]); acc[2][3] = fmaf(a2, b3, acc[2][3]);
            acc[3][0] = fmaf(a3, b0, acc[3][0]); acc[3][1] = fmaf(a3, c1, acc[3][1]);
            acc[3][2] = fmaf(a3, c2, acc[3][2]); acc[3][3] = fmaf(a3, b3, acc[3][3]);
        }
        __syncthreads();
    }

#pragma unroll
    for (int ii = 0; ii < 4; ii++)
#pragma unroll
        for (int jj = 0; jj < 4; jj++) {
            const int gn = bn + tx * 4 + jj;
            const float bias = (gn < 256) ? b1[gn] : 0.0f;
            AB[(bm + ty * 4 + ii) * 512 + gn] = acc[ii][jj] + bias;
        }
}

// ---------------------------------------------------------------------------
// Kernel 2b: convert W2 into a single fp16 row-major [k][n] image
// ---------------------------------------------------------------------------
__global__ void __launch_bounds__(256)
w2split_kernel(const float* __restrict__ W2) {
    const int id = blockIdx.x * 256 + threadIdx.x;
    const float4 v = ((const float4*)W2)[id];
    g_W2h32[id * 2 + 0] = pack_h2(v.x, v.y);
    g_W2h32[id * 2 + 1] = pack_h2(v.z, v.w);
}

// ---------------------------------------------------------------------------
// Kernel 3: mma.sync fp16 edge GEMM, single-term (A_fp16 * B_fp16).
// Block = 4 nodes (M=64), 256 threads = 8 warps (2m x 4n), K=256 in 8 chunks
// of k=32, double-buffered cp.async W2 stream.
// smem/CTA: A 32KB + 2 x 16KB B = 64KB -> 2 CTAs/SM co-reside, so one CTA's
// MMA stream hides the other's gather/sync/epilogue phases.
// ---------------------------------------------------------------------------
#define SA_HI   0
#define SB_BASE 32768
#define SB_BUF  16384          // per buffer: 32 rows x 256 cols fp16
#define SM_TOTAL 65536

__global__ void __launch_bounds__(EM_THREADS, 2)
edge_mma_kernel(const float* __restrict__ AB,
                const int* __restrict__ idx,
                const float* __restrict__ b2,
                float* __restrict__ out) {
    extern __shared__ char smem[];
    const uint32_t sbase = smem_u32(smem);
    __shared__ int idxs[64];

    const int t    = threadIdx.x;
    const int lane = t & 31;
    const int wid  = t >> 5;
    const int wm   = wid & 1;        // 2 m-warps (rows 32*wm)
    const int wn   = wid >> 1;       // 4 n-warps (cols 64*wn)
    const int i0   = blockIdx.x * NODES_PB;

    if (t < 64) idxs[t] = idx[i0 * KNN + t];
    __syncthreads();

    // ---- prologue: async-load W2 chunk 0 (overlaps gather phase) ----
    {
#pragma unroll
        for (int ii = 0; ii < 4; ii++) {
            const int e = t + ii * EM_THREADS;       // 0..1023
            const int row = e >> 5, c = e & 31;
            const uint32_t dst = sbase + SB_BASE + row * 512 + ((c ^ (row & 7)) * 16);
            const int src = row * 32 + c;
            CP_ASYNC16(dst, (const uint4*)g_W2h32 + src);
        }
        CP_ASYNC_COMMIT();
    }

    // ---- Phase A: gather + relu + fp16 convert -> smem (rows = edges) ----
    {
        const int r = t >> 2;                // edge row 0..63
        const int q = t & 3;                 // 64-col quarter
        const int j = idxs[r];
        const float4* arow = (const float4*)(AB + (size_t)(i0 + (r >> 4)) * 512) + q * 16;
        const float4* brow = (const float4*)(AB + (size_t)j * 512 + 256) + q * 16;
        const int sw_r = r & 7;
        char* smem_c = smem;
#pragma unroll
        for (int w = 0; w < 8; w++) {
            const float4 a0 = arow[w * 2 + 0];
            const float4 a1 = arow[w * 2 + 1];
            const float4 e0 = brow[w * 2 + 0];
            const float4 e1 = brow[w * 2 + 1];
            uint4 H;
            H.x = pack_h2(fmaxf(a0.x + e0.x, 0.0f), fmaxf(a0.y + e0.y, 0.0f));
            H.y = pack_h2(fmaxf(a0.z + e0.z, 0.0f), fmaxf(a0.w + e0.w, 0.0f));
            H.z = pack_h2(fmaxf(a1.x + e1.x, 0.0f), fmaxf(a1.y + e1.y, 0.0f));
            H.w = pack_h2(fmaxf(a1.z + e1.z, 0.0f), fmaxf(a1.w + e1.w, 0.0f));
            const int c = (q * 8 + w) ^ sw_r;
            *(uint4*)(smem_c + SA_HI + r * 512 + c * 16) = H;
        }
    }
    __syncthreads();

    // ---- Main loop: 8 chunks of k=32, double-buffered ----
    float D[2][8][4];
#pragma unroll
    for (int mt = 0; mt < 2; mt++)
#pragma unroll
        for (int f = 0; f < 8; f++)
#pragma unroll
            for (int c = 0; c < 4; c++) D[mt][f][c] = 0.0f;

    const int a_row  = wm * 32 + (lane & 15);
    const int a_swz  = a_row & 7;
    const uint32_t a_base = sbase + SA_HI + a_row * 512;
    const int b_krow  = lane & 15;
    const int b_cbase = wn * 8 + (lane >> 4);

    for (int kc = 0; kc < 8; kc++) {
        if (kc < 7) {
            const int b = (kc + 1) & 1;
#pragma unroll
            for (int ii = 0; ii < 4; ii++) {
                const int e = t + ii * EM_THREADS;
                const int row = e >> 5, c = e & 31;
                const uint32_t dst = sbase + SB_BASE + b * SB_BUF +
                                     row * 512 + ((c ^ (row & 7)) * 16);
                const int src = ((kc + 1) * 32 + row) * 32 + c;
                CP_ASYNC16(dst, (const uint4*)g_W2h32 + src);
            }
            CP_ASYNC_COMMIT();
            CP_ASYNC_WAIT(1);
        } else {
            CP_ASYNC_WAIT(0);
        }
        __syncthreads();

        const uint32_t sb = sbase + SB_BASE + (kc & 1) * SB_BUF;
#pragma unroll
        for (int kt = 0; kt < 2; kt++) {
            const int kg = kc * 2 + kt;
            uint32_t ah[2][4];
#pragma unroll
            for (int mt = 0; mt < 2; mt++) {
                const uint32_t roff = mt * 16 * 512;
                const uint32_t c = (uint32_t)((kg * 2 + (lane >> 4)) ^ a_swz) * 16;
                ldsm_x4(ah[mt][0], ah[mt][1], ah[mt][2], ah[mt][3], a_base + roff + c);
            }
#pragma unroll
            for (int g = 0; g < 4; g++) {
                const int krow = kt * 16 + b_krow;
                const uint32_t c = (uint32_t)((b_cbase + g * 2) ^ (krow & 7)) * 16;
                const uint32_t baddr = sb + krow * 512 + c;
                uint32_t bh0, bh1, bh2, bh3;
                ldsm_x4_t(bh0, bh1, bh2, bh3, baddr);
#pragma unroll
                for (int mt = 0; mt < 2; mt++) {
                    float* d0 = D[mt][g * 2 + 0];
                    float* d1 = D[mt][g * 2 + 1];
                    mma_f16(d0[0], d0[1], d0[2], d0[3],
                            ah[mt][0], ah[mt][1], ah[mt][2], ah[mt][3], bh0, bh1);
                    mma_f16(d1[0], d1[1], d1[2], d1[3],
                            ah[mt][0], ah[mt][1], ah[mt][2], ah[mt][3], bh2, bh3);
                }
            }
        }
        __syncthreads();
    }

    // ---- Epilogue: max over each node's 16 rows (warp-local) + b2 ----
#pragma unroll
    for (int mt = 0; mt < 2; mt++) {
        const int node = i0 + wm * 2 + mt;
#pragma unroll
        for (int f = 0; f < 8; f++) {
            float m0 = fmaxf(D[mt][f][0], D[mt][f][2]);
            float m1 = fmaxf(D[mt][f][1], D[mt][f][3]);
            m0 = fmaxf(m0, __shfl_xor_sync(0xffffffffu, m0, 4));
            m1 = fmaxf(m1, __shfl_xor_sync(0xffffffffu, m1, 4));
            m0 = fmaxf(m0, __shfl_xor_sync(0xffffffffu, m0, 8));
            m1 = fmaxf(m1, __shfl_xor_sync(0xffffffffu, m1, 8));
            m0 = fmaxf(m0, __shfl_xor_sync(0xffffffffu, m0, 16));
            m1 = fmaxf(m1, __shfl_xor_sync(0xffffffffu, m1, 16));
            if ((lane >> 2) == 0) {
                const int col = wn * 64 + f * 8 + 2 * (lane & 3);
                float2 o;
                o.x = m0 + b2[col];
                o.y = m1 + b2[col + 1];
                *(float2*)(out + (size_t)node * DDIM + col) = o;
            }
        }
    }
}

// ---------------------------------------------------------------------------
// Launch: fork gemm1/w2split onto a side stream so they overlap the kNN
// chain in the captured graph (independent until edge_mma joins both).
// ---------------------------------------------------------------------------
extern "C" void kernel_launch(void* const* d_in, const int* in_sizes, int n_in,
                              void* d_out, int out_size) {
    const float* x   = (const float*)d_in[0];
    const float* pos = (const float*)d_in[1];
    const float* W1  = (const float*)d_in[2];
    const float* b1  = (const float*)d_in[3];
    const float* W2  = (const float*)d_in[4];
    const float* b2  = (const float*)d_in[5];
    float* out = (float*)d_out;
    (void)in_sizes; (void)n_in; (void)out_size;

    int*   idx_ptr = nullptr;
    float* ab_ptr  = nullptr;
    cudaGetSymbolAddress((void**)&idx_ptr, g_idx);
    cudaGetSymbolAddress((void**)&ab_ptr, g_AB);

    static bool init_done = false;
    static cudaStream_t s2 = nullptr;
    static cudaEvent_t ev_fork = nullptr, ev_join = nullptr;
    if (!init_done) {
        cudaGetLastError();  // clear any stale sticky error before first use
        cudaFuncSetAttribute(edge_mma_kernel,
                             cudaFuncAttributeMaxDynamicSharedMemorySize, SM_TOTAL);
        cudaStreamCreateWithFlags(&s2, cudaStreamNonBlocking);
        cudaEventCreateWithFlags(&ev_fork, cudaEventDisableTiming);
        cudaEventCreateWithFlags(&ev_join, cudaEventDisableTiming);
        init_done = true;
    }

    // fork: side stream runs gemm1 + w2split concurrently with kNN chain
    cudaEventRecord(ev_fork, 0);
    cudaStreamWaitEvent(s2, ev_fork, 0);

    // main stream: grid kNN build + warp-cooperative query
    zero_hist_kernel<<<NCELL / 1024, 1024>>>();
    cell_assign_kernel<<<NPTS / 256, 256>>>(pos);
    scan_kernel<<<1, 1024>>>();
    scatter_kernel<<<NPTS / 256, 256>>>(pos);
    knn_query_kernel<<<NPTS * 32 / 256, 256>>>(idx_ptr);

    // side stream: MLP prep
    gemm1_kernel<<<dim3(512 / 64, NPTS / 64), 256, 0, s2>>>(x, W1, b1, ab_ptr);
    w2split_kernel<<<64, 256, 0, s2>>>(W2);
    cudaEventRecord(ev_join, s2);

    // join, then fused edge GEMM
    cudaStreamWaitEvent(0, ev_join, 0);
    edge_mma_kernel<<<NPTS / NODES_PB, EM_THREADS, SM_TOTAL>>>(ab_ptr, idx_ptr, b2, out);
}